// round 2
// baseline (speedup 1.0000x reference)
#include <cuda_runtime.h>
#include <math.h>

// Problem constants
#define DEPTH 12
#define E_DIM 256
#define F_DIM 128
#define H_DIM 8
#define HD 32
#define U_DIM 1000
#define I_DIM 1000
#define B_DIM 64
#define N_TOK 257                 // 2F+1
#define M_ROWS (B_DIM * N_TOK)    // 16448, divisible by 64
#define FF_DIM 1024
#define QKV_DIM 768

// ---------------- scratch (device globals; no allocation allowed) -----------
__device__ float d_x[M_ROWS * E_DIM];
__device__ float d_h[M_ROWS * E_DIM];
__device__ float d_qkv[M_ROWS * QKV_DIM];
__device__ float d_o[M_ROWS * E_DIM];
__device__ float d_t[M_ROWS * FF_DIM];
__device__ float d_Wqkv[DEPTH * E_DIM * QKV_DIM];
__device__ float d_bqkv[DEPTH * QKV_DIM];

// ---------------- weight packing: Wqkv = [Wq | Wk | Wv] ---------------------
__global__ __launch_bounds__(256) void pack_w_kernel(
    const float* __restrict__ Wq, const float* __restrict__ Wk,
    const float* __restrict__ Wv, float* __restrict__ Wqkv)
{
    int idx = blockIdx.x * 256 + threadIdx.x;
    if (idx >= DEPTH * E_DIM * QKV_DIM) return;
    int n = idx % QKV_DIM;
    int r = (idx / QKV_DIM) % E_DIM;
    int l = idx / (QKV_DIM * E_DIM);
    size_t so = (size_t)l * E_DIM * E_DIM + (size_t)r * E_DIM;
    float v;
    if (n < 256)      v = Wq[so + n];
    else if (n < 512) v = Wk[so + (n - 256)];
    else              v = Wv[so + (n - 512)];
    Wqkv[idx] = v;
}

__global__ __launch_bounds__(256) void pack_b_kernel(
    const float* __restrict__ bq, const float* __restrict__ bk,
    const float* __restrict__ bv, float* __restrict__ bqkv)
{
    int idx = blockIdx.x * 256 + threadIdx.x;
    if (idx >= DEPTH * QKV_DIM) return;
    int n = idx % QKV_DIM;
    int l = idx / QKV_DIM;
    float v;
    if (n < 256)      v = bq[l * E_DIM + n];
    else if (n < 512) v = bk[l * E_DIM + (n - 256)];
    else              v = bv[l * E_DIM + (n - 512)];
    bqkv[idx] = v;
}

// ---------------- embedding: x = concat(cls, xu, xi) + positions ------------
__global__ __launch_bounds__(256) void embed_kernel(
    const int* __restrict__ user, const int* __restrict__ item,
    const float* __restrict__ ut, const float* __restrict__ it,
    const float* __restrict__ cls, const float* __restrict__ pos,
    float* __restrict__ x)
{
    int n = blockIdx.x;          // 0..256
    int b = blockIdx.y;          // 0..63
    int e = threadIdx.x;         // 0..255
    float v;
    if (n == 0) {
        v = cls[e];
    } else if (n <= F_DIM) {
        int uid = user[b];
        v = ut[((size_t)e * U_DIM + uid) * F_DIM + (n - 1)];
    } else {
        int iid = item[b];
        v = it[((size_t)e * I_DIM + iid) * F_DIM + (n - 1 - F_DIM)];
    }
    x[((size_t)b * N_TOK + n) * E_DIM + e] = v + pos[(size_t)n * E_DIM + e];
}

// ---------------- layernorm: warp per row, 8 rows per block -----------------
__device__ __forceinline__ float warp_sum(float v) {
    #pragma unroll
    for (int o = 16; o > 0; o >>= 1) v += __shfl_xor_sync(0xffffffffu, v, o);
    return v;
}

__global__ __launch_bounds__(256) void layernorm_kernel(
    const float* __restrict__ x, const float* __restrict__ g,
    const float* __restrict__ b, float* __restrict__ out)
{
    int row  = blockIdx.x * 8 + (threadIdx.x >> 5);
    int lane = threadIdx.x & 31;
    const float4* xr = (const float4*)(x + (size_t)row * E_DIM);
    float4 v0 = xr[lane * 2];
    float4 v1 = xr[lane * 2 + 1];
    float s  = v0.x + v0.y + v0.z + v0.w + v1.x + v1.y + v1.z + v1.w;
    float ss = v0.x*v0.x + v0.y*v0.y + v0.z*v0.z + v0.w*v0.w
             + v1.x*v1.x + v1.y*v1.y + v1.z*v1.z + v1.w*v1.w;
    s  = warp_sum(s);
    ss = warp_sum(ss);
    float mean = s * (1.f / E_DIM);
    float var  = ss * (1.f / E_DIM) - mean * mean;
    float rstd = rsqrtf(var + 1e-5f);
    float4 g0 = ((const float4*)g)[lane * 2], g1 = ((const float4*)g)[lane * 2 + 1];
    float4 b0 = ((const float4*)b)[lane * 2], b1 = ((const float4*)b)[lane * 2 + 1];
    float4 o0, o1;
    o0.x = (v0.x - mean) * rstd * g0.x + b0.x;
    o0.y = (v0.y - mean) * rstd * g0.y + b0.y;
    o0.z = (v0.z - mean) * rstd * g0.z + b0.z;
    o0.w = (v0.w - mean) * rstd * g0.w + b0.w;
    o1.x = (v1.x - mean) * rstd * g1.x + b1.x;
    o1.y = (v1.y - mean) * rstd * g1.y + b1.y;
    o1.z = (v1.z - mean) * rstd * g1.z + b1.z;
    o1.w = (v1.w - mean) * rstd * g1.w + b1.w;
    float4* orow = (float4*)(out + (size_t)row * E_DIM);
    orow[lane * 2]     = o0;
    orow[lane * 2 + 1] = o1;
}

// ---------------- SGEMM: 64x128x16 tile, 4x8 microtile, 256 threads ---------
// C = A[MxK] @ W[KxN] + bias (+gelu) (+res).  M%64==0, N%128==0, K%16==0.
#define BM 64
#define BN 128
#define BK 16

__global__ __launch_bounds__(256) void sgemm_kernel(
    const float* __restrict__ A, const float* __restrict__ W,
    const float* __restrict__ bias, const float* __restrict__ res,
    float* __restrict__ C, int M, int K, int N, int gelu)
{
    __shared__ float As[BK][BM + 4];
    __shared__ float Bs[BK][BN + 4];

    int tid = threadIdx.x;
    int tx = tid & 15;            // col group (x8)
    int ty = tid >> 4;            // row group (x4)
    int br = blockIdx.y * BM;
    int bc = blockIdx.x * BN;

    int arow = tid >> 2;          // 0..63
    int ak4  = (tid & 3) * 4;     // 0,4,8,12

    float acc[4][8];
    #pragma unroll
    for (int i = 0; i < 4; i++)
        #pragma unroll
        for (int j = 0; j < 8; j++) acc[i][j] = 0.f;

    const float* Ag = A + (size_t)(br + arow) * K + ak4;

    for (int k0 = 0; k0 < K; k0 += BK) {
        float4 av = *(const float4*)(Ag + k0);
        As[ak4 + 0][arow] = av.x;
        As[ak4 + 1][arow] = av.y;
        As[ak4 + 2][arow] = av.z;
        As[ak4 + 3][arow] = av.w;
        #pragma unroll
        for (int s = 0; s < 2; s++) {
            int idx = tid * 2 + s;
            int kr = idx >> 5;
            int n4 = (idx & 31) * 4;
            *(float4*)&Bs[kr][n4] =
                *(const float4*)(W + (size_t)(k0 + kr) * N + bc + n4);
        }
        __syncthreads();

        #pragma unroll
        for (int kk = 0; kk < BK; kk++) {
            float4 a  = *(const float4*)&As[kk][ty * 4];
            float4 b0 = *(const float4*)&Bs[kk][tx * 8];
            float4 b1 = *(const float4*)&Bs[kk][tx * 8 + 4];
            float aa[4] = {a.x, a.y, a.z, a.w};
            float bb[8] = {b0.x, b0.y, b0.z, b0.w, b1.x, b1.y, b1.z, b1.w};
            #pragma unroll
            for (int i = 0; i < 4; i++)
                #pragma unroll
                for (int j = 0; j < 8; j++)
                    acc[i][j] = fmaf(aa[i], bb[j], acc[i][j]);
        }
        __syncthreads();
    }

    float4 bi0 = *(const float4*)&bias[bc + tx * 8];
    float4 bi1 = *(const float4*)&bias[bc + tx * 8 + 4];
    float bb[8] = {bi0.x, bi0.y, bi0.z, bi0.w, bi1.x, bi1.y, bi1.z, bi1.w};

    #pragma unroll
    for (int i = 0; i < 4; i++) {
        size_t row = (size_t)(br + ty * 4 + i);
        float o[8];
        #pragma unroll
        for (int j = 0; j < 8; j++) {
            float v = acc[i][j] + bb[j];
            if (gelu) v = 0.5f * v * (1.0f + erff(v * 0.70710678118654752f));
            o[j] = v;
        }
        if (res) {
            float4 r0 = *(const float4*)&res[row * N + bc + tx * 8];
            float4 r1 = *(const float4*)&res[row * N + bc + tx * 8 + 4];
            o[0] += r0.x; o[1] += r0.y; o[2] += r0.z; o[3] += r0.w;
            o[4] += r1.x; o[5] += r1.y; o[6] += r1.z; o[7] += r1.w;
        }
        float4 ov0 = {o[0], o[1], o[2], o[3]};
        float4 ov1 = {o[4], o[5], o[6], o[7]};
        *(float4*)&C[row * N + bc + tx * 8]     = ov0;
        *(float4*)&C[row * N + bc + tx * 8 + 4] = ov1;
    }
}

// ---------------- attention: K,V in smem; 2 queries per warp ----------------
// qkv rows: [q(256) | k(256) | v(256)], head slice h*32.
// O rows: [256] (E layout for the Wo GEMM).
#define ATT_SMEM ((2 * N_TOK * 33 + 8 * 2 * 32) * 4)

__global__ __launch_bounds__(256) void attention_kernel(
    const float* __restrict__ qkv, float* __restrict__ O)
{
    extern __shared__ float sm[];
    float* Ks = sm;                       // N_TOK * 33
    float* Vs = sm + N_TOK * 33;          // N_TOK * 33
    float* qs = Vs + N_TOK * 33;          // 8 warps * 2 queries * 32

    int h = blockIdx.x;
    int b = blockIdx.y;
    int tid = threadIdx.x;
    int w = tid >> 5, lane = tid & 31;

    const size_t base = ((size_t)b * N_TOK) * QKV_DIM + h * HD;
    const size_t obase = ((size_t)b * N_TOK) * E_DIM + h * HD;

    for (int idx = tid; idx < N_TOK * 32; idx += 256) {
        int k = idx >> 5, d = idx & 31;
        Ks[k * 33 + d] = qkv[base + (size_t)k * QKV_DIM + 256 + d];
        Vs[k * 33 + d] = qkv[base + (size_t)k * QKV_DIM + 512 + d];
    }
    __syncthreads();

    float* qsa = qs + w * 64;
    float* qsb = qsa + 32;

    for (int it = 0; it < 17; it++) {
        int pair = w + it * 8;
        if (pair > 128) break;
        int qa = 2 * pair;
        int qb = qa + 1;
        bool hb = (qb < N_TOK);

        qsa[lane] = qkv[base + (size_t)qa * QKV_DIM + lane];
        qsb[lane] = hb ? qkv[base + (size_t)qb * QKV_DIM + lane] : 0.f;
        __syncwarp();

        float ea[9], eb[9];
        #pragma unroll
        for (int j = 0; j < 9; j++) {
            int k = j * 32 + lane;
            int kc = (k < N_TOK) ? k : (N_TOK - 1);
            float fa = 0.f, fb = 0.f;
            #pragma unroll
            for (int d = 0; d < 32; d++) {
                float kv = Ks[kc * 33 + d];
                fa = fmaf(qsa[d], kv, fa);
                fb = fmaf(qsb[d], kv, fb);
            }
            ea[j] = (k < N_TOK) ? fa : -INFINITY;
            eb[j] = (k < N_TOK) ? fb : -INFINITY;
        }

        float ma = ea[0], mb = eb[0];
        #pragma unroll
        for (int j = 1; j < 9; j++) { ma = fmaxf(ma, ea[j]); mb = fmaxf(mb, eb[j]); }
        #pragma unroll
        for (int o = 16; o > 0; o >>= 1) {
            ma = fmaxf(ma, __shfl_xor_sync(0xffffffffu, ma, o));
            mb = fmaxf(mb, __shfl_xor_sync(0xffffffffu, mb, o));
        }

        float pa[9], pb[9], sa = 0.f, sb = 0.f;
        #pragma unroll
        for (int j = 0; j < 9; j++) {
            int k = j * 32 + lane;
            pa[j] = (k < N_TOK) ? __expf(ea[j] - ma) : 0.f;
            pb[j] = (k < N_TOK) ? __expf(eb[j] - mb) : 0.f;
            sa += pa[j]; sb += pb[j];
        }
        sa = warp_sum(sa); sb = warp_sum(sb);
        float sca = 1.f / (sa * 16.0f);      // /sqrt(E) applied after softmax
        float scb = 1.f / (sb * 16.0f);

        float acc_a = 0.f, acc_b = 0.f;
        #pragma unroll
        for (int j = 0; j < 8; j++) {
            #pragma unroll
            for (int kk = 0; kk < 32; kk++) {
                float vv = Vs[(j * 32 + kk) * 33 + lane];
                acc_a = fmaf(__shfl_sync(0xffffffffu, pa[j], kk), vv, acc_a);
                acc_b = fmaf(__shfl_sync(0xffffffffu, pb[j], kk), vv, acc_b);
            }
        }
        {
            float vv = Vs[256 * 33 + lane];
            acc_a = fmaf(__shfl_sync(0xffffffffu, pa[8], 0), vv, acc_a);
            acc_b = fmaf(__shfl_sync(0xffffffffu, pb[8], 0), vv, acc_b);
        }
        O[obase + (size_t)qa * E_DIM + lane] = acc_a * sca;
        if (hb) O[obase + (size_t)qb * E_DIM + lane] = acc_b * scb;
    }
}

// ---------------- mean-pool + head LN + linear ------------------------------
__global__ __launch_bounds__(256) void pool_head_kernel(
    const float* __restrict__ x, const float* __restrict__ g,
    const float* __restrict__ b, const float* __restrict__ W,
    const float* __restrict__ bias, float* __restrict__ out)
{
    int bb = blockIdx.x;
    int e = threadIdx.x;
    int w = e >> 5, lane = e & 31;
    float s = 0.f;
    const float* xb = x + (size_t)bb * N_TOK * E_DIM + e;
    for (int n = 0; n < N_TOK; n++) s += xb[(size_t)n * E_DIM];
    float pooled = s * (1.0f / N_TOK);

    __shared__ float sA[8], sB[8];
    float s1 = warp_sum(pooled);
    float s2 = warp_sum(pooled * pooled);
    if (lane == 0) { sA[w] = s1; sB[w] = s2; }
    __syncthreads();
    float tot = 0.f, tot2 = 0.f;
    #pragma unroll
    for (int i = 0; i < 8; i++) { tot += sA[i]; tot2 += sB[i]; }
    float mean = tot * (1.f / E_DIM);
    float var = tot2 * (1.f / E_DIM) - mean * mean;
    float rstd = rsqrtf(var + 1e-5f);
    float y = (pooled - mean) * rstd * g[e] + b[e];
    float t = y * W[e];
    __syncthreads();
    float t1 = warp_sum(t);
    if (lane == 0) sA[w] = t1;
    __syncthreads();
    if (e == 0) {
        float tot3 = 0.f;
        #pragma unroll
        for (int i = 0; i < 8; i++) tot3 += sA[i];
        out[bb] = tot3 + bias[0];
    }
}

// ---------------- driver -----------------------------------------------------
extern "C" void kernel_launch(void* const* d_in, const int* in_sizes, int n_in,
                              void* d_out, int out_size)
{
    const int*   user    = (const int*)  d_in[0];
    const int*   item    = (const int*)  d_in[1];
    const float* ut      = (const float*)d_in[2];
    const float* it      = (const float*)d_in[3];
    const float* cls     = (const float*)d_in[4];
    const float* pos     = (const float*)d_in[5];
    const float* ln1_g   = (const float*)d_in[6];
    const float* ln1_b   = (const float*)d_in[7];
    const float* Wq      = (const float*)d_in[8];
    const float* bq      = (const float*)d_in[9];
    const float* Wk      = (const float*)d_in[10];
    const float* bk      = (const float*)d_in[11];
    const float* Wv      = (const float*)d_in[12];
    const float* bv      = (const float*)d_in[13];
    const float* Wo      = (const float*)d_in[14];
    const float* bo      = (const float*)d_in[15];
    const float* ln2_g   = (const float*)d_in[16];
    const float* ln2_b   = (const float*)d_in[17];
    const float* W1      = (const float*)d_in[18];
    const float* b1      = (const float*)d_in[19];
    const float* W2      = (const float*)d_in[20];
    const float* b2      = (const float*)d_in[21];
    const float* head_g  = (const float*)d_in[22];
    const float* head_b  = (const float*)d_in[23];
    const float* head_W  = (const float*)d_in[24];
    const float* head_bi = (const float*)d_in[25];

    float *x, *h, *qkv, *o, *t, *Wqkv, *bqkv;
    cudaGetSymbolAddress((void**)&x,    d_x);
    cudaGetSymbolAddress((void**)&h,    d_h);
    cudaGetSymbolAddress((void**)&qkv,  d_qkv);
    cudaGetSymbolAddress((void**)&o,    d_o);
    cudaGetSymbolAddress((void**)&t,    d_t);
    cudaGetSymbolAddress((void**)&Wqkv, d_Wqkv);
    cudaGetSymbolAddress((void**)&bqkv, d_bqkv);

    cudaFuncSetAttribute(attention_kernel,
                         cudaFuncAttributeMaxDynamicSharedMemorySize, ATT_SMEM);

    // pack QKV weights/biases
    {
        int nW = DEPTH * E_DIM * QKV_DIM;
        pack_w_kernel<<<(nW + 255) / 256, 256>>>(Wq, Wk, Wv, Wqkv);
        int nB = DEPTH * QKV_DIM;
        pack_b_kernel<<<(nB + 255) / 256, 256>>>(bq, bk, bv, bqkv);
    }

    embed_kernel<<<dim3(N_TOK, B_DIM), 256>>>(user, item, ut, it, cls, pos, x);

    const dim3 gQKV(QKV_DIM / BN, M_ROWS / BM);   // (6, 257)
    const dim3 gE(E_DIM / BN, M_ROWS / BM);       // (2, 257)
    const dim3 gFF(FF_DIM / BN, M_ROWS / BM);     // (8, 257)
    const int  lnGrid = M_ROWS / 8;               // 2056

    for (int l = 0; l < DEPTH; l++) {
        size_t eOff   = (size_t)l * E_DIM;
        size_t eeOff  = (size_t)l * E_DIM * E_DIM;
        size_t ffOff  = (size_t)l * E_DIM * FF_DIM;
        size_t qkvOff = (size_t)l * E_DIM * QKV_DIM;

        layernorm_kernel<<<lnGrid, 256>>>(x, ln1_g + eOff, ln1_b + eOff, h);

        sgemm_kernel<<<gQKV, 256>>>(h, Wqkv + qkvOff, bqkv + (size_t)l * QKV_DIM,
                                    nullptr, qkv, M_ROWS, E_DIM, QKV_DIM, 0);

        attention_kernel<<<dim3(H_DIM, B_DIM), 256, ATT_SMEM>>>(qkv, o);

        // x = x + (o @ Wo + bo)
        sgemm_kernel<<<gE, 256>>>(o, Wo + eeOff, bo + eOff, x, x,
                                  M_ROWS, E_DIM, E_DIM, 0);

        layernorm_kernel<<<lnGrid, 256>>>(x, ln2_g + eOff, ln2_b + eOff, h);

        // t = gelu(h @ W1 + b1)
        sgemm_kernel<<<gFF, 256>>>(h, W1 + ffOff, b1 + (size_t)l * FF_DIM,
                                   nullptr, t, M_ROWS, E_DIM, FF_DIM, 1);
        // x = x + (t @ W2 + b2)
        sgemm_kernel<<<gE, 256>>>(t, W2 + ffOff, b2 + eOff, x, x,
                                  M_ROWS, FF_DIM, E_DIM, 0);
    }

    pool_head_kernel<<<B_DIM, 256>>>(x, head_g, head_b, head_W, head_bi,
                                     (float*)d_out);
}

// round 3
// speedup vs baseline: 1.6219x; 1.6219x over previous
#include <cuda_runtime.h>
#include <cuda_bf16.h>
#include <math.h>

// Problem constants
#define DEPTH 12
#define E_DIM 256
#define F_DIM 128
#define H_DIM 8
#define HD 32
#define U_DIM 1000
#define I_DIM 1000
#define B_DIM 64
#define N_TOK 257                  // 2F+1
#define M_ROWS (B_DIM * N_TOK)     // 16448
#define M_PAD 16512                // 129 * 128 (padded; pad rows are junk, never read as outputs)
#define FF_DIM 1024
#define QKV_DIM 768

// ---------------- scratch (device globals; zero-init, no allocation) --------
__device__ float d_x[M_PAD * E_DIM];
__device__ float d_h[M_PAD * E_DIM];
__device__ float d_qkv[M_PAD * QKV_DIM];
__device__ float d_o[M_PAD * E_DIM];
__device__ float d_t[M_PAD * FF_DIM];
__device__ float d_bqkv[DEPTH * QKV_DIM];
// packed bf16 hi/lo transposed weights: layout [l][N][K]
__device__ __nv_bfloat16 d_WqkvH[DEPTH * QKV_DIM * E_DIM];
__device__ __nv_bfloat16 d_WqkvL[DEPTH * QKV_DIM * E_DIM];
__device__ __nv_bfloat16 d_WoH[DEPTH * E_DIM * E_DIM];
__device__ __nv_bfloat16 d_WoL[DEPTH * E_DIM * E_DIM];
__device__ __nv_bfloat16 d_W1H[DEPTH * FF_DIM * E_DIM];
__device__ __nv_bfloat16 d_W1L[DEPTH * FF_DIM * E_DIM];
__device__ __nv_bfloat16 d_W2H[DEPTH * E_DIM * FF_DIM];
__device__ __nv_bfloat16 d_W2L[DEPTH * E_DIM * FF_DIM];

// ---------------- bf16 split helpers ----------------------------------------
__device__ __forceinline__ void bf16_split(float x, __nv_bfloat16& h, __nv_bfloat16& l) {
    h = __float2bfloat16(x);
    l = __float2bfloat16(x - __bfloat162float(h));
}

// ---------------- weight pack: out[l][n][k] = split(W[l][k][n]) -------------
__global__ __launch_bounds__(256) void pack_t_kernel(
    const float* __restrict__ W, __nv_bfloat16* __restrict__ oh,
    __nv_bfloat16* __restrict__ ol, int K, int N)
{
    long long idx = (long long)blockIdx.x * 256 + threadIdx.x;
    long long tot = (long long)DEPTH * K * N;
    if (idx >= tot) return;
    int k = idx % K;
    int n = (idx / K) % N;
    int l = idx / ((long long)K * N);
    float v = W[((long long)l * K + k) * N + n];
    __nv_bfloat16 h, lo; bf16_split(v, h, lo);
    oh[idx] = h; ol[idx] = lo;
}

__global__ __launch_bounds__(256) void pack_qkv_kernel(
    const float* __restrict__ Wq, const float* __restrict__ Wk,
    const float* __restrict__ Wv, __nv_bfloat16* __restrict__ oh,
    __nv_bfloat16* __restrict__ ol)
{
    long long idx = (long long)blockIdx.x * 256 + threadIdx.x;
    long long tot = (long long)DEPTH * QKV_DIM * E_DIM;
    if (idx >= tot) return;
    int k = idx % E_DIM;
    int n = (idx / E_DIM) % QKV_DIM;
    int l = idx / ((long long)E_DIM * QKV_DIM);
    const float* W = (n < 256) ? Wq : (n < 512) ? Wk : Wv;
    int nn = n & 255;
    float v = W[((long long)l * E_DIM + k) * E_DIM + nn];
    __nv_bfloat16 h, lo; bf16_split(v, h, lo);
    oh[idx] = h; ol[idx] = lo;
}

__global__ __launch_bounds__(256) void pack_b_kernel(
    const float* __restrict__ bq, const float* __restrict__ bk,
    const float* __restrict__ bv, float* __restrict__ bqkv)
{
    int idx = blockIdx.x * 256 + threadIdx.x;
    if (idx >= DEPTH * QKV_DIM) return;
    int n = idx % QKV_DIM;
    int l = idx / QKV_DIM;
    float v;
    if (n < 256)      v = bq[l * E_DIM + n];
    else if (n < 512) v = bk[l * E_DIM + (n - 256)];
    else              v = bv[l * E_DIM + (n - 512)];
    bqkv[idx] = v;
}

// ---------------- embedding --------------------------------------------------
__global__ __launch_bounds__(256) void embed_kernel(
    const int* __restrict__ user, const int* __restrict__ item,
    const float* __restrict__ ut, const float* __restrict__ it,
    const float* __restrict__ cls, const float* __restrict__ pos,
    float* __restrict__ x)
{
    int n = blockIdx.x;
    int b = blockIdx.y;
    int e = threadIdx.x;
    float v;
    if (n == 0) {
        v = cls[e];
    } else if (n <= F_DIM) {
        int uid = user[b];
        v = ut[((size_t)e * U_DIM + uid) * F_DIM + (n - 1)];
    } else {
        int iid = item[b];
        v = it[((size_t)e * I_DIM + iid) * F_DIM + (n - 1 - F_DIM)];
    }
    x[((size_t)b * N_TOK + n) * E_DIM + e] = v + pos[(size_t)n * E_DIM + e];
}

// ---------------- layernorm: warp per row ------------------------------------
__device__ __forceinline__ float warp_sum(float v) {
    #pragma unroll
    for (int o = 16; o > 0; o >>= 1) v += __shfl_xor_sync(0xffffffffu, v, o);
    return v;
}

__global__ __launch_bounds__(256) void layernorm_kernel(
    const float* __restrict__ x, const float* __restrict__ g,
    const float* __restrict__ b, float* __restrict__ out)
{
    int row  = blockIdx.x * 8 + (threadIdx.x >> 5);
    int lane = threadIdx.x & 31;
    const float4* xr = (const float4*)(x + (size_t)row * E_DIM);
    float4 v0 = xr[lane * 2];
    float4 v1 = xr[lane * 2 + 1];
    float s  = v0.x + v0.y + v0.z + v0.w + v1.x + v1.y + v1.z + v1.w;
    float ss = v0.x*v0.x + v0.y*v0.y + v0.z*v0.z + v0.w*v0.w
             + v1.x*v1.x + v1.y*v1.y + v1.z*v1.z + v1.w*v1.w;
    s  = warp_sum(s);
    ss = warp_sum(ss);
    float mean = s * (1.f / E_DIM);
    float var  = ss * (1.f / E_DIM) - mean * mean;
    float rstd = rsqrtf(var + 1e-5f);
    float4 g0 = ((const float4*)g)[lane * 2], g1 = ((const float4*)g)[lane * 2 + 1];
    float4 b0 = ((const float4*)b)[lane * 2], b1 = ((const float4*)b)[lane * 2 + 1];
    float4 o0, o1;
    o0.x = (v0.x - mean) * rstd * g0.x + b0.x;
    o0.y = (v0.y - mean) * rstd * g0.y + b0.y;
    o0.z = (v0.z - mean) * rstd * g0.z + b0.z;
    o0.w = (v0.w - mean) * rstd * g0.w + b0.w;
    o1.x = (v1.x - mean) * rstd * g1.x + b1.x;
    o1.y = (v1.y - mean) * rstd * g1.y + b1.y;
    o1.z = (v1.z - mean) * rstd * g1.z + b1.z;
    o1.w = (v1.w - mean) * rstd * g1.w + b1.w;
    float4* orow = (float4*)(out + (size_t)row * E_DIM);
    orow[lane * 2]     = o0;
    orow[lane * 2 + 1] = o1;
}

// ---------------- tensor-core GEMM (bf16x2 split, m16n8k16) ------------------
// C[M_PAD x N] = A[M_PAD x K](f32) @ Wt[N x K](bf16 hi/lo) + bias (+gelu)(+res)
// block tile 128x64xBK32, 8 warps (4m x 2n), warp tile 32x32.
#define GBM 128
#define GBN 64
#define GBK 32
#define AKP 40   // smem K-pitch (elements) for conflict-free fragment LDS

__device__ __forceinline__ void mma_bf16(float* c, const unsigned* a, const unsigned* b) {
    asm volatile(
        "mma.sync.aligned.m16n8k16.row.col.f32.bf16.bf16.f32 "
        "{%0,%1,%2,%3}, {%4,%5,%6,%7}, {%8,%9}, {%0,%1,%2,%3};\n"
        : "+f"(c[0]), "+f"(c[1]), "+f"(c[2]), "+f"(c[3])
        : "r"(a[0]), "r"(a[1]), "r"(a[2]), "r"(a[3]), "r"(b[0]), "r"(b[1]));
}

__global__ __launch_bounds__(256) void tgemm_kernel(
    const float* __restrict__ A,
    const __nv_bfloat16* __restrict__ WtH, const __nv_bfloat16* __restrict__ WtL,
    const float* __restrict__ bias, const float* __restrict__ res,
    float* __restrict__ C, int K, int N, int gelu)
{
    __shared__ __nv_bfloat16 AsH[2][GBM * AKP];
    __shared__ __nv_bfloat16 AsL[2][GBM * AKP];
    __shared__ __nv_bfloat16 BsH[2][GBN * AKP];
    __shared__ __nv_bfloat16 BsL[2][GBN * AKP];

    const int tid  = threadIdx.x;
    const int lane = tid & 31;
    const int wid  = tid >> 5;
    const int wm   = wid & 3;        // 0..3  (m)
    const int wn   = wid >> 2;       // 0..1  (n)
    const int br   = blockIdx.y * GBM;
    const int bc   = blockIdx.x * GBN;
    const int qrow = lane >> 2;      // 0..7
    const int qcol = (lane & 3) * 2; // 0,2,4,6

    // staging registers
    float4 rA[4];
    uint4 rBh, rBl;

    const int arow = tid >> 1;            // 0..127
    const int acb  = (tid & 1) * 16;      // 0 or 16
    const float* Abase = A + (size_t)(br + arow) * K + acb;
    const int bn  = tid >> 2;             // 0..63
    const int bkg = (tid & 3) * 8;        // 0,8,16,24
    const __nv_bfloat16* BHbase = WtH + (size_t)(bc + bn) * K + bkg;
    const __nv_bfloat16* BLbase = WtL + (size_t)(bc + bn) * K + bkg;

    float acc[2][4][4];
    #pragma unroll
    for (int i = 0; i < 2; i++)
        #pragma unroll
        for (int j = 0; j < 4; j++)
            #pragma unroll
            for (int r = 0; r < 4; r++) acc[i][j][r] = 0.f;

    auto load_g = [&](int k0) {
        #pragma unroll
        for (int i = 0; i < 4; i++)
            rA[i] = *(const float4*)(Abase + k0 + i * 4);
        rBh = *(const uint4*)(BHbase + k0);
        rBl = *(const uint4*)(BLbase + k0);
    };

    auto store_s = [&](int s) {
        #pragma unroll
        for (int i = 0; i < 4; i++) {
            float f[4] = {rA[i].x, rA[i].y, rA[i].z, rA[i].w};
            #pragma unroll
            for (int p = 0; p < 2; p++) {
                __nv_bfloat16 h0, l0, h1, l1;
                bf16_split(f[p * 2],     h0, l0);
                bf16_split(f[p * 2 + 1], h1, l1);
                __nv_bfloat162 H; H.x = h0; H.y = h1;
                __nv_bfloat162 L; L.x = l0; L.y = l1;
                int off = arow * AKP + acb + i * 4 + p * 2;
                *(__nv_bfloat162*)&AsH[s][off] = H;
                *(__nv_bfloat162*)&AsL[s][off] = L;
            }
        }
        *(uint4*)&BsH[s][bn * AKP + bkg] = rBh;
        *(uint4*)&BsL[s][bn * AKP + bkg] = rBl;
    };

    auto compute = [&](int s) {
        #pragma unroll
        for (int kk = 0; kk < 2; kk++) {
            const int kb = kk * 16;
            unsigned aH[2][4], aL[2][4], bH[4][2], bL[4][2];
            #pragma unroll
            for (int ma = 0; ma < 2; ma++) {
                int m0 = wm * 32 + ma * 16 + qrow;
                int o00 = m0 * AKP + kb + qcol;
                int o10 = (m0 + 8) * AKP + kb + qcol;
                aH[ma][0] = *(const unsigned*)&AsH[s][o00];
                aH[ma][1] = *(const unsigned*)&AsH[s][o10];
                aH[ma][2] = *(const unsigned*)&AsH[s][o00 + 8];
                aH[ma][3] = *(const unsigned*)&AsH[s][o10 + 8];
                aL[ma][0] = *(const unsigned*)&AsL[s][o00];
                aL[ma][1] = *(const unsigned*)&AsL[s][o10];
                aL[ma][2] = *(const unsigned*)&AsL[s][o00 + 8];
                aL[ma][3] = *(const unsigned*)&AsL[s][o10 + 8];
            }
            #pragma unroll
            for (int na = 0; na < 4; na++) {
                int n0 = wn * 32 + na * 8 + qrow;
                int o = n0 * AKP + kb + qcol;
                bH[na][0] = *(const unsigned*)&BsH[s][o];
                bH[na][1] = *(const unsigned*)&BsH[s][o + 8];
                bL[na][0] = *(const unsigned*)&BsL[s][o];
                bL[na][1] = *(const unsigned*)&BsL[s][o + 8];
            }
            #pragma unroll
            for (int ma = 0; ma < 2; ma++)
                #pragma unroll
                for (int na = 0; na < 4; na++) {
                    mma_bf16(acc[ma][na], aH[ma], bH[na]);
                    mma_bf16(acc[ma][na], aH[ma], bL[na]);
                    mma_bf16(acc[ma][na], aL[ma], bH[na]);
                }
        }
    };

    load_g(0);
    store_s(0);
    __syncthreads();

    const int nst = K / GBK;
    for (int s0 = 0; s0 < nst; s0++) {
        int cur = s0 & 1;
        if (s0 + 1 < nst) load_g((s0 + 1) * GBK);
        compute(cur);
        if (s0 + 1 < nst) store_s(cur ^ 1);
        __syncthreads();
    }

    // epilogue
    #pragma unroll
    for (int ma = 0; ma < 2; ma++) {
        #pragma unroll
        for (int half = 0; half < 2; half++) {
            int gr = br + wm * 32 + ma * 16 + qrow + half * 8;
            #pragma unroll
            for (int na = 0; na < 4; na++) {
                int gc = bc + wn * 32 + na * 8 + qcol;
                float v0 = acc[ma][na][half * 2 + 0] + bias[gc];
                float v1 = acc[ma][na][half * 2 + 1] + bias[gc + 1];
                if (gelu) {
                    v0 = 0.5f * v0 * (1.0f + erff(v0 * 0.70710678118654752f));
                    v1 = 0.5f * v1 * (1.0f + erff(v1 * 0.70710678118654752f));
                }
                if (res) {
                    float2 r = *(const float2*)&res[(size_t)gr * N + gc];
                    v0 += r.x; v1 += r.y;
                }
                float2 ov = {v0, v1};
                *(float2*)&C[(size_t)gr * N + gc] = ov;
            }
        }
    }
}

// ---------------- attention (R1 style): K in smem, V via L1 ------------------
__global__ __launch_bounds__(256) void attention_kernel(
    const float* __restrict__ qkv, float* __restrict__ O)
{
    int h = blockIdx.x;
    int b = blockIdx.y;
    __shared__ float Ks[N_TOK * 33];
    __shared__ float qs[8 * 32];

    int tid = threadIdx.x;
    int w = tid >> 5, lane = tid & 31;
    const size_t base  = ((size_t)b * N_TOK) * QKV_DIM + h * HD;
    const size_t obase = ((size_t)b * N_TOK) * E_DIM + h * HD;

    for (int idx = tid; idx < N_TOK * 32; idx += 256) {
        int k = idx >> 5, d = idx & 31;
        Ks[k * 33 + d] = qkv[base + (size_t)k * QKV_DIM + 256 + d];
    }
    __syncthreads();

    for (int qi = w; qi < N_TOK; qi += 8) {
        qs[w * 32 + lane] = qkv[base + (size_t)qi * QKV_DIM + lane];
        __syncwarp();

        float e[9];
        #pragma unroll
        for (int j = 0; j < 9; j++) {
            int k = j * 32 + lane;
            float s;
            if (k < N_TOK) {
                s = 0.f;
                #pragma unroll
                for (int d = 0; d < 32; d++)
                    s = fmaf(qs[w * 32 + d], Ks[k * 33 + d], s);
            } else {
                s = -INFINITY;
            }
            e[j] = s;
        }
        float m = e[0];
        #pragma unroll
        for (int j = 1; j < 9; j++) m = fmaxf(m, e[j]);
        #pragma unroll
        for (int o = 16; o > 0; o >>= 1) m = fmaxf(m, __shfl_xor_sync(0xffffffffu, m, o));

        float p[9]; float sum = 0.f;
        #pragma unroll
        for (int j = 0; j < 9; j++) {
            int k = j * 32 + lane;
            p[j] = (k < N_TOK) ? __expf(e[j] - m) : 0.f;
            sum += p[j];
        }
        sum = warp_sum(sum);
        float scale = 1.f / (sum * 16.0f);   // /sqrt(E) applied AFTER softmax

        const float* Vb = qkv + base + 512 + lane;
        float acc = 0.f;
        #pragma unroll
        for (int j = 0; j < 8; j++) {
            #pragma unroll
            for (int kk = 0; kk < 32; kk++) {
                float a = __shfl_sync(0xffffffffu, p[j], kk);
                acc = fmaf(a, __ldg(Vb + (size_t)(j * 32 + kk) * QKV_DIM), acc);
            }
        }
        {
            float a = __shfl_sync(0xffffffffu, p[8], 0);
            acc = fmaf(a, __ldg(Vb + (size_t)256 * QKV_DIM), acc);
        }
        O[obase + (size_t)qi * E_DIM + lane] = acc * scale;
    }
}

// ---------------- mean-pool + head LN + linear -------------------------------
__global__ __launch_bounds__(256) void pool_head_kernel(
    const float* __restrict__ x, const float* __restrict__ g,
    const float* __restrict__ b, const float* __restrict__ W,
    const float* __restrict__ bias, float* __restrict__ out)
{
    int bb = blockIdx.x;
    int e = threadIdx.x;
    int w = e >> 5, lane = e & 31;
    float s = 0.f;
    const float* xb = x + (size_t)bb * N_TOK * E_DIM + e;
    for (int n = 0; n < N_TOK; n++) s += xb[(size_t)n * E_DIM];
    float pooled = s * (1.0f / N_TOK);

    __shared__ float sA[8], sB[8];
    float s1 = warp_sum(pooled);
    float s2 = warp_sum(pooled * pooled);
    if (lane == 0) { sA[w] = s1; sB[w] = s2; }
    __syncthreads();
    float tot = 0.f, tot2 = 0.f;
    #pragma unroll
    for (int i = 0; i < 8; i++) { tot += sA[i]; tot2 += sB[i]; }
    float mean = tot * (1.f / E_DIM);
    float var = tot2 * (1.f / E_DIM) - mean * mean;
    float rstd = rsqrtf(var + 1e-5f);
    float y = (pooled - mean) * rstd * g[e] + b[e];
    float t = y * W[e];
    __syncthreads();
    float t1 = warp_sum(t);
    if (lane == 0) sA[w] = t1;
    __syncthreads();
    if (e == 0) {
        float tot3 = 0.f;
        #pragma unroll
        for (int i = 0; i < 8; i++) tot3 += sA[i];
        out[bb] = tot3 + bias[0];
    }
}

// ---------------- driver ------------------------------------------------------
extern "C" void kernel_launch(void* const* d_in, const int* in_sizes, int n_in,
                              void* d_out, int out_size)
{
    const int*   user    = (const int*)  d_in[0];
    const int*   item    = (const int*)  d_in[1];
    const float* ut      = (const float*)d_in[2];
    const float* it      = (const float*)d_in[3];
    const float* cls     = (const float*)d_in[4];
    const float* pos     = (const float*)d_in[5];
    const float* ln1_g   = (const float*)d_in[6];
    const float* ln1_b   = (const float*)d_in[7];
    const float* Wq      = (const float*)d_in[8];
    const float* bq      = (const float*)d_in[9];
    const float* Wk      = (const float*)d_in[10];
    const float* bk      = (const float*)d_in[11];
    const float* Wv      = (const float*)d_in[12];
    const float* bv      = (const float*)d_in[13];
    const float* Wo      = (const float*)d_in[14];
    const float* bo      = (const float*)d_in[15];
    const float* ln2_g   = (const float*)d_in[16];
    const float* ln2_b   = (const float*)d_in[17];
    const float* W1      = (const float*)d_in[18];
    const float* b1      = (const float*)d_in[19];
    const float* W2      = (const float*)d_in[20];
    const float* b2      = (const float*)d_in[21];
    const float* head_g  = (const float*)d_in[22];
    const float* head_b  = (const float*)d_in[23];
    const float* head_W  = (const float*)d_in[24];
    const float* head_bi = (const float*)d_in[25];

    float *x, *h, *qkv, *o, *t, *bqkv;
    __nv_bfloat16 *WqkvH, *WqkvL, *WoH, *WoL, *W1H, *W1L, *W2H, *W2L;
    cudaGetSymbolAddress((void**)&x,     d_x);
    cudaGetSymbolAddress((void**)&h,     d_h);
    cudaGetSymbolAddress((void**)&qkv,   d_qkv);
    cudaGetSymbolAddress((void**)&o,     d_o);
    cudaGetSymbolAddress((void**)&t,     d_t);
    cudaGetSymbolAddress((void**)&bqkv,  d_bqkv);
    cudaGetSymbolAddress((void**)&WqkvH, d_WqkvH);
    cudaGetSymbolAddress((void**)&WqkvL, d_WqkvL);
    cudaGetSymbolAddress((void**)&WoH,   d_WoH);
    cudaGetSymbolAddress((void**)&WoL,   d_WoL);
    cudaGetSymbolAddress((void**)&W1H,   d_W1H);
    cudaGetSymbolAddress((void**)&W1L,   d_W1L);
    cudaGetSymbolAddress((void**)&W2H,   d_W2H);
    cudaGetSymbolAddress((void**)&W2L,   d_W2L);

    // pack weights (bf16 hi/lo, transposed to [l][N][K])
    {
        long long n;
        n = (long long)DEPTH * QKV_DIM * E_DIM;
        pack_qkv_kernel<<<(int)((n + 255) / 256), 256>>>(Wq, Wk, Wv, WqkvH, WqkvL);
        n = (long long)DEPTH * E_DIM * E_DIM;
        pack_t_kernel<<<(int)((n + 255) / 256), 256>>>(Wo, WoH, WoL, E_DIM, E_DIM);
        n = (long long)DEPTH * E_DIM * FF_DIM;
        pack_t_kernel<<<(int)((n + 255) / 256), 256>>>(W1, W1H, W1L, E_DIM, FF_DIM);
        pack_t_kernel<<<(int)((n + 255) / 256), 256>>>(W2, W2H, W2L, FF_DIM, E_DIM);
        int nb = DEPTH * QKV_DIM;
        pack_b_kernel<<<(nb + 255) / 256, 256>>>(bq, bk, bv, bqkv);
    }

    embed_kernel<<<dim3(N_TOK, B_DIM), 256>>>(user, item, ut, it, cls, pos, x);

    const dim3 gQKV(QKV_DIM / GBN, M_PAD / GBM);   // (12, 129)
    const dim3 gE(E_DIM / GBN, M_PAD / GBM);       // (4, 129)
    const dim3 gFF(FF_DIM / GBN, M_PAD / GBM);     // (16, 129)
    const int  lnGrid = M_ROWS / 8;                // 2056

    for (int l = 0; l < DEPTH; l++) {
        size_t eOff   = (size_t)l * E_DIM;
        size_t eeOff  = (size_t)l * E_DIM * E_DIM;
        size_t ffOff  = (size_t)l * E_DIM * FF_DIM;
        size_t qkvOff = (size_t)l * E_DIM * QKV_DIM;

        layernorm_kernel<<<lnGrid, 256>>>(x, ln1_g + eOff, ln1_b + eOff, h);

        tgemm_kernel<<<gQKV, 256>>>(h, WqkvH + qkvOff, WqkvL + qkvOff,
                                    bqkv + (size_t)l * QKV_DIM, nullptr, qkv,
                                    E_DIM, QKV_DIM, 0);

        attention_kernel<<<dim3(H_DIM, B_DIM), 256>>>(qkv, o);

        // x = x + (o @ Wo + bo)
        tgemm_kernel<<<gE, 256>>>(o, WoH + eeOff, WoL + eeOff,
                                  bo + eOff, x, x, E_DIM, E_DIM, 0);

        layernorm_kernel<<<lnGrid, 256>>>(x, ln2_g + eOff, ln2_b + eOff, h);

        // t = gelu(h @ W1 + b1)
        tgemm_kernel<<<gFF, 256>>>(h, W1H + ffOff, W1L + ffOff,
                                   b1 + (size_t)l * FF_DIM, nullptr, t,
                                   E_DIM, FF_DIM, 1);
        // x = x + (t @ W2 + b2)
        tgemm_kernel<<<gE, 256>>>(t, W2H + ffOff, W2L + ffOff,
                                  b2 + eOff, x, x, FF_DIM, E_DIM, 0);
    }

    pool_head_kernel<<<B_DIM, 256>>>(x, head_g, head_b, head_W, head_bi,
                                     (float*)d_out);
}

// round 4
// speedup vs baseline: 2.3342x; 1.4392x over previous
#include <cuda_runtime.h>
#include <cuda_bf16.h>
#include <math.h>

// Problem constants
#define DEPTH 12
#define E_DIM 256
#define F_DIM 128
#define H_DIM 8
#define HD 32
#define U_DIM 1000
#define I_DIM 1000
#define B_DIM 64
#define N_TOK 257                  // 2F+1
#define M_ROWS (B_DIM * N_TOK)     // 16448
#define M_PAD 16512                // 129*128 (pad rows: finite junk, never read as outputs)
#define FF_DIM 1024
#define QKV_DIM 768

// ---------------- scratch (device globals; zero-init, no allocation) --------
__device__ float d_x[M_PAD * E_DIM];
__device__ float d_qkv[M_PAD * QKV_DIM];
__device__ float d_bqkv[DEPTH * QKV_DIM];
// bf16 hi/lo activations
__device__ __nv_bfloat16 d_hH[M_PAD * E_DIM];
__device__ __nv_bfloat16 d_hL[M_PAD * E_DIM];
__device__ __nv_bfloat16 d_oH[M_PAD * E_DIM];
__device__ __nv_bfloat16 d_oL[M_PAD * E_DIM];
__device__ __nv_bfloat16 d_tH[M_PAD * FF_DIM];
__device__ __nv_bfloat16 d_tL[M_PAD * FF_DIM];
// packed bf16 hi/lo transposed weights: layout [l][N][K]
__device__ __nv_bfloat16 d_WqkvH[DEPTH * QKV_DIM * E_DIM];
__device__ __nv_bfloat16 d_WqkvL[DEPTH * QKV_DIM * E_DIM];
__device__ __nv_bfloat16 d_WoH[DEPTH * E_DIM * E_DIM];
__device__ __nv_bfloat16 d_WoL[DEPTH * E_DIM * E_DIM];
__device__ __nv_bfloat16 d_W1H[DEPTH * FF_DIM * E_DIM];
__device__ __nv_bfloat16 d_W1L[DEPTH * FF_DIM * E_DIM];
__device__ __nv_bfloat16 d_W2H[DEPTH * E_DIM * FF_DIM];
__device__ __nv_bfloat16 d_W2L[DEPTH * E_DIM * FF_DIM];

// ---------------- bf16 split helper -----------------------------------------
__device__ __forceinline__ void bf16_split(float x, __nv_bfloat16& h, __nv_bfloat16& l) {
    h = __float2bfloat16(x);
    l = __float2bfloat16(x - __bfloat162float(h));
}

// ---------------- weight pack: out[l][n][k] = split(W[l][k][n]) -------------
__global__ __launch_bounds__(256) void pack_t_kernel(
    const float* __restrict__ W, __nv_bfloat16* __restrict__ oh,
    __nv_bfloat16* __restrict__ ol, int K, int N)
{
    long long idx = (long long)blockIdx.x * 256 + threadIdx.x;
    long long tot = (long long)DEPTH * K * N;
    if (idx >= tot) return;
    int k = idx % K;
    int n = (idx / K) % N;
    int l = idx / ((long long)K * N);
    float v = W[((long long)l * K + k) * N + n];
    __nv_bfloat16 h, lo; bf16_split(v, h, lo);
    oh[idx] = h; ol[idx] = lo;
}

__global__ __launch_bounds__(256) void pack_qkv_kernel(
    const float* __restrict__ Wq, const float* __restrict__ Wk,
    const float* __restrict__ Wv, __nv_bfloat16* __restrict__ oh,
    __nv_bfloat16* __restrict__ ol)
{
    long long idx = (long long)blockIdx.x * 256 + threadIdx.x;
    long long tot = (long long)DEPTH * QKV_DIM * E_DIM;
    if (idx >= tot) return;
    int k = idx % E_DIM;
    int n = (idx / E_DIM) % QKV_DIM;
    int l = idx / ((long long)E_DIM * QKV_DIM);
    const float* W = (n < 256) ? Wq : (n < 512) ? Wk : Wv;
    int nn = n & 255;
    float v = W[((long long)l * E_DIM + k) * E_DIM + nn];
    __nv_bfloat16 h, lo; bf16_split(v, h, lo);
    oh[idx] = h; ol[idx] = lo;
}

__global__ __launch_bounds__(256) void pack_b_kernel(
    const float* __restrict__ bq, const float* __restrict__ bk,
    const float* __restrict__ bv, float* __restrict__ bqkv)
{
    int idx = blockIdx.x * 256 + threadIdx.x;
    if (idx >= DEPTH * QKV_DIM) return;
    int n = idx % QKV_DIM;
    int l = idx / QKV_DIM;
    float v;
    if (n < 256)      v = bq[l * E_DIM + n];
    else if (n < 512) v = bk[l * E_DIM + (n - 256)];
    else              v = bv[l * E_DIM + (n - 512)];
    bqkv[idx] = v;
}

// ---------------- embedding --------------------------------------------------
__global__ __launch_bounds__(256) void embed_kernel(
    const int* __restrict__ user, const int* __restrict__ item,
    const float* __restrict__ ut, const float* __restrict__ it,
    const float* __restrict__ cls, const float* __restrict__ pos,
    float* __restrict__ x)
{
    int n = blockIdx.x;
    int b = blockIdx.y;
    int e = threadIdx.x;
    float v;
    if (n == 0) {
        v = cls[e];
    } else if (n <= F_DIM) {
        int uid = user[b];
        v = ut[((size_t)e * U_DIM + uid) * F_DIM + (n - 1)];
    } else {
        int iid = item[b];
        v = it[((size_t)e * I_DIM + iid) * F_DIM + (n - 1 - F_DIM)];
    }
    x[((size_t)b * N_TOK + n) * E_DIM + e] = v + pos[(size_t)n * E_DIM + e];
}

// ---------------- layernorm: warp per row, emits bf16 hi/lo ------------------
__device__ __forceinline__ float warp_sum(float v) {
    #pragma unroll
    for (int o = 16; o > 0; o >>= 1) v += __shfl_xor_sync(0xffffffffu, v, o);
    return v;
}

__global__ __launch_bounds__(256) void layernorm_kernel(
    const float* __restrict__ x, const float* __restrict__ g,
    const float* __restrict__ b,
    __nv_bfloat16* __restrict__ outH, __nv_bfloat16* __restrict__ outL)
{
    int row  = blockIdx.x * 8 + (threadIdx.x >> 5);
    int lane = threadIdx.x & 31;
    const float4* xr = (const float4*)(x + (size_t)row * E_DIM);
    float4 v0 = xr[lane * 2];
    float4 v1 = xr[lane * 2 + 1];
    float s  = v0.x + v0.y + v0.z + v0.w + v1.x + v1.y + v1.z + v1.w;
    float ss = v0.x*v0.x + v0.y*v0.y + v0.z*v0.z + v0.w*v0.w
             + v1.x*v1.x + v1.y*v1.y + v1.z*v1.z + v1.w*v1.w;
    s  = warp_sum(s);
    ss = warp_sum(ss);
    float mean = s * (1.f / E_DIM);
    float var  = ss * (1.f / E_DIM) - mean * mean;
    float rstd = rsqrtf(var + 1e-5f);

    float vv[8] = {v0.x, v0.y, v0.z, v0.w, v1.x, v1.y, v1.z, v1.w};
    const float* gp = g + lane * 8;
    const float* bp = b + lane * 8;
    __nv_bfloat162 H[4], L[4];
    #pragma unroll
    for (int i = 0; i < 4; i++) {
        float y0 = (vv[2*i]   - mean) * rstd * gp[2*i]   + bp[2*i];
        float y1 = (vv[2*i+1] - mean) * rstd * gp[2*i+1] + bp[2*i+1];
        __nv_bfloat16 h0, l0, h1, l1;
        bf16_split(y0, h0, l0);
        bf16_split(y1, h1, l1);
        H[i].x = h0; H[i].y = h1;
        L[i].x = l0; L[i].y = l1;
    }
    __nv_bfloat162* oh = (__nv_bfloat162*)(outH + (size_t)row * E_DIM) + lane * 4;
    __nv_bfloat162* ol = (__nv_bfloat162*)(outL + (size_t)row * E_DIM) + lane * 4;
    #pragma unroll
    for (int i = 0; i < 4; i++) { oh[i] = H[i]; ol[i] = L[i]; }
}

// ---------------- tensor-core GEMM (bf16x2 split, m16n8k16) ------------------
// C[M_PAD x N] = A(hi/lo bf16)[M_PAD x K] @ Wt(hi/lo)[N x K] + bias
//   output: Cf (fp32) or Ch/Cl (bf16 hi/lo, with optional gelu); optional res.
#define GBM 128
#define GBN 64
#define GBK 32
#define AKP 40

__device__ __forceinline__ void mma_bf16(float* c, const unsigned* a, const unsigned* b) {
    asm volatile(
        "mma.sync.aligned.m16n8k16.row.col.f32.bf16.bf16.f32 "
        "{%0,%1,%2,%3}, {%4,%5,%6,%7}, {%8,%9}, {%0,%1,%2,%3};\n"
        : "+f"(c[0]), "+f"(c[1]), "+f"(c[2]), "+f"(c[3])
        : "r"(a[0]), "r"(a[1]), "r"(a[2]), "r"(a[3]), "r"(b[0]), "r"(b[1]));
}

__global__ __launch_bounds__(256) void tgemm_kernel(
    const __nv_bfloat16* __restrict__ AH, const __nv_bfloat16* __restrict__ AL,
    const __nv_bfloat16* __restrict__ WtH, const __nv_bfloat16* __restrict__ WtL,
    const float* __restrict__ bias, const float* __restrict__ res,
    float* __restrict__ Cf,
    __nv_bfloat16* __restrict__ Ch, __nv_bfloat16* __restrict__ Cl,
    int K, int N, int gelu)
{
    __shared__ __nv_bfloat16 AsH[2][GBM * AKP];
    __shared__ __nv_bfloat16 AsL[2][GBM * AKP];
    __shared__ __nv_bfloat16 BsH[2][GBN * AKP];
    __shared__ __nv_bfloat16 BsL[2][GBN * AKP];

    const int tid  = threadIdx.x;
    const int lane = tid & 31;
    const int wid  = tid >> 5;
    const int wm   = wid & 3;
    const int wn   = wid >> 2;
    const int br   = blockIdx.y * GBM;
    const int bc   = blockIdx.x * GBN;
    const int qrow = lane >> 2;
    const int qcol = (lane & 3) * 2;

    uint4 rAh[2], rAl[2], rBh, rBl;

    const int arow = tid >> 1;            // 0..127
    const int akh  = (tid & 1) * 16;      // 0 or 16
    const __nv_bfloat16* AHbase = AH + (size_t)(br + arow) * K + akh;
    const __nv_bfloat16* ALbase = AL + (size_t)(br + arow) * K + akh;
    const int bn  = tid >> 2;
    const int bkg = (tid & 3) * 8;
    const __nv_bfloat16* BHbase = WtH + (size_t)(bc + bn) * K + bkg;
    const __nv_bfloat16* BLbase = WtL + (size_t)(bc + bn) * K + bkg;

    float acc[2][4][4];
    #pragma unroll
    for (int i = 0; i < 2; i++)
        #pragma unroll
        for (int j = 0; j < 4; j++)
            #pragma unroll
            for (int r = 0; r < 4; r++) acc[i][j][r] = 0.f;

    auto load_g = [&](int k0) {
        rAh[0] = *(const uint4*)(AHbase + k0);
        rAh[1] = *(const uint4*)(AHbase + k0 + 8);
        rAl[0] = *(const uint4*)(ALbase + k0);
        rAl[1] = *(const uint4*)(ALbase + k0 + 8);
        rBh = *(const uint4*)(BHbase + k0);
        rBl = *(const uint4*)(BLbase + k0);
    };

    auto store_s = [&](int s) {
        int off = arow * AKP + akh;
        *(uint4*)&AsH[s][off]     = rAh[0];
        *(uint4*)&AsH[s][off + 8] = rAh[1];
        *(uint4*)&AsL[s][off]     = rAl[0];
        *(uint4*)&AsL[s][off + 8] = rAl[1];
        *(uint4*)&BsH[s][bn * AKP + bkg] = rBh;
        *(uint4*)&BsL[s][bn * AKP + bkg] = rBl;
    };

    auto compute = [&](int s) {
        #pragma unroll
        for (int kk = 0; kk < 2; kk++) {
            const int kb = kk * 16;
            unsigned aH[2][4], aL[2][4], bH[4][2], bL[4][2];
            #pragma unroll
            for (int ma = 0; ma < 2; ma++) {
                int m0 = wm * 32 + ma * 16 + qrow;
                int o00 = m0 * AKP + kb + qcol;
                int o10 = (m0 + 8) * AKP + kb + qcol;
                aH[ma][0] = *(const unsigned*)&AsH[s][o00];
                aH[ma][1] = *(const unsigned*)&AsH[s][o10];
                aH[ma][2] = *(const unsigned*)&AsH[s][o00 + 8];
                aH[ma][3] = *(const unsigned*)&AsH[s][o10 + 8];
                aL[ma][0] = *(const unsigned*)&AsL[s][o00];
                aL[ma][1] = *(const unsigned*)&AsL[s][o10];
                aL[ma][2] = *(const unsigned*)&AsL[s][o00 + 8];
                aL[ma][3] = *(const unsigned*)&AsL[s][o10 + 8];
            }
            #pragma unroll
            for (int na = 0; na < 4; na++) {
                int n0 = wn * 32 + na * 8 + qrow;
                int o = n0 * AKP + kb + qcol;
                bH[na][0] = *(const unsigned*)&BsH[s][o];
                bH[na][1] = *(const unsigned*)&BsH[s][o + 8];
                bL[na][0] = *(const unsigned*)&BsL[s][o];
                bL[na][1] = *(const unsigned*)&BsL[s][o + 8];
            }
            #pragma unroll
            for (int ma = 0; ma < 2; ma++)
                #pragma unroll
                for (int na = 0; na < 4; na++) {
                    mma_bf16(acc[ma][na], aH[ma], bH[na]);
                    mma_bf16(acc[ma][na], aH[ma], bL[na]);
                    mma_bf16(acc[ma][na], aL[ma], bH[na]);
                }
        }
    };

    load_g(0);
    store_s(0);
    __syncthreads();

    const int nst = K / GBK;
    for (int s0 = 0; s0 < nst; s0++) {
        int cur = s0 & 1;
        if (s0 + 1 < nst) load_g((s0 + 1) * GBK);
        compute(cur);
        if (s0 + 1 < nst) store_s(cur ^ 1);
        __syncthreads();
    }

    // epilogue
    #pragma unroll
    for (int ma = 0; ma < 2; ma++) {
        #pragma unroll
        for (int half = 0; half < 2; half++) {
            int gr = br + wm * 32 + ma * 16 + qrow + half * 8;
            #pragma unroll
            for (int na = 0; na < 4; na++) {
                int gc = bc + wn * 32 + na * 8 + qcol;
                float v0 = acc[ma][na][half * 2 + 0] + bias[gc];
                float v1 = acc[ma][na][half * 2 + 1] + bias[gc + 1];
                if (gelu) {
                    v0 = 0.5f * v0 * (1.0f + erff(v0 * 0.70710678118654752f));
                    v1 = 0.5f * v1 * (1.0f + erff(v1 * 0.70710678118654752f));
                }
                if (res) {
                    float2 r = *(const float2*)&res[(size_t)gr * N + gc];
                    v0 += r.x; v1 += r.y;
                }
                if (Cf) {
                    float2 ov = {v0, v1};
                    *(float2*)&Cf[(size_t)gr * N + gc] = ov;
                }
                if (Ch) {
                    __nv_bfloat16 h0, l0, h1, l1;
                    bf16_split(v0, h0, l0);
                    bf16_split(v1, h1, l1);
                    __nv_bfloat162 Hh; Hh.x = h0; Hh.y = h1;
                    __nv_bfloat162 Ll; Ll.x = l0; Ll.y = l1;
                    *(__nv_bfloat162*)&Ch[(size_t)gr * N + gc] = Hh;
                    *(__nv_bfloat162*)&Cl[(size_t)gr * N + gc] = Ll;
                }
            }
        }
    }
}

// ---------------- attention: 4 queries/warp, K + V^T + P in smem -------------
// per (h, b) block. energies fp32; att = softmax(e)/sqrt(E); output bf16 hi/lo.
#define KS_ROWS 264
#define KS_PITCH 36
#define VT_PITCH 268
#define PS_PITCH 264
#define ATT_SMEM ((KS_ROWS * KS_PITCH + 32 * VT_PITCH + 32 * PS_PITCH + 32 * KS_PITCH) * 4)

__global__ __launch_bounds__(256) void attention_kernel(
    const float* __restrict__ qkv,
    __nv_bfloat16* __restrict__ oH, __nv_bfloat16* __restrict__ oL)
{
    extern __shared__ float sm[];
    float* Ks  = sm;                           // [264][36]
    float* VsT = Ks + KS_ROWS * KS_PITCH;      // [32][268]
    float* Ps  = VsT + 32 * VT_PITCH;          // [32][264]
    float* qs  = Ps + 32 * PS_PITCH;           // [32][36]

    const int h = blockIdx.x;
    const int b = blockIdx.y;
    const int tid = threadIdx.x;
    const int w = tid >> 5, lane = tid & 31;
    const size_t base = ((size_t)b * N_TOK) * QKV_DIM + h * HD;

    // load K (rows) and V (transposed) into smem; zero-pad keys 257..263
    for (int idx = tid; idx < KS_ROWS * 32; idx += 256) {
        int k = idx >> 5, d = idx & 31;
        float kv = 0.f, vv = 0.f;
        if (k < N_TOK) {
            kv = qkv[base + (size_t)k * QKV_DIM + 256 + d];
            vv = qkv[base + (size_t)k * QKV_DIM + 512 + d];
        }
        Ks[k * KS_PITCH + d] = kv;
        VsT[d * VT_PITCH + k] = vv;
    }
    __syncthreads();

    const int qr = lane >> 3;             // 0..3
    const int d4 = (lane & 7) * 4;        // 0..28
    float* myqs[4];
    #pragma unroll
    for (int q = 0; q < 4; q++) myqs[q] = qs + (w * 4 + q) * KS_PITCH;

    for (int it = 0; it < 9; it++) {
        int qbase = it * 32;

        // warp-local q tile load (4 queries x 32 dims)
        __syncwarp();
        {
            int query = qbase + w * 4 + qr;
            float4 qv = {0.f, 0.f, 0.f, 0.f};
            if (query < N_TOK)
                qv = *(const float4*)&qkv[base + (size_t)query * QKV_DIM + d4];
            *(float4*)&qs[(w * 4 + qr) * KS_PITCH + d4] = qv;
        }
        __syncwarp();

        // QK: e[q][j], lane = key within group j
        float e[4][9];
        #pragma unroll
        for (int q = 0; q < 4; q++)
            #pragma unroll
            for (int j = 0; j < 9; j++) e[q][j] = 0.f;

        #pragma unroll
        for (int dd = 0; dd < 8; dd++) {
            float4 qv[4];
            #pragma unroll
            for (int q = 0; q < 4; q++)
                qv[q] = *(const float4*)&myqs[q][dd * 4];
            #pragma unroll
            for (int j = 0; j < 9; j++) {
                int key = j * 32 + lane;
                int kc = (key < KS_ROWS) ? key : 0;
                float4 kv = *(const float4*)&Ks[kc * KS_PITCH + dd * 4];
                #pragma unroll
                for (int q = 0; q < 4; q++) {
                    e[q][j] = fmaf(qv[q].x, kv.x, e[q][j]);
                    e[q][j] = fmaf(qv[q].y, kv.y, e[q][j]);
                    e[q][j] = fmaf(qv[q].z, kv.z, e[q][j]);
                    e[q][j] = fmaf(qv[q].w, kv.w, e[q][j]);
                }
            }
        }
        // mask invalid keys
        #pragma unroll
        for (int j = 0; j < 9; j++) {
            int key = j * 32 + lane;
            if (key >= N_TOK)
                #pragma unroll
                for (int q = 0; q < 4; q++) e[q][j] = -INFINITY;
        }

        // softmax (unnormalized p in smem, scale kept in regs)
        float scale[4];
        #pragma unroll
        for (int q = 0; q < 4; q++) {
            float m = e[q][0];
            #pragma unroll
            for (int j = 1; j < 9; j++) m = fmaxf(m, e[q][j]);
            #pragma unroll
            for (int o = 16; o > 0; o >>= 1)
                m = fmaxf(m, __shfl_xor_sync(0xffffffffu, m, o));
            float sum = 0.f;
            #pragma unroll
            for (int j = 0; j < 9; j++) {
                int key = j * 32 + lane;
                float p = (key < N_TOK) ? __expf(e[q][j] - m) : 0.f;
                e[q][j] = p;
                sum += p;
            }
            sum = warp_sum(sum);
            scale[q] = 1.f / (sum * 16.0f);   // /sqrt(E) after softmax
            #pragma unroll
            for (int j = 0; j < 9; j++) {
                int key = j * 32 + lane;
                if (key < KS_ROWS)
                    Ps[(w * 4 + q) * PS_PITCH + key] = e[q][j];
            }
        }
        __syncwarp();

        // PV: lane = output dim d; dot(P[q], V^T[d]) over 264 keys
        float acc[4] = {0.f, 0.f, 0.f, 0.f};
        #pragma unroll 4
        for (int k4 = 0; k4 < PS_PITCH / 4; k4++) {
            float4 vv = *(const float4*)&VsT[lane * VT_PITCH + k4 * 4];
            #pragma unroll
            for (int q = 0; q < 4; q++) {
                float4 pv = *(const float4*)&Ps[(w * 4 + q) * PS_PITCH + k4 * 4];
                acc[q] = fmaf(pv.x, vv.x, acc[q]);
                acc[q] = fmaf(pv.y, vv.y, acc[q]);
                acc[q] = fmaf(pv.z, vv.z, acc[q]);
                acc[q] = fmaf(pv.w, vv.w, acc[q]);
            }
        }

        #pragma unroll
        for (int q = 0; q < 4; q++) {
            int query = qbase + w * 4 + q;
            if (query < N_TOK) {
                float val = acc[q] * scale[q];
                size_t oidx = ((size_t)b * N_TOK + query) * E_DIM + h * HD + lane;
                __nv_bfloat16 hh, ll;
                bf16_split(val, hh, ll);
                oH[oidx] = hh;
                oL[oidx] = ll;
            }
        }
        __syncwarp();
    }
}

// ---------------- mean-pool + head LN + linear -------------------------------
__global__ __launch_bounds__(256) void pool_head_kernel(
    const float* __restrict__ x, const float* __restrict__ g,
    const float* __restrict__ b, const float* __restrict__ W,
    const float* __restrict__ bias, float* __restrict__ out)
{
    int bb = blockIdx.x;
    int e = threadIdx.x;
    int w = e >> 5, lane = e & 31;
    float s = 0.f;
    const float* xb = x + (size_t)bb * N_TOK * E_DIM + e;
    for (int n = 0; n < N_TOK; n++) s += xb[(size_t)n * E_DIM];
    float pooled = s * (1.0f / N_TOK);

    __shared__ float sA[8], sB[8];
    float s1 = warp_sum(pooled);
    float s2 = warp_sum(pooled * pooled);
    if (lane == 0) { sA[w] = s1; sB[w] = s2; }
    __syncthreads();
    float tot = 0.f, tot2 = 0.f;
    #pragma unroll
    for (int i = 0; i < 8; i++) { tot += sA[i]; tot2 += sB[i]; }
    float mean = tot * (1.f / E_DIM);
    float var = tot2 * (1.f / E_DIM) - mean * mean;
    float rstd = rsqrtf(var + 1e-5f);
    float y = (pooled - mean) * rstd * g[e] + b[e];
    float t = y * W[e];
    __syncthreads();
    float t1 = warp_sum(t);
    if (lane == 0) sA[w] = t1;
    __syncthreads();
    if (e == 0) {
        float tot3 = 0.f;
        #pragma unroll
        for (int i = 0; i < 8; i++) tot3 += sA[i];
        out[bb] = tot3 + bias[0];
    }
}

// ---------------- driver ------------------------------------------------------
extern "C" void kernel_launch(void* const* d_in, const int* in_sizes, int n_in,
                              void* d_out, int out_size)
{
    const int*   user    = (const int*)  d_in[0];
    const int*   item    = (const int*)  d_in[1];
    const float* ut      = (const float*)d_in[2];
    const float* it      = (const float*)d_in[3];
    const float* cls     = (const float*)d_in[4];
    const float* pos     = (const float*)d_in[5];
    const float* ln1_g   = (const float*)d_in[6];
    const float* ln1_b   = (const float*)d_in[7];
    const float* Wq      = (const float*)d_in[8];
    const float* bq      = (const float*)d_in[9];
    const float* Wk      = (const float*)d_in[10];
    const float* bk      = (const float*)d_in[11];
    const float* Wv      = (const float*)d_in[12];
    const float* bv      = (const float*)d_in[13];
    const float* Wo      = (const float*)d_in[14];
    const float* bo      = (const float*)d_in[15];
    const float* ln2_g   = (const float*)d_in[16];
    const float* ln2_b   = (const float*)d_in[17];
    const float* W1      = (const float*)d_in[18];
    const float* b1      = (const float*)d_in[19];
    const float* W2      = (const float*)d_in[20];
    const float* b2      = (const float*)d_in[21];
    const float* head_g  = (const float*)d_in[22];
    const float* head_b  = (const float*)d_in[23];
    const float* head_W  = (const float*)d_in[24];
    const float* head_bi = (const float*)d_in[25];

    float *x, *qkv, *bqkv;
    __nv_bfloat16 *hH, *hL, *oH, *oL, *tH, *tL;
    __nv_bfloat16 *WqkvH, *WqkvL, *WoH, *WoL, *W1H, *W1L, *W2H, *W2L;
    cudaGetSymbolAddress((void**)&x,     d_x);
    cudaGetSymbolAddress((void**)&qkv,   d_qkv);
    cudaGetSymbolAddress((void**)&bqkv,  d_bqkv);
    cudaGetSymbolAddress((void**)&hH,    d_hH);
    cudaGetSymbolAddress((void**)&hL,    d_hL);
    cudaGetSymbolAddress((void**)&oH,    d_oH);
    cudaGetSymbolAddress((void**)&oL,    d_oL);
    cudaGetSymbolAddress((void**)&tH,    d_tH);
    cudaGetSymbolAddress((void**)&tL,    d_tL);
    cudaGetSymbolAddress((void**)&WqkvH, d_WqkvH);
    cudaGetSymbolAddress((void**)&WqkvL, d_WqkvL);
    cudaGetSymbolAddress((void**)&WoH,   d_WoH);
    cudaGetSymbolAddress((void**)&WoL,   d_WoL);
    cudaGetSymbolAddress((void**)&W1H,   d_W1H);
    cudaGetSymbolAddress((void**)&W1L,   d_W1L);
    cudaGetSymbolAddress((void**)&W2H,   d_W2H);
    cudaGetSymbolAddress((void**)&W2L,   d_W2L);

    cudaFuncSetAttribute(attention_kernel,
                         cudaFuncAttributeMaxDynamicSharedMemorySize, ATT_SMEM);

    // pack weights (bf16 hi/lo, transposed to [l][N][K])
    {
        long long n;
        n = (long long)DEPTH * QKV_DIM * E_DIM;
        pack_qkv_kernel<<<(int)((n + 255) / 256), 256>>>(Wq, Wk, Wv, WqkvH, WqkvL);
        n = (long long)DEPTH * E_DIM * E_DIM;
        pack_t_kernel<<<(int)((n + 255) / 256), 256>>>(Wo, WoH, WoL, E_DIM, E_DIM);
        n = (long long)DEPTH * E_DIM * FF_DIM;
        pack_t_kernel<<<(int)((n + 255) / 256), 256>>>(W1, W1H, W1L, E_DIM, FF_DIM);
        pack_t_kernel<<<(int)((n + 255) / 256), 256>>>(W2, W2H, W2L, FF_DIM, E_DIM);
        int nb = DEPTH * QKV_DIM;
        pack_b_kernel<<<(nb + 255) / 256, 256>>>(bq, bk, bv, bqkv);
    }

    embed_kernel<<<dim3(N_TOK, B_DIM), 256>>>(user, item, ut, it, cls, pos, x);

    const dim3 gQKV(QKV_DIM / GBN, M_PAD / GBM);   // (12, 129)
    const dim3 gE(E_DIM / GBN, M_PAD / GBM);       // (4, 129)
    const dim3 gFF(FF_DIM / GBN, M_PAD / GBM);     // (16, 129)
    const int  lnGrid = M_ROWS / 8;                // 2056

    for (int l = 0; l < DEPTH; l++) {
        size_t eOff   = (size_t)l * E_DIM;
        size_t eeOff  = (size_t)l * E_DIM * E_DIM;
        size_t ffOff  = (size_t)l * E_DIM * FF_DIM;
        size_t qkvOff = (size_t)l * E_DIM * QKV_DIM;

        layernorm_kernel<<<lnGrid, 256>>>(x, ln1_g + eOff, ln1_b + eOff, hH, hL);

        tgemm_kernel<<<gQKV, 256>>>(hH, hL, WqkvH + qkvOff, WqkvL + qkvOff,
                                    bqkv + (size_t)l * QKV_DIM, nullptr,
                                    qkv, nullptr, nullptr, E_DIM, QKV_DIM, 0);

        attention_kernel<<<dim3(H_DIM, B_DIM), 256, ATT_SMEM>>>(qkv, oH, oL);

        // x = x + (o @ Wo + bo)
        tgemm_kernel<<<gE, 256>>>(oH, oL, WoH + eeOff, WoL + eeOff,
                                  bo + eOff, x, x, nullptr, nullptr,
                                  E_DIM, E_DIM, 0);

        layernorm_kernel<<<lnGrid, 256>>>(x, ln2_g + eOff, ln2_b + eOff, hH, hL);

        // t = gelu(h @ W1 + b1)  (bf16 hi/lo output)
        tgemm_kernel<<<gFF, 256>>>(hH, hL, W1H + ffOff, W1L + ffOff,
                                   b1 + (size_t)l * FF_DIM, nullptr,
                                   nullptr, tH, tL, E_DIM, FF_DIM, 1);
        // x = x + (t @ W2 + b2)
        tgemm_kernel<<<gE, 256>>>(tH, tL, W2H + ffOff, W2L + ffOff,
                                  b2 + eOff, x, x, nullptr, nullptr,
                                  FF_DIM, E_DIM, 0);
    }

    pool_head_kernel<<<B_DIM, 256>>>(x, head_g, head_b, head_W, head_bi,
                                     (float*)d_out);
}

// round 5
// speedup vs baseline: 2.5221x; 1.0805x over previous
#include <cuda_runtime.h>
#include <cuda_bf16.h>
#include <math.h>

// Problem constants
#define DEPTH 12
#define E_DIM 256
#define F_DIM 128
#define H_DIM 8
#define HD 32
#define U_DIM 1000
#define I_DIM 1000
#define B_DIM 64
#define N_TOK 257                  // 2F+1
#define M_ROWS (B_DIM * N_TOK)     // 16448
#define M_PAD 16512                // 129*128 (pad rows: finite junk, never read as outputs)
#define FF_DIM 1024
#define QKV_DIM 768

// ---------------- scratch (device globals; zero-init, no allocation) --------
__device__ float d_x[M_PAD * E_DIM];
__device__ float d_qkv[M_PAD * QKV_DIM];
__device__ float d_bqkv[DEPTH * QKV_DIM];
// bf16 hi/lo activations
__device__ __nv_bfloat16 d_hH[M_PAD * E_DIM];
__device__ __nv_bfloat16 d_hL[M_PAD * E_DIM];
__device__ __nv_bfloat16 d_oH[M_PAD * E_DIM];
__device__ __nv_bfloat16 d_oL[M_PAD * E_DIM];
__device__ __nv_bfloat16 d_tH[M_PAD * FF_DIM];
__device__ __nv_bfloat16 d_tL[M_PAD * FF_DIM];
// packed bf16 hi/lo transposed weights: layout [l][N][K]
__device__ __nv_bfloat16 d_WqkvH[DEPTH * QKV_DIM * E_DIM];
__device__ __nv_bfloat16 d_WqkvL[DEPTH * QKV_DIM * E_DIM];
__device__ __nv_bfloat16 d_WoH[DEPTH * E_DIM * E_DIM];
__device__ __nv_bfloat16 d_WoL[DEPTH * E_DIM * E_DIM];
__device__ __nv_bfloat16 d_W1H[DEPTH * FF_DIM * E_DIM];
__device__ __nv_bfloat16 d_W1L[DEPTH * FF_DIM * E_DIM];
__device__ __nv_bfloat16 d_W2H[DEPTH * E_DIM * FF_DIM];
__device__ __nv_bfloat16 d_W2L[DEPTH * E_DIM * FF_DIM];

// ---------------- bf16 split helper -----------------------------------------
__device__ __forceinline__ void bf16_split(float x, __nv_bfloat16& h, __nv_bfloat16& l) {
    h = __float2bfloat16(x);
    l = __float2bfloat16(x - __bfloat162float(h));
}

// ---------------- weight pack: out[l][n][k] = split(W[l][k][n]) -------------
__global__ __launch_bounds__(256) void pack_t_kernel(
    const float* __restrict__ W, __nv_bfloat16* __restrict__ oh,
    __nv_bfloat16* __restrict__ ol, int K, int N)
{
    long long idx = (long long)blockIdx.x * 256 + threadIdx.x;
    long long tot = (long long)DEPTH * K * N;
    if (idx >= tot) return;
    int k = idx % K;
    int n = (idx / K) % N;
    int l = idx / ((long long)K * N);
    float v = W[((long long)l * K + k) * N + n];
    __nv_bfloat16 h, lo; bf16_split(v, h, lo);
    oh[idx] = h; ol[idx] = lo;
}

__global__ __launch_bounds__(256) void pack_qkv_kernel(
    const float* __restrict__ Wq, const float* __restrict__ Wk,
    const float* __restrict__ Wv, __nv_bfloat16* __restrict__ oh,
    __nv_bfloat16* __restrict__ ol)
{
    long long idx = (long long)blockIdx.x * 256 + threadIdx.x;
    long long tot = (long long)DEPTH * QKV_DIM * E_DIM;
    if (idx >= tot) return;
    int k = idx % E_DIM;
    int n = (idx / E_DIM) % QKV_DIM;
    int l = idx / ((long long)E_DIM * QKV_DIM);
    const float* W = (n < 256) ? Wq : (n < 512) ? Wk : Wv;
    int nn = n & 255;
    float v = W[((long long)l * E_DIM + k) * E_DIM + nn];
    __nv_bfloat16 h, lo; bf16_split(v, h, lo);
    oh[idx] = h; ol[idx] = lo;
}

__global__ __launch_bounds__(256) void pack_b_kernel(
    const float* __restrict__ bq, const float* __restrict__ bk,
    const float* __restrict__ bv, float* __restrict__ bqkv)
{
    int idx = blockIdx.x * 256 + threadIdx.x;
    if (idx >= DEPTH * QKV_DIM) return;
    int n = idx % QKV_DIM;
    int l = idx / QKV_DIM;
    float v;
    if (n < 256)      v = bq[l * E_DIM + n];
    else if (n < 512) v = bk[l * E_DIM + (n - 256)];
    else              v = bv[l * E_DIM + (n - 512)];
    bqkv[idx] = v;
}

// ---------------- embedding --------------------------------------------------
__global__ __launch_bounds__(256) void embed_kernel(
    const int* __restrict__ user, const int* __restrict__ item,
    const float* __restrict__ ut, const float* __restrict__ it,
    const float* __restrict__ cls, const float* __restrict__ pos,
    float* __restrict__ x)
{
    int n = blockIdx.x;
    int b = blockIdx.y;
    int e = threadIdx.x;
    float v;
    if (n == 0) {
        v = cls[e];
    } else if (n <= F_DIM) {
        int uid = user[b];
        v = ut[((size_t)e * U_DIM + uid) * F_DIM + (n - 1)];
    } else {
        int iid = item[b];
        v = it[((size_t)e * I_DIM + iid) * F_DIM + (n - 1 - F_DIM)];
    }
    x[((size_t)b * N_TOK + n) * E_DIM + e] = v + pos[(size_t)n * E_DIM + e];
}

// ---------------- layernorm: warp per row, emits bf16 hi/lo ------------------
__device__ __forceinline__ float warp_sum(float v) {
    #pragma unroll
    for (int o = 16; o > 0; o >>= 1) v += __shfl_xor_sync(0xffffffffu, v, o);
    return v;
}

__global__ __launch_bounds__(256) void layernorm_kernel(
    const float* __restrict__ x, const float* __restrict__ g,
    const float* __restrict__ b,
    __nv_bfloat16* __restrict__ outH, __nv_bfloat16* __restrict__ outL)
{
    int row  = blockIdx.x * 8 + (threadIdx.x >> 5);
    int lane = threadIdx.x & 31;
    const float4* xr = (const float4*)(x + (size_t)row * E_DIM);
    float4 v0 = xr[lane * 2];
    float4 v1 = xr[lane * 2 + 1];
    float s  = v0.x + v0.y + v0.z + v0.w + v1.x + v1.y + v1.z + v1.w;
    float ss = v0.x*v0.x + v0.y*v0.y + v0.z*v0.z + v0.w*v0.w
             + v1.x*v1.x + v1.y*v1.y + v1.z*v1.z + v1.w*v1.w;
    s  = warp_sum(s);
    ss = warp_sum(ss);
    float mean = s * (1.f / E_DIM);
    float var  = ss * (1.f / E_DIM) - mean * mean;
    float rstd = rsqrtf(var + 1e-5f);

    float vv[8] = {v0.x, v0.y, v0.z, v0.w, v1.x, v1.y, v1.z, v1.w};
    const float* gp = g + lane * 8;
    const float* bp = b + lane * 8;
    __nv_bfloat162 H[4], L[4];
    #pragma unroll
    for (int i = 0; i < 4; i++) {
        float y0 = (vv[2*i]   - mean) * rstd * gp[2*i]   + bp[2*i];
        float y1 = (vv[2*i+1] - mean) * rstd * gp[2*i+1] + bp[2*i+1];
        __nv_bfloat16 h0, l0, h1, l1;
        bf16_split(y0, h0, l0);
        bf16_split(y1, h1, l1);
        H[i].x = h0; H[i].y = h1;
        L[i].x = l0; L[i].y = l1;
    }
    __nv_bfloat162* oh = (__nv_bfloat162*)(outH + (size_t)row * E_DIM) + lane * 4;
    __nv_bfloat162* ol = (__nv_bfloat162*)(outL + (size_t)row * E_DIM) + lane * 4;
    #pragma unroll
    for (int i = 0; i < 4; i++) { oh[i] = H[i]; ol[i] = L[i]; }
}

// ---------------- tensor-core GEMM (bf16x2 split, m16n8k16, ldmatrix) -------
#define GBM 128
#define GBN 64
#define GBK 32
#define AKP 40   // pitch: 80B rows -> 16B-aligned, conflict-free 8-row LDSM phases

__device__ __forceinline__ void mma_bf16(float* c, const unsigned* a, const unsigned* b) {
    asm volatile(
        "mma.sync.aligned.m16n8k16.row.col.f32.bf16.bf16.f32 "
        "{%0,%1,%2,%3}, {%4,%5,%6,%7}, {%8,%9}, {%0,%1,%2,%3};\n"
        : "+f"(c[0]), "+f"(c[1]), "+f"(c[2]), "+f"(c[3])
        : "r"(a[0]), "r"(a[1]), "r"(a[2]), "r"(a[3]), "r"(b[0]), "r"(b[1]));
}

#define LDSM4(R, ADDR) \
    asm volatile("ldmatrix.sync.aligned.m8n8.x4.shared.b16 {%0,%1,%2,%3}, [%4];" \
        : "=r"((R)[0]), "=r"((R)[1]), "=r"((R)[2]), "=r"((R)[3]) : "r"(ADDR))

__global__ __launch_bounds__(256) void tgemm_kernel(
    const __nv_bfloat16* __restrict__ AH, const __nv_bfloat16* __restrict__ AL,
    const __nv_bfloat16* __restrict__ WtH, const __nv_bfloat16* __restrict__ WtL,
    const float* __restrict__ bias, const float* __restrict__ res,
    float* __restrict__ Cf,
    __nv_bfloat16* __restrict__ Ch, __nv_bfloat16* __restrict__ Cl,
    int K, int N, int gelu)
{
    __shared__ __nv_bfloat16 AsH[2][GBM * AKP];
    __shared__ __nv_bfloat16 AsL[2][GBM * AKP];
    __shared__ __nv_bfloat16 BsH[2][GBN * AKP];
    __shared__ __nv_bfloat16 BsL[2][GBN * AKP];

    const int tid  = threadIdx.x;
    const int lane = tid & 31;
    const int wid  = tid >> 5;
    const int wm   = wid & 3;
    const int wn   = wid >> 2;
    const int br   = blockIdx.y * GBM;
    const int bc   = blockIdx.x * GBN;
    const int qrow = lane >> 2;
    const int qcol = (lane & 3) * 2;

    uint4 rAh[2], rAl[2], rBh, rBl;

    const int arow = tid >> 1;            // 0..127
    const int akh  = (tid & 1) * 16;      // 0 or 16
    const __nv_bfloat16* AHbase = AH + (size_t)(br + arow) * K + akh;
    const __nv_bfloat16* ALbase = AL + (size_t)(br + arow) * K + akh;
    const int bn  = tid >> 2;
    const int bkg = (tid & 3) * 8;
    const __nv_bfloat16* BHbase = WtH + (size_t)(bc + bn) * K + bkg;
    const __nv_bfloat16* BLbase = WtL + (size_t)(bc + bn) * K + bkg;

    // per-lane LDSM offsets (elements)
    //  A x4 tiles: {m0..7,kb} {m8..15,kb} {m0..7,kb+8} {m8..15,kb+8}
    const unsigned a_off = (unsigned)((wm * 32 + (lane & 7) + ((lane >> 3) & 1) * 8) * AKP
                                      + ((lane >> 4) & 1) * 8);
    //  B x4 tiles: {n0..7,kb} {n0..7,kb+8} {n8..15,kb} {n8..15,kb+8}
    const unsigned b_off = (unsigned)((wn * 32 + ((lane >> 4) & 1) * 8 + (lane & 7)) * AKP
                                      + ((lane >> 3) & 1) * 8);

    const unsigned sAH0 = (unsigned)__cvta_generic_to_shared(&AsH[0][0]);
    const unsigned sAL0 = (unsigned)__cvta_generic_to_shared(&AsL[0][0]);
    const unsigned sBH0 = (unsigned)__cvta_generic_to_shared(&BsH[0][0]);
    const unsigned sBL0 = (unsigned)__cvta_generic_to_shared(&BsL[0][0]);

    float acc[2][4][4];
    #pragma unroll
    for (int i = 0; i < 2; i++)
        #pragma unroll
        for (int j = 0; j < 4; j++)
            #pragma unroll
            for (int r = 0; r < 4; r++) acc[i][j][r] = 0.f;

    auto load_g = [&](int k0) {
        rAh[0] = *(const uint4*)(AHbase + k0);
        rAh[1] = *(const uint4*)(AHbase + k0 + 8);
        rAl[0] = *(const uint4*)(ALbase + k0);
        rAl[1] = *(const uint4*)(ALbase + k0 + 8);
        rBh = *(const uint4*)(BHbase + k0);
        rBl = *(const uint4*)(BLbase + k0);
    };

    auto store_s = [&](int s) {
        int off = arow * AKP + akh;
        *(uint4*)&AsH[s][off]     = rAh[0];
        *(uint4*)&AsH[s][off + 8] = rAh[1];
        *(uint4*)&AsL[s][off]     = rAl[0];
        *(uint4*)&AsL[s][off + 8] = rAl[1];
        *(uint4*)&BsH[s][bn * AKP + bkg] = rBh;
        *(uint4*)&BsL[s][bn * AKP + bkg] = rBl;
    };

    auto compute = [&](int s) {
        const unsigned aHs = sAH0 + (unsigned)(s * GBM * AKP * 2);
        const unsigned aLs = sAL0 + (unsigned)(s * GBM * AKP * 2);
        const unsigned bHs = sBH0 + (unsigned)(s * GBN * AKP * 2);
        const unsigned bLs = sBL0 + (unsigned)(s * GBN * AKP * 2);
        #pragma unroll
        for (int kk = 0; kk < 2; kk++) {
            const unsigned kb = kk * 16;
            unsigned aH[2][4], aL[2][4], bHf[2][4], bLf[2][4];
            #pragma unroll
            for (int ma = 0; ma < 2; ma++) {
                unsigned eoff = a_off + (unsigned)(ma * 16 * AKP) + kb;
                LDSM4(aH[ma], aHs + eoff * 2);
                LDSM4(aL[ma], aLs + eoff * 2);
            }
            #pragma unroll
            for (int p = 0; p < 2; p++) {
                unsigned eoff = b_off + (unsigned)(p * 16 * AKP) + kb;
                LDSM4(bHf[p], bHs + eoff * 2);
                LDSM4(bLf[p], bLs + eoff * 2);
            }
            #pragma unroll
            for (int ma = 0; ma < 2; ma++)
                #pragma unroll
                for (int na = 0; na < 4; na++) {
                    const unsigned* bh = &bHf[na >> 1][(na & 1) * 2];
                    const unsigned* bl = &bLf[na >> 1][(na & 1) * 2];
                    mma_bf16(acc[ma][na], aH[ma], bh);
                    mma_bf16(acc[ma][na], aH[ma], bl);
                    mma_bf16(acc[ma][na], aL[ma], bh);
                }
        }
    };

    load_g(0);
    store_s(0);
    __syncthreads();

    const int nst = K / GBK;
    for (int s0 = 0; s0 < nst; s0++) {
        int cur = s0 & 1;
        if (s0 + 1 < nst) load_g((s0 + 1) * GBK);
        compute(cur);
        if (s0 + 1 < nst) store_s(cur ^ 1);
        __syncthreads();
    }

    // epilogue
    #pragma unroll
    for (int ma = 0; ma < 2; ma++) {
        #pragma unroll
        for (int half = 0; half < 2; half++) {
            int gr = br + wm * 32 + ma * 16 + qrow + half * 8;
            #pragma unroll
            for (int na = 0; na < 4; na++) {
                int gc = bc + wn * 32 + na * 8 + qcol;
                float v0 = acc[ma][na][half * 2 + 0] + bias[gc];
                float v1 = acc[ma][na][half * 2 + 1] + bias[gc + 1];
                if (gelu) {
                    v0 = 0.5f * v0 * (1.0f + erff(v0 * 0.70710678118654752f));
                    v1 = 0.5f * v1 * (1.0f + erff(v1 * 0.70710678118654752f));
                }
                if (res) {
                    float2 r = *(const float2*)&res[(size_t)gr * N + gc];
                    v0 += r.x; v1 += r.y;
                }
                if (Cf) {
                    float2 ov = {v0, v1};
                    *(float2*)&Cf[(size_t)gr * N + gc] = ov;
                }
                if (Ch) {
                    __nv_bfloat16 h0, l0, h1, l1;
                    bf16_split(v0, h0, l0);
                    bf16_split(v1, h1, l1);
                    __nv_bfloat162 Hh; Hh.x = h0; Hh.y = h1;
                    __nv_bfloat162 Ll; Ll.x = l0; Ll.y = l1;
                    *(__nv_bfloat162*)&Ch[(size_t)gr * N + gc] = Hh;
                    *(__nv_bfloat162*)&Cl[(size_t)gr * N + gc] = Ll;
                }
            }
        }
    }
}

// ---------------- attention: 4 queries/warp, K + V^T + P in smem -------------
#define KS_ROWS 264
#define KS_PITCH 36
#define VT_PITCH 268
#define PS_PITCH 264
#define ATT_SMEM ((KS_ROWS * KS_PITCH + 32 * VT_PITCH + 32 * PS_PITCH + 32 * KS_PITCH) * 4)

__global__ __launch_bounds__(256) void attention_kernel(
    const float* __restrict__ qkv,
    __nv_bfloat16* __restrict__ oH, __nv_bfloat16* __restrict__ oL)
{
    extern __shared__ float sm[];
    float* Ks  = sm;                           // [264][36]
    float* VsT = Ks + KS_ROWS * KS_PITCH;      // [32][268]
    float* Ps  = VsT + 32 * VT_PITCH;          // [32][264]
    float* qs  = Ps + 32 * PS_PITCH;           // [32][36]

    const int h = blockIdx.x;
    const int b = blockIdx.y;
    const int tid = threadIdx.x;
    const int w = tid >> 5, lane = tid & 31;
    const size_t base = ((size_t)b * N_TOK) * QKV_DIM + h * HD;

    for (int idx = tid; idx < KS_ROWS * 32; idx += 256) {
        int k = idx >> 5, d = idx & 31;
        float kv = 0.f, vv = 0.f;
        if (k < N_TOK) {
            kv = qkv[base + (size_t)k * QKV_DIM + 256 + d];
            vv = qkv[base + (size_t)k * QKV_DIM + 512 + d];
        }
        Ks[k * KS_PITCH + d] = kv;
        VsT[d * VT_PITCH + k] = vv;
    }
    __syncthreads();

    const int qr = lane >> 3;
    const int d4 = (lane & 7) * 4;
    float* myqs[4];
    #pragma unroll
    for (int q = 0; q < 4; q++) myqs[q] = qs + (w * 4 + q) * KS_PITCH;

    for (int it = 0; it < 9; it++) {
        int qbase = it * 32;

        __syncwarp();
        {
            int query = qbase + w * 4 + qr;
            float4 qv = {0.f, 0.f, 0.f, 0.f};
            if (query < N_TOK)
                qv = *(const float4*)&qkv[base + (size_t)query * QKV_DIM + d4];
            *(float4*)&qs[(w * 4 + qr) * KS_PITCH + d4] = qv;
        }
        __syncwarp();

        float e[4][9];
        #pragma unroll
        for (int q = 0; q < 4; q++)
            #pragma unroll
            for (int j = 0; j < 9; j++) e[q][j] = 0.f;

        #pragma unroll
        for (int dd = 0; dd < 8; dd++) {
            float4 qv[4];
            #pragma unroll
            for (int q = 0; q < 4; q++)
                qv[q] = *(const float4*)&myqs[q][dd * 4];
            #pragma unroll
            for (int j = 0; j < 9; j++) {
                int key = j * 32 + lane;
                int kc = (key < KS_ROWS) ? key : 0;
                float4 kv = *(const float4*)&Ks[kc * KS_PITCH + dd * 4];
                #pragma unroll
                for (int q = 0; q < 4; q++) {
                    e[q][j] = fmaf(qv[q].x, kv.x, e[q][j]);
                    e[q][j] = fmaf(qv[q].y, kv.y, e[q][j]);
                    e[q][j] = fmaf(qv[q].z, kv.z, e[q][j]);
                    e[q][j] = fmaf(qv[q].w, kv.w, e[q][j]);
                }
            }
        }
        #pragma unroll
        for (int j = 0; j < 9; j++) {
            int key = j * 32 + lane;
            if (key >= N_TOK)
                #pragma unroll
                for (int q = 0; q < 4; q++) e[q][j] = -INFINITY;
        }

        float scale[4];
        #pragma unroll
        for (int q = 0; q < 4; q++) {
            float m = e[q][0];
            #pragma unroll
            for (int j = 1; j < 9; j++) m = fmaxf(m, e[q][j]);
            #pragma unroll
            for (int o = 16; o > 0; o >>= 1)
                m = fmaxf(m, __shfl_xor_sync(0xffffffffu, m, o));
            float sum = 0.f;
            #pragma unroll
            for (int j = 0; j < 9; j++) {
                int key = j * 32 + lane;
                float p = (key < N_TOK) ? __expf(e[q][j] - m) : 0.f;
                e[q][j] = p;
                sum += p;
            }
            sum = warp_sum(sum);
            scale[q] = 1.f / (sum * 16.0f);
            #pragma unroll
            for (int j = 0; j < 9; j++) {
                int key = j * 32 + lane;
                if (key < KS_ROWS)
                    Ps[(w * 4 + q) * PS_PITCH + key] = e[q][j];
            }
        }
        __syncwarp();

        float acc[4] = {0.f, 0.f, 0.f, 0.f};
        #pragma unroll 4
        for (int k4 = 0; k4 < PS_PITCH / 4; k4++) {
            float4 vv = *(const float4*)&VsT[lane * VT_PITCH + k4 * 4];
            #pragma unroll
            for (int q = 0; q < 4; q++) {
                float4 pv = *(const float4*)&Ps[(w * 4 + q) * PS_PITCH + k4 * 4];
                acc[q] = fmaf(pv.x, vv.x, acc[q]);
                acc[q] = fmaf(pv.y, vv.y, acc[q]);
                acc[q] = fmaf(pv.z, vv.z, acc[q]);
                acc[q] = fmaf(pv.w, vv.w, acc[q]);
            }
        }

        #pragma unroll
        for (int q = 0; q < 4; q++) {
            int query = qbase + w * 4 + q;
            if (query < N_TOK) {
                float val = acc[q] * scale[q];
                size_t oidx = ((size_t)b * N_TOK + query) * E_DIM + h * HD + lane;
                __nv_bfloat16 hh, ll;
                bf16_split(val, hh, ll);
                oH[oidx] = hh;
                oL[oidx] = ll;
            }
        }
        __syncwarp();
    }
}

// ---------------- mean-pool + head LN + linear -------------------------------
__global__ __launch_bounds__(256) void pool_head_kernel(
    const float* __restrict__ x, const float* __restrict__ g,
    const float* __restrict__ b, const float* __restrict__ W,
    const float* __restrict__ bias, float* __restrict__ out)
{
    int bb = blockIdx.x;
    int e = threadIdx.x;
    int w = e >> 5, lane = e & 31;
    float s = 0.f;
    const float* xb = x + (size_t)bb * N_TOK * E_DIM + e;
    for (int n = 0; n < N_TOK; n++) s += xb[(size_t)n * E_DIM];
    float pooled = s * (1.0f / N_TOK);

    __shared__ float sA[8], sB[8];
    float s1 = warp_sum(pooled);
    float s2 = warp_sum(pooled * pooled);
    if (lane == 0) { sA[w] = s1; sB[w] = s2; }
    __syncthreads();
    float tot = 0.f, tot2 = 0.f;
    #pragma unroll
    for (int i = 0; i < 8; i++) { tot += sA[i]; tot2 += sB[i]; }
    float mean = tot * (1.f / E_DIM);
    float var = tot2 * (1.f / E_DIM) - mean * mean;
    float rstd = rsqrtf(var + 1e-5f);
    float y = (pooled - mean) * rstd * g[e] + b[e];
    float t = y * W[e];
    __syncthreads();
    float t1 = warp_sum(t);
    if (lane == 0) sA[w] = t1;
    __syncthreads();
    if (e == 0) {
        float tot3 = 0.f;
        #pragma unroll
        for (int i = 0; i < 8; i++) tot3 += sA[i];
        out[bb] = tot3 + bias[0];
    }
}

// ---------------- driver ------------------------------------------------------
extern "C" void kernel_launch(void* const* d_in, const int* in_sizes, int n_in,
                              void* d_out, int out_size)
{
    const int*   user    = (const int*)  d_in[0];
    const int*   item    = (const int*)  d_in[1];
    const float* ut      = (const float*)d_in[2];
    const float* it      = (const float*)d_in[3];
    const float* cls     = (const float*)d_in[4];
    const float* pos     = (const float*)d_in[5];
    const float* ln1_g   = (const float*)d_in[6];
    const float* ln1_b   = (const float*)d_in[7];
    const float* Wq      = (const float*)d_in[8];
    const float* bq      = (const float*)d_in[9];
    const float* Wk      = (const float*)d_in[10];
    const float* bk      = (const float*)d_in[11];
    const float* Wv      = (const float*)d_in[12];
    const float* bv      = (const float*)d_in[13];
    const float* Wo      = (const float*)d_in[14];
    const float* bo      = (const float*)d_in[15];
    const float* ln2_g   = (const float*)d_in[16];
    const float* ln2_b   = (const float*)d_in[17];
    const float* W1      = (const float*)d_in[18];
    const float* b1      = (const float*)d_in[19];
    const float* W2      = (const float*)d_in[20];
    const float* b2      = (const float*)d_in[21];
    const float* head_g  = (const float*)d_in[22];
    const float* head_b  = (const float*)d_in[23];
    const float* head_W  = (const float*)d_in[24];
    const float* head_bi = (const float*)d_in[25];

    float *x, *qkv, *bqkv;
    __nv_bfloat16 *hH, *hL, *oH, *oL, *tH, *tL;
    __nv_bfloat16 *WqkvH, *WqkvL, *WoH, *WoL, *W1H, *W1L, *W2H, *W2L;
    cudaGetSymbolAddress((void**)&x,     d_x);
    cudaGetSymbolAddress((void**)&qkv,   d_qkv);
    cudaGetSymbolAddress((void**)&bqkv,  d_bqkv);
    cudaGetSymbolAddress((void**)&hH,    d_hH);
    cudaGetSymbolAddress((void**)&hL,    d_hL);
    cudaGetSymbolAddress((void**)&oH,    d_oH);
    cudaGetSymbolAddress((void**)&oL,    d_oL);
    cudaGetSymbolAddress((void**)&tH,    d_tH);
    cudaGetSymbolAddress((void**)&tL,    d_tL);
    cudaGetSymbolAddress((void**)&WqkvH, d_WqkvH);
    cudaGetSymbolAddress((void**)&WqkvL, d_WqkvL);
    cudaGetSymbolAddress((void**)&WoH,   d_WoH);
    cudaGetSymbolAddress((void**)&WoL,   d_WoL);
    cudaGetSymbolAddress((void**)&W1H,   d_W1H);
    cudaGetSymbolAddress((void**)&W1L,   d_W1L);
    cudaGetSymbolAddress((void**)&W2H,   d_W2H);
    cudaGetSymbolAddress((void**)&W2L,   d_W2L);

    cudaFuncSetAttribute(attention_kernel,
                         cudaFuncAttributeMaxDynamicSharedMemorySize, ATT_SMEM);

    // pack weights (bf16 hi/lo, transposed to [l][N][K])
    {
        long long n;
        n = (long long)DEPTH * QKV_DIM * E_DIM;
        pack_qkv_kernel<<<(int)((n + 255) / 256), 256>>>(Wq, Wk, Wv, WqkvH, WqkvL);
        n = (long long)DEPTH * E_DIM * E_DIM;
        pack_t_kernel<<<(int)((n + 255) / 256), 256>>>(Wo, WoH, WoL, E_DIM, E_DIM);
        n = (long long)DEPTH * E_DIM * FF_DIM;
        pack_t_kernel<<<(int)((n + 255) / 256), 256>>>(W1, W1H, W1L, E_DIM, FF_DIM);
        pack_t_kernel<<<(int)((n + 255) / 256), 256>>>(W2, W2H, W2L, FF_DIM, E_DIM);
        int nb = DEPTH * QKV_DIM;
        pack_b_kernel<<<(nb + 255) / 256, 256>>>(bq, bk, bv, bqkv);
    }

    embed_kernel<<<dim3(N_TOK, B_DIM), 256>>>(user, item, ut, it, cls, pos, x);

    const dim3 gQKV(QKV_DIM / GBN, M_PAD / GBM);   // (12, 129)
    const dim3 gE(E_DIM / GBN, M_PAD / GBM);       // (4, 129)
    const dim3 gFF(FF_DIM / GBN, M_PAD / GBM);     // (16, 129)
    const int  lnGrid = M_ROWS / 8;                // 2056

    for (int l = 0; l < DEPTH; l++) {
        size_t eOff   = (size_t)l * E_DIM;
        size_t eeOff  = (size_t)l * E_DIM * E_DIM;
        size_t ffOff  = (size_t)l * E_DIM * FF_DIM;
        size_t qkvOff = (size_t)l * E_DIM * QKV_DIM;

        layernorm_kernel<<<lnGrid, 256>>>(x, ln1_g + eOff, ln1_b + eOff, hH, hL);

        tgemm_kernel<<<gQKV, 256>>>(hH, hL, WqkvH + qkvOff, WqkvL + qkvOff,
                                    bqkv + (size_t)l * QKV_DIM, nullptr,
                                    qkv, nullptr, nullptr, E_DIM, QKV_DIM, 0);

        attention_kernel<<<dim3(H_DIM, B_DIM), 256, ATT_SMEM>>>(qkv, oH, oL);

        // x = x + (o @ Wo + bo)
        tgemm_kernel<<<gE, 256>>>(oH, oL, WoH + eeOff, WoL + eeOff,
                                  bo + eOff, x, x, nullptr, nullptr,
                                  E_DIM, E_DIM, 0);

        layernorm_kernel<<<lnGrid, 256>>>(x, ln2_g + eOff, ln2_b + eOff, hH, hL);

        // t = gelu(h @ W1 + b1)  (bf16 hi/lo output)
        tgemm_kernel<<<gFF, 256>>>(hH, hL, W1H + ffOff, W1L + ffOff,
                                   b1 + (size_t)l * FF_DIM, nullptr,
                                   nullptr, tH, tL, E_DIM, FF_DIM, 1);
        // x = x + (t @ W2 + b2)
        tgemm_kernel<<<gE, 256>>>(tH, tL, W2H + ffOff, W2L + ffOff,
                                  b2 + eOff, x, x, nullptr, nullptr,
                                  FF_DIM, E_DIM, 0);
    }

    pool_head_kernel<<<B_DIM, 256>>>(x, head_g, head_b, head_W, head_bi,
                                     (float*)d_out);
}

// round 8
// speedup vs baseline: 2.6514x; 1.0512x over previous
#include <cuda_runtime.h>
#include <cuda_bf16.h>
#include <math.h>
#include <stdint.h>

// Problem constants
#define DEPTH 12
#define E_DIM 256
#define F_DIM 128
#define H_DIM 8
#define HD 32
#define U_DIM 1000
#define I_DIM 1000
#define B_DIM 64
#define N_TOK 257                  // 2F+1
#define M_ROWS (B_DIM * N_TOK)     // 16448
#define M_PAD 16512                // 129*128 (pad rows: junk, never real outputs)
#define FF_DIM 1024
#define QKV_DIM 768

// ---------------- scratch (device globals; zero-init, no allocation) --------
__device__ float d_x[M_PAD * E_DIM];
__device__ float d_qkv[M_PAD * QKV_DIM];
__device__ float d_bqkv[DEPTH * QKV_DIM];
__device__ __nv_bfloat16 d_hH[M_PAD * E_DIM];
__device__ __nv_bfloat16 d_hL[M_PAD * E_DIM];
__device__ __nv_bfloat16 d_oH[M_PAD * E_DIM];
__device__ __nv_bfloat16 d_oL[M_PAD * E_DIM];
__device__ __nv_bfloat16 d_tH[M_PAD * FF_DIM];
__device__ __nv_bfloat16 d_tL[M_PAD * FF_DIM];
// packed bf16 hi/lo transposed weights: layout [l][N][K]
__device__ __nv_bfloat16 d_WqkvH[DEPTH * QKV_DIM * E_DIM];
__device__ __nv_bfloat16 d_WqkvL[DEPTH * QKV_DIM * E_DIM];
__device__ __nv_bfloat16 d_WoH[DEPTH * E_DIM * E_DIM];
__device__ __nv_bfloat16 d_WoL[DEPTH * E_DIM * E_DIM];
__device__ __nv_bfloat16 d_W1H[DEPTH * FF_DIM * E_DIM];
__device__ __nv_bfloat16 d_W1L[DEPTH * FF_DIM * E_DIM];
__device__ __nv_bfloat16 d_W2H[DEPTH * E_DIM * FF_DIM];
__device__ __nv_bfloat16 d_W2L[DEPTH * E_DIM * FF_DIM];

// ---------------- bf16 split helper -----------------------------------------
__device__ __forceinline__ void bf16_split(float x, __nv_bfloat16& h, __nv_bfloat16& l) {
    h = __float2bfloat16(x);
    l = __float2bfloat16(x - __bfloat162float(h));
}

// ---------------- fused weight/bias pack (single launch) ---------------------
#define NQKV (DEPTH * QKV_DIM * E_DIM)
#define NWO  (DEPTH * E_DIM * E_DIM)
#define NW1  (DEPTH * E_DIM * FF_DIM)
#define NW2  (DEPTH * FF_DIM * E_DIM)
#define NB   (DEPTH * QKV_DIM)
#define NPACK (NQKV + NWO + NW1 + NW2 + NB)

__global__ __launch_bounds__(256) void pack_all_kernel(
    const float* __restrict__ Wq, const float* __restrict__ Wk,
    const float* __restrict__ Wv, const float* __restrict__ Wo,
    const float* __restrict__ W1, const float* __restrict__ W2,
    const float* __restrict__ bq, const float* __restrict__ bk,
    const float* __restrict__ bv,
    __nv_bfloat16* __restrict__ WqkvH, __nv_bfloat16* __restrict__ WqkvL,
    __nv_bfloat16* __restrict__ WoH, __nv_bfloat16* __restrict__ WoL,
    __nv_bfloat16* __restrict__ W1H, __nv_bfloat16* __restrict__ W1L,
    __nv_bfloat16* __restrict__ W2H, __nv_bfloat16* __restrict__ W2L,
    float* __restrict__ bqkv)
{
    long long idx = (long long)blockIdx.x * 256 + threadIdx.x;
    if (idx >= NPACK) return;
    if (idx < NQKV) {
        int k = idx % E_DIM;
        int n = (idx / E_DIM) % QKV_DIM;
        int l = idx / ((long long)E_DIM * QKV_DIM);
        const float* W = (n < 256) ? Wq : (n < 512) ? Wk : Wv;
        float v = W[((long long)l * E_DIM + k) * E_DIM + (n & 255)];
        bf16_split(v, WqkvH[idx], WqkvL[idx]);
        return;
    }
    idx -= NQKV;
    if (idx < NWO) {
        int k = idx % E_DIM;
        int n = (idx / E_DIM) % E_DIM;
        int l = idx / ((long long)E_DIM * E_DIM);
        float v = Wo[((long long)l * E_DIM + k) * E_DIM + n];
        bf16_split(v, WoH[idx], WoL[idx]);
        return;
    }
    idx -= NWO;
    if (idx < NW1) {
        int k = idx % E_DIM;                // K = E
        int n = (idx / E_DIM) % FF_DIM;     // N = FF
        int l = idx / ((long long)E_DIM * FF_DIM);
        float v = W1[((long long)l * E_DIM + k) * FF_DIM + n];
        bf16_split(v, W1H[idx], W1L[idx]);
        return;
    }
    idx -= NW1;
    if (idx < NW2) {
        int k = idx % FF_DIM;               // K = FF
        int n = (idx / FF_DIM) % E_DIM;     // N = E
        int l = idx / ((long long)FF_DIM * E_DIM);
        float v = W2[((long long)l * FF_DIM + k) * E_DIM + n];
        bf16_split(v, W2H[idx], W2L[idx]);
        return;
    }
    idx -= NW2;
    {
        int n = idx % QKV_DIM;
        int l = idx / QKV_DIM;
        float v;
        if (n < 256)      v = bq[l * E_DIM + n];
        else if (n < 512) v = bk[l * E_DIM + (n - 256)];
        else              v = bv[l * E_DIM + (n - 512)];
        bqkv[idx] = v;
    }
}

// ---------------- embedding --------------------------------------------------
__global__ __launch_bounds__(256) void embed_kernel(
    const int* __restrict__ user, const int* __restrict__ item,
    const float* __restrict__ ut, const float* __restrict__ it,
    const float* __restrict__ cls, const float* __restrict__ pos,
    float* __restrict__ x)
{
    int n = blockIdx.x;
    int b = blockIdx.y;
    int e = threadIdx.x;
    float v;
    if (n == 0) {
        v = cls[e];
    } else if (n <= F_DIM) {
        int uid = user[b];
        v = ut[((size_t)e * U_DIM + uid) * F_DIM + (n - 1)];
    } else {
        int iid = item[b];
        v = it[((size_t)e * I_DIM + iid) * F_DIM + (n - 1 - F_DIM)];
    }
    x[((size_t)b * N_TOK + n) * E_DIM + e] = v + pos[(size_t)n * E_DIM + e];
}

// ---------------- layernorm: warp per row, emits bf16 hi/lo ------------------
__device__ __forceinline__ float warp_sum(float v) {
    #pragma unroll
    for (int o = 16; o > 0; o >>= 1) v += __shfl_xor_sync(0xffffffffu, v, o);
    return v;
}

__global__ __launch_bounds__(256) void layernorm_kernel(
    const float* __restrict__ x, const float* __restrict__ g,
    const float* __restrict__ b,
    __nv_bfloat16* __restrict__ outH, __nv_bfloat16* __restrict__ outL)
{
    int row  = blockIdx.x * 8 + (threadIdx.x >> 5);
    int lane = threadIdx.x & 31;
    const float4* xr = (const float4*)(x + (size_t)row * E_DIM);
    float4 v0 = xr[lane * 2];
    float4 v1 = xr[lane * 2 + 1];
    float s  = v0.x + v0.y + v0.z + v0.w + v1.x + v1.y + v1.z + v1.w;
    float ss = v0.x*v0.x + v0.y*v0.y + v0.z*v0.z + v0.w*v0.w
             + v1.x*v1.x + v1.y*v1.y + v1.z*v1.z + v1.w*v1.w;
    s  = warp_sum(s);
    ss = warp_sum(ss);
    float mean = s * (1.f / E_DIM);
    float var  = ss * (1.f / E_DIM) - mean * mean;
    float rstd = rsqrtf(var + 1e-5f);

    float vv[8] = {v0.x, v0.y, v0.z, v0.w, v1.x, v1.y, v1.z, v1.w};
    const float* gp = g + lane * 8;
    const float* bp = b + lane * 8;
    __nv_bfloat162 H[4], L[4];
    #pragma unroll
    for (int i = 0; i < 4; i++) {
        float y0 = (vv[2*i]   - mean) * rstd * gp[2*i]   + bp[2*i];
        float y1 = (vv[2*i+1] - mean) * rstd * gp[2*i+1] + bp[2*i+1];
        bf16_split(y0, H[i].x, L[i].x);
        bf16_split(y1, H[i].y, L[i].y);
    }
    __nv_bfloat162* oh = (__nv_bfloat162*)(outH + (size_t)row * E_DIM) + lane * 4;
    __nv_bfloat162* ol = (__nv_bfloat162*)(outL + (size_t)row * E_DIM) + lane * 4;
    #pragma unroll
    for (int i = 0; i < 4; i++) { oh[i] = H[i]; ol[i] = L[i]; }
}

// ---------------- tensor-core GEMM (bf16 3-term, ldmatrix, cp.async) ---------
#define GBM 128
#define GBN 64
#define GBK 32
#define AKP 40   // pitch: 80B rows, 16B-aligned, conflict-free 8-row LDSM phases

__device__ __forceinline__ void mma_bf16(float* c, const unsigned* a, const unsigned* b) {
    asm volatile(
        "mma.sync.aligned.m16n8k16.row.col.f32.bf16.bf16.f32 "
        "{%0,%1,%2,%3}, {%4,%5,%6,%7}, {%8,%9}, {%0,%1,%2,%3};\n"
        : "+f"(c[0]), "+f"(c[1]), "+f"(c[2]), "+f"(c[3])
        : "r"(a[0]), "r"(a[1]), "r"(a[2]), "r"(a[3]), "r"(b[0]), "r"(b[1]));
}

#define LDSM4(R, ADDR) \
    asm volatile("ldmatrix.sync.aligned.m8n8.x4.shared.b16 {%0,%1,%2,%3}, [%4];" \
        : "=r"((R)[0]), "=r"((R)[1]), "=r"((R)[2]), "=r"((R)[3]) : "r"(ADDR))

#define CP16(dst, src) \
    asm volatile("cp.async.cg.shared.global [%0], [%1], 16;" :: "r"(dst), "l"(src))
#define CP_COMMIT() asm volatile("cp.async.commit_group;" ::: "memory")
#define CP_WAIT(n)  asm volatile("cp.async.wait_group %0;" :: "n"(n) : "memory")

__global__ __launch_bounds__(256) void tgemm_kernel(
    const __nv_bfloat16* __restrict__ AH, const __nv_bfloat16* __restrict__ AL,
    const __nv_bfloat16* __restrict__ WtH, const __nv_bfloat16* __restrict__ WtL,
    const float* __restrict__ bias, const float* __restrict__ res,
    float* __restrict__ Cf,
    __nv_bfloat16* __restrict__ Ch, __nv_bfloat16* __restrict__ Cl,
    int K, int N, int gelu)
{
    __shared__ __nv_bfloat16 AsH[2][GBM * AKP];
    __shared__ __nv_bfloat16 AsL[2][GBM * AKP];
    __shared__ __nv_bfloat16 BsH[2][GBN * AKP];
    __shared__ __nv_bfloat16 BsL[2][GBN * AKP];

    const int tid  = threadIdx.x;
    const int lane = tid & 31;
    const int wid  = tid >> 5;
    const int wm   = wid & 3;
    const int wn   = wid >> 2;
    const int br   = blockIdx.y * GBM;
    const int bc   = blockIdx.x * GBN;
    const int qrow = lane >> 2;
    const int qcol = (lane & 3) * 2;

    const int arow = tid >> 1;            // 0..127
    const int akh  = (tid & 1) * 16;      // 0 or 16
    const __nv_bfloat16* AHbase = AH + (size_t)(br + arow) * K + akh;
    const __nv_bfloat16* ALbase = AL + (size_t)(br + arow) * K + akh;
    const int bn  = tid >> 2;
    const int bkg = (tid & 3) * 8;
    const __nv_bfloat16* BHbase = WtH + (size_t)(bc + bn) * K + bkg;
    const __nv_bfloat16* BLbase = WtL + (size_t)(bc + bn) * K + bkg;

    // per-lane LDSM offsets (elements)
    const unsigned a_off = (unsigned)((wm * 32 + (lane & 7) + ((lane >> 3) & 1) * 8) * AKP
                                      + ((lane >> 4) & 1) * 8);
    const unsigned b_off = (unsigned)((wn * 32 + ((lane >> 4) & 1) * 8 + (lane & 7)) * AKP
                                      + ((lane >> 3) & 1) * 8);

    const unsigned sAH0 = (unsigned)__cvta_generic_to_shared(&AsH[0][0]);
    const unsigned sAL0 = (unsigned)__cvta_generic_to_shared(&AsL[0][0]);
    const unsigned sBH0 = (unsigned)__cvta_generic_to_shared(&BsH[0][0]);
    const unsigned sBL0 = (unsigned)__cvta_generic_to_shared(&BsL[0][0]);

    // per-thread cp.async destination offsets (bytes)
    const unsigned dA = (unsigned)((arow * AKP + akh) * 2);
    const unsigned dB = (unsigned)((bn * AKP + bkg) * 2);

    float acc[2][4][4];
    #pragma unroll
    for (int i = 0; i < 2; i++)
        #pragma unroll
        for (int j = 0; j < 4; j++)
            #pragma unroll
            for (int r = 0; r < 4; r++) acc[i][j][r] = 0.f;

    auto cp_stage = [&](int k0, int s) {
        unsigned off = (unsigned)(s * GBM * AKP * 2);
        unsigned offB = (unsigned)(s * GBN * AKP * 2);
        CP16(sAH0 + off + dA,      AHbase + k0);
        CP16(sAH0 + off + dA + 16, AHbase + k0 + 8);
        CP16(sAL0 + off + dA,      ALbase + k0);
        CP16(sAL0 + off + dA + 16, ALbase + k0 + 8);
        CP16(sBH0 + offB + dB,     BHbase + k0);
        CP16(sBL0 + offB + dB,     BLbase + k0);
    };

    auto compute = [&](int s) {
        const unsigned aHs = sAH0 + (unsigned)(s * GBM * AKP * 2);
        const unsigned aLs = sAL0 + (unsigned)(s * GBM * AKP * 2);
        const unsigned bHs = sBH0 + (unsigned)(s * GBN * AKP * 2);
        const unsigned bLs = sBL0 + (unsigned)(s * GBN * AKP * 2);
        #pragma unroll
        for (int kk = 0; kk < 2; kk++) {
            const unsigned kb = kk * 16;
            unsigned aH[2][4], aL[2][4], bHf[2][4], bLf[2][4];
            #pragma unroll
            for (int ma = 0; ma < 2; ma++) {
                unsigned eoff = a_off + (unsigned)(ma * 16 * AKP) + kb;
                LDSM4(aH[ma], aHs + eoff * 2);
                LDSM4(aL[ma], aLs + eoff * 2);
            }
            #pragma unroll
            for (int p = 0; p < 2; p++) {
                unsigned eoff = b_off + (unsigned)(p * 16 * AKP) + kb;
                LDSM4(bHf[p], bHs + eoff * 2);
                LDSM4(bLf[p], bLs + eoff * 2);
            }
            // term-major ordering across 8 independent accumulators
            #pragma unroll
            for (int ma = 0; ma < 2; ma++)
                #pragma unroll
                for (int na = 0; na < 4; na++)
                    mma_bf16(acc[ma][na], aH[ma], &bHf[na >> 1][(na & 1) * 2]);
            #pragma unroll
            for (int ma = 0; ma < 2; ma++)
                #pragma unroll
                for (int na = 0; na < 4; na++)
                    mma_bf16(acc[ma][na], aH[ma], &bLf[na >> 1][(na & 1) * 2]);
            #pragma unroll
            for (int ma = 0; ma < 2; ma++)
                #pragma unroll
                for (int na = 0; na < 4; na++)
                    mma_bf16(acc[ma][na], aL[ma], &bHf[na >> 1][(na & 1) * 2]);
        }
    };

    const int nst = K / GBK;
    cp_stage(0, 0);
    CP_COMMIT();

    for (int s0 = 0; s0 < nst; s0++) {
        int cur = s0 & 1;
        if (s0 + 1 < nst) {
            cp_stage((s0 + 1) * GBK, cur ^ 1);
            CP_COMMIT();
            CP_WAIT(1);
        } else {
            CP_WAIT(0);
        }
        __syncthreads();
        compute(cur);
        __syncthreads();
    }

    // epilogue
    #pragma unroll
    for (int ma = 0; ma < 2; ma++) {
        #pragma unroll
        for (int half = 0; half < 2; half++) {
            int gr = br + wm * 32 + ma * 16 + qrow + half * 8;
            #pragma unroll
            for (int na = 0; na < 4; na++) {
                int gc = bc + wn * 32 + na * 8 + qcol;
                float v0 = acc[ma][na][half * 2 + 0] + bias[gc];
                float v1 = acc[ma][na][half * 2 + 1] + bias[gc + 1];
                if (gelu) {
                    v0 = 0.5f * v0 * (1.0f + erff(v0 * 0.70710678118654752f));
                    v1 = 0.5f * v1 * (1.0f + erff(v1 * 0.70710678118654752f));
                }
                if (res) {
                    float2 r = *(const float2*)&res[(size_t)gr * N + gc];
                    v0 += r.x; v1 += r.y;
                }
                if (Cf) {
                    float2 ov = {v0, v1};
                    *(float2*)&Cf[(size_t)gr * N + gc] = ov;
                }
                if (Ch) {
                    __nv_bfloat162 Hh, Ll;
                    bf16_split(v0, Hh.x, Ll.x);
                    bf16_split(v1, Hh.y, Ll.y);
                    *(__nv_bfloat162*)&Ch[(size_t)gr * N + gc] = Hh;
                    *(__nv_bfloat162*)&Cl[(size_t)gr * N + gc] = Ll;
                }
            }
        }
    }
}

// ---------------- attention: 4 queries/warp, K + V^T + P in smem -------------
#define KS_ROWS 264
#define KS_PITCH 36
#define VT_PITCH 268
#define PS_PITCH 264
#define ATT_SMEM ((KS_ROWS * KS_PITCH + 32 * VT_PITCH + 32 * PS_PITCH + 32 * KS_PITCH) * 4)

__global__ __launch_bounds__(256) void attention_kernel(
    const float* __restrict__ qkv,
    __nv_bfloat16* __restrict__ oH, __nv_bfloat16* __restrict__ oL)
{
    extern __shared__ float sm[];
    float* Ks  = sm;                           // [264][36]
    float* VsT = Ks + KS_ROWS * KS_PITCH;      // [32][268]
    float* Ps  = VsT + 32 * VT_PITCH;          // [32][264]
    float* qs  = Ps + 32 * PS_PITCH;           // [32][36]

    const int h = blockIdx.x;
    const int b = blockIdx.y;
    const int tid = threadIdx.x;
    const int w = tid >> 5, lane = tid & 31;
    const size_t base = ((size_t)b * N_TOK) * QKV_DIM + h * HD;

    for (int idx = tid; idx < KS_ROWS * 32; idx += 256) {
        int k = idx >> 5, d = idx & 31;
        float kv = 0.f, vv = 0.f;
        if (k < N_TOK) {
            kv = qkv[base + (size_t)k * QKV_DIM + 256 + d];
            vv = qkv[base + (size_t)k * QKV_DIM + 512 + d];
        }
        Ks[k * KS_PITCH + d] = kv;
        VsT[d * VT_PITCH + k] = vv;
    }
    __syncthreads();

    const int qr = lane >> 3;
    const int d4 = (lane & 7) * 4;
    float* myqs[4];
    #pragma unroll
    for (int q = 0; q < 4; q++) myqs[q] = qs + (w * 4 + q) * KS_PITCH;

    for (int it = 0; it < 9; it++) {
        int qbase = it * 32;

        __syncwarp();
        {
            int query = qbase + w * 4 + qr;
            float4 qv = {0.f, 0.f, 0.f, 0.f};
            if (query < N_TOK)
                qv = *(const float4*)&qkv[base + (size_t)query * QKV_DIM + d4];
            *(float4*)&qs[(w * 4 + qr) * KS_PITCH + d4] = qv;
        }
        __syncwarp();

        float e[4][9];
        #pragma unroll
        for (int q = 0; q < 4; q++)
            #pragma unroll
            for (int j = 0; j < 9; j++) e[q][j] = 0.f;

        #pragma unroll
        for (int dd = 0; dd < 8; dd++) {
            float4 qv[4];
            #pragma unroll
            for (int q = 0; q < 4; q++)
                qv[q] = *(const float4*)&myqs[q][dd * 4];
            #pragma unroll
            for (int j = 0; j < 9; j++) {
                int key = j * 32 + lane;
                int kc = (key < KS_ROWS) ? key : 0;
                float4 kv = *(const float4*)&Ks[kc * KS_PITCH + dd * 4];
                #pragma unroll
                for (int q = 0; q < 4; q++) {
                    e[q][j] = fmaf(qv[q].x, kv.x, e[q][j]);
                    e[q][j] = fmaf(qv[q].y, kv.y, e[q][j]);
                    e[q][j] = fmaf(qv[q].z, kv.z, e[q][j]);
                    e[q][j] = fmaf(qv[q].w, kv.w, e[q][j]);
                }
            }
        }
        #pragma unroll
        for (int j = 0; j < 9; j++) {
            int key = j * 32 + lane;
            if (key >= N_TOK)
                #pragma unroll
                for (int q = 0; q < 4; q++) e[q][j] = -INFINITY;
        }

        float scale[4];
        #pragma unroll
        for (int q = 0; q < 4; q++) {
            float m = e[q][0];
            #pragma unroll
            for (int j = 1; j < 9; j++) m = fmaxf(m, e[q][j]);
            #pragma unroll
            for (int o = 16; o > 0; o >>= 1)
                m = fmaxf(m, __shfl_xor_sync(0xffffffffu, m, o));
            float sum = 0.f;
            #pragma unroll
            for (int j = 0; j < 9; j++) {
                int key = j * 32 + lane;
                float p = (key < N_TOK) ? __expf(e[q][j] - m) : 0.f;
                e[q][j] = p;
                sum += p;
            }
            sum = warp_sum(sum);
            scale[q] = 1.f / (sum * 16.0f);
            #pragma unroll
            for (int j = 0; j < 9; j++) {
                int key = j * 32 + lane;
                if (key < KS_ROWS)
                    Ps[(w * 4 + q) * PS_PITCH + key] = e[q][j];
            }
        }
        __syncwarp();

        float acc[4] = {0.f, 0.f, 0.f, 0.f};
        #pragma unroll 4
        for (int k4 = 0; k4 < PS_PITCH / 4; k4++) {
            float4 vv = *(const float4*)&VsT[lane * VT_PITCH + k4 * 4];
            #pragma unroll
            for (int q = 0; q < 4; q++) {
                float4 pv = *(const float4*)&Ps[(w * 4 + q) * PS_PITCH + k4 * 4];
                acc[q] = fmaf(pv.x, vv.x, acc[q]);
                acc[q] = fmaf(pv.y, vv.y, acc[q]);
                acc[q] = fmaf(pv.z, vv.z, acc[q]);
                acc[q] = fmaf(pv.w, vv.w, acc[q]);
            }
        }

        #pragma unroll
        for (int q = 0; q < 4; q++) {
            int query = qbase + w * 4 + q;
            if (query < N_TOK) {
                float val = acc[q] * scale[q];
                size_t oidx = ((size_t)b * N_TOK + query) * E_DIM + h * HD + lane;
                __nv_bfloat16 hh, ll;
                bf16_split(val, hh, ll);
                oH[oidx] = hh;
                oL[oidx] = ll;
            }
        }
        __syncwarp();
    }
}

// ---------------- mean-pool + head LN + linear -------------------------------
__global__ __launch_bounds__(256) void pool_head_kernel(
    const float* __restrict__ x, const float* __restrict__ g,
    const float* __restrict__ b, const float* __restrict__ W,
    const float* __restrict__ bias, float* __restrict__ out)
{
    int bb = blockIdx.x;
    int e = threadIdx.x;
    int w = e >> 5, lane = e & 31;
    float s = 0.f;
    const float* xb = x + (size_t)bb * N_TOK * E_DIM + e;
    for (int n = 0; n < N_TOK; n++) s += xb[(size_t)n * E_DIM];
    float pooled = s * (1.0f / N_TOK);

    __shared__ float sA[8], sB[8];
    float s1 = warp_sum(pooled);
    float s2 = warp_sum(pooled * pooled);
    if (lane == 0) { sA[w] = s1; sB[w] = s2; }
    __syncthreads();
    float tot = 0.f, tot2 = 0.f;
    #pragma unroll
    for (int i = 0; i < 8; i++) { tot += sA[i]; tot2 += sB[i]; }
    float mean = tot * (1.f / E_DIM);
    float var = tot2 * (1.f / E_DIM) - mean * mean;
    float rstd = rsqrtf(var + 1e-5f);
    float y = (pooled - mean) * rstd * g[e] + b[e];
    float t = y * W[e];
    __syncthreads();
    float t1 = warp_sum(t);
    if (lane == 0) sA[w] = t1;
    __syncthreads();
    if (e == 0) {
        float tot3 = 0.f;
        #pragma unroll
        for (int i = 0; i < 8; i++) tot3 += sA[i];
        out[bb] = tot3 + bias[0];
    }
}

// ---------------- driver ------------------------------------------------------
extern "C" void kernel_launch(void* const* d_in, const int* in_sizes, int n_in,
                              void* d_out, int out_size)
{
    const int*   user    = (const int*)  d_in[0];
    const int*   item    = (const int*)  d_in[1];
    const float* ut      = (const float*)d_in[2];
    const float* it      = (const float*)d_in[3];
    const float* cls     = (const float*)d_in[4];
    const float* pos     = (const float*)d_in[5];
    const float* ln1_g   = (const float*)d_in[6];
    const float* ln1_b   = (const float*)d_in[7];
    const float* Wq      = (const float*)d_in[8];
    const float* bq      = (const float*)d_in[9];
    const float* Wk      = (const float*)d_in[10];
    const float* bk      = (const float*)d_in[11];
    const float* Wv      = (const float*)d_in[12];
    const float* bv      = (const float*)d_in[13];
    const float* Wo      = (const float*)d_in[14];
    const float* bo      = (const float*)d_in[15];
    const float* ln2_g   = (const float*)d_in[16];
    const float* ln2_b   = (const float*)d_in[17];
    const float* W1      = (const float*)d_in[18];
    const float* b1      = (const float*)d_in[19];
    const float* W2      = (const float*)d_in[20];
    const float* b2      = (const float*)d_in[21];
    const float* head_g  = (const float*)d_in[22];
    const float* head_b  = (const float*)d_in[23];
    const float* head_W  = (const float*)d_in[24];
    const float* head_bi = (const float*)d_in[25];

    float *x, *qkv, *bqkv;
    __nv_bfloat16 *hH, *hL, *oH, *oL, *tH, *tL;
    __nv_bfloat16 *WqkvH, *WqkvL, *WoH, *WoL, *W1H, *W1L, *W2H, *W2L;
    cudaGetSymbolAddress((void**)&x,     d_x);
    cudaGetSymbolAddress((void**)&qkv,   d_qkv);
    cudaGetSymbolAddress((void**)&bqkv,  d_bqkv);
    cudaGetSymbolAddress((void**)&hH,    d_hH);
    cudaGetSymbolAddress((void**)&hL,    d_hL);
    cudaGetSymbolAddress((void**)&oH,    d_oH);
    cudaGetSymbolAddress((void**)&oL,    d_oL);
    cudaGetSymbolAddress((void**)&tH,    d_tH);
    cudaGetSymbolAddress((void**)&tL,    d_tL);
    cudaGetSymbolAddress((void**)&WqkvH, d_WqkvH);
    cudaGetSymbolAddress((void**)&WqkvL, d_WqkvL);
    cudaGetSymbolAddress((void**)&WoH,   d_WoH);
    cudaGetSymbolAddress((void**)&WoL,   d_WoL);
    cudaGetSymbolAddress((void**)&W1H,   d_W1H);
    cudaGetSymbolAddress((void**)&W1L,   d_W1L);
    cudaGetSymbolAddress((void**)&W2H,   d_W2H);
    cudaGetSymbolAddress((void**)&W2L,   d_W2L);

    cudaFuncSetAttribute(attention_kernel,
                         cudaFuncAttributeMaxDynamicSharedMemorySize, ATT_SMEM);

    // single fused pack launch
    pack_all_kernel<<<(int)((NPACK + 255LL) / 256), 256>>>(
        Wq, Wk, Wv, Wo, W1, W2, bq, bk, bv,
        WqkvH, WqkvL, WoH, WoL, W1H, W1L, W2H, W2L, bqkv);

    embed_kernel<<<dim3(N_TOK, B_DIM), 256>>>(user, item, ut, it, cls, pos, x);

    const dim3 gQKV(QKV_DIM / GBN, M_PAD / GBM);   // (12, 129)
    const dim3 gE(E_DIM / GBN, M_PAD / GBM);       // (4, 129)
    const dim3 gFF(FF_DIM / GBN, M_PAD / GBM);     // (16, 129)
    const int  lnGrid = M_ROWS / 8;                // 2056

    for (int l = 0; l < DEPTH; l++) {
        size_t eOff   = (size_t)l * E_DIM;
        size_t eeOff  = (size_t)l * E_DIM * E_DIM;
        size_t ffOff  = (size_t)l * E_DIM * FF_DIM;
        size_t qkvOff = (size_t)l * E_DIM * QKV_DIM;

        layernorm_kernel<<<lnGrid, 256>>>(x, ln1_g + eOff, ln1_b + eOff, hH, hL);

        tgemm_kernel<<<gQKV, 256>>>(hH, hL, WqkvH + qkvOff, WqkvL + qkvOff,
                                    bqkv + (size_t)l * QKV_DIM, nullptr,
                                    qkv, nullptr, nullptr, E_DIM, QKV_DIM, 0);

        attention_kernel<<<dim3(H_DIM, B_DIM), 256, ATT_SMEM>>>(qkv, oH, oL);

        // x = x + (o @ Wo + bo)
        tgemm_kernel<<<gE, 256>>>(oH, oL, WoH + eeOff, WoL + eeOff,
                                  bo + eOff, x, x, nullptr, nullptr,
                                  E_DIM, E_DIM, 0);

        layernorm_kernel<<<lnGrid, 256>>>(x, ln2_g + eOff, ln2_b + eOff, hH, hL);

        // t = gelu(h @ W1 + b1)  (bf16 hi/lo output)
        tgemm_kernel<<<gFF, 256>>>(hH, hL, W1H + ffOff, W1L + ffOff,
                                   b1 + (size_t)l * FF_DIM, nullptr,
                                   nullptr, tH, tL, E_DIM, FF_DIM, 1);
        // x = x + (t @ W2 + b2)
        tgemm_kernel<<<gE, 256>>>(tH, tL, W2H + ffOff, W2L + ffOff,
                                  b2 + eOff, x, x, nullptr, nullptr,
                                  FF_DIM, E_DIM, 0);
    }

    pool_head_kernel<<<B_DIM, 256>>>(x, head_g, head_b, head_W, head_bi,
                                     (float*)d_out);
}

// round 9
// speedup vs baseline: 2.7068x; 1.0209x over previous
#include <cuda_runtime.h>
#include <cuda_bf16.h>
#include <math.h>
#include <stdint.h>

// Problem constants
#define DEPTH 12
#define E_DIM 256
#define F_DIM 128
#define H_DIM 8
#define HD 32
#define U_DIM 1000
#define I_DIM 1000
#define B_DIM 64
#define N_TOK 257                  // 2F+1
#define M_ROWS (B_DIM * N_TOK)     // 16448
#define M_PAD 16512                // 129*128 (pad rows: junk, never real outputs)
#define FF_DIM 1024
#define QKV_DIM 768

// ---------------- scratch (device globals; zero-init, no allocation) --------
__device__ float d_x[M_PAD * E_DIM];
__device__ float d_qkv[M_PAD * QKV_DIM];
__device__ float d_bqkv[DEPTH * QKV_DIM];
__device__ __nv_bfloat16 d_hH[M_PAD * E_DIM];
__device__ __nv_bfloat16 d_hL[M_PAD * E_DIM];
__device__ __nv_bfloat16 d_oH[M_PAD * E_DIM];
__device__ __nv_bfloat16 d_oL[M_PAD * E_DIM];
__device__ __nv_bfloat16 d_tH[M_PAD * FF_DIM];
__device__ __nv_bfloat16 d_tL[M_PAD * FF_DIM];
// packed bf16 hi/lo transposed weights: layout [l][N][K]
__device__ __nv_bfloat16 d_WqkvH[DEPTH * QKV_DIM * E_DIM];
__device__ __nv_bfloat16 d_WqkvL[DEPTH * QKV_DIM * E_DIM];
__device__ __nv_bfloat16 d_WoH[DEPTH * E_DIM * E_DIM];
__device__ __nv_bfloat16 d_WoL[DEPTH * E_DIM * E_DIM];
__device__ __nv_bfloat16 d_W1H[DEPTH * FF_DIM * E_DIM];
__device__ __nv_bfloat16 d_W1L[DEPTH * FF_DIM * E_DIM];
__device__ __nv_bfloat16 d_W2H[DEPTH * E_DIM * FF_DIM];
__device__ __nv_bfloat16 d_W2L[DEPTH * E_DIM * FF_DIM];

// ---------------- bf16 split helper -----------------------------------------
__device__ __forceinline__ void bf16_split(float x, __nv_bfloat16& h, __nv_bfloat16& l) {
    h = __float2bfloat16(x);
    l = __float2bfloat16(x - __bfloat162float(h));
}

// ---------------- fused weight/bias pack (single launch) ---------------------
#define NQKV (DEPTH * QKV_DIM * E_DIM)
#define NWO  (DEPTH * E_DIM * E_DIM)
#define NW1  (DEPTH * E_DIM * FF_DIM)
#define NW2  (DEPTH * FF_DIM * E_DIM)
#define NB   (DEPTH * QKV_DIM)
#define NPACK (NQKV + NWO + NW1 + NW2 + NB)

__global__ __launch_bounds__(256) void pack_all_kernel(
    const float* __restrict__ Wq, const float* __restrict__ Wk,
    const float* __restrict__ Wv, const float* __restrict__ Wo,
    const float* __restrict__ W1, const float* __restrict__ W2,
    const float* __restrict__ bq, const float* __restrict__ bk,
    const float* __restrict__ bv,
    __nv_bfloat16* __restrict__ WqkvH, __nv_bfloat16* __restrict__ WqkvL,
    __nv_bfloat16* __restrict__ WoH, __nv_bfloat16* __restrict__ WoL,
    __nv_bfloat16* __restrict__ W1H, __nv_bfloat16* __restrict__ W1L,
    __nv_bfloat16* __restrict__ W2H, __nv_bfloat16* __restrict__ W2L,
    float* __restrict__ bqkv)
{
    long long idx = (long long)blockIdx.x * 256 + threadIdx.x;
    if (idx >= NPACK) return;
    if (idx < NQKV) {
        int k = idx % E_DIM;
        int n = (idx / E_DIM) % QKV_DIM;
        int l = idx / ((long long)E_DIM * QKV_DIM);
        const float* W = (n < 256) ? Wq : (n < 512) ? Wk : Wv;
        float v = W[((long long)l * E_DIM + k) * E_DIM + (n & 255)];
        bf16_split(v, WqkvH[idx], WqkvL[idx]);
        return;
    }
    idx -= NQKV;
    if (idx < NWO) {
        int k = idx % E_DIM;
        int n = (idx / E_DIM) % E_DIM;
        int l = idx / ((long long)E_DIM * E_DIM);
        float v = Wo[((long long)l * E_DIM + k) * E_DIM + n];
        bf16_split(v, WoH[idx], WoL[idx]);
        return;
    }
    idx -= NWO;
    if (idx < NW1) {
        int k = idx % E_DIM;
        int n = (idx / E_DIM) % FF_DIM;
        int l = idx / ((long long)E_DIM * FF_DIM);
        float v = W1[((long long)l * E_DIM + k) * FF_DIM + n];
        bf16_split(v, W1H[idx], W1L[idx]);
        return;
    }
    idx -= NW1;
    if (idx < NW2) {
        int k = idx % FF_DIM;
        int n = (idx / FF_DIM) % E_DIM;
        int l = idx / ((long long)FF_DIM * E_DIM);
        float v = W2[((long long)l * FF_DIM + k) * E_DIM + n];
        bf16_split(v, W2H[idx], W2L[idx]);
        return;
    }
    idx -= NW2;
    {
        int n = idx % QKV_DIM;
        int l = idx / QKV_DIM;
        float v;
        if (n < 256)      v = bq[l * E_DIM + n];
        else if (n < 512) v = bk[l * E_DIM + (n - 256)];
        else              v = bv[l * E_DIM + (n - 512)];
        bqkv[idx] = v;
    }
}

// ---------------- embedding --------------------------------------------------
__global__ __launch_bounds__(256) void embed_kernel(
    const int* __restrict__ user, const int* __restrict__ item,
    const float* __restrict__ ut, const float* __restrict__ it,
    const float* __restrict__ cls, const float* __restrict__ pos,
    float* __restrict__ x)
{
    int n = blockIdx.x;
    int b = blockIdx.y;
    int e = threadIdx.x;
    float v;
    if (n == 0) {
        v = cls[e];
    } else if (n <= F_DIM) {
        int uid = user[b];
        v = ut[((size_t)e * U_DIM + uid) * F_DIM + (n - 1)];
    } else {
        int iid = item[b];
        v = it[((size_t)e * I_DIM + iid) * F_DIM + (n - 1 - F_DIM)];
    }
    x[((size_t)b * N_TOK + n) * E_DIM + e] = v + pos[(size_t)n * E_DIM + e];
}

// ---------------- layernorm: warp per row, emits bf16 hi/lo ------------------
__device__ __forceinline__ float warp_sum(float v) {
    #pragma unroll
    for (int o = 16; o > 0; o >>= 1) v += __shfl_xor_sync(0xffffffffu, v, o);
    return v;
}

__global__ __launch_bounds__(256) void layernorm_kernel(
    const float* __restrict__ x, const float* __restrict__ g,
    const float* __restrict__ b,
    __nv_bfloat16* __restrict__ outH, __nv_bfloat16* __restrict__ outL)
{
    int row  = blockIdx.x * 8 + (threadIdx.x >> 5);
    int lane = threadIdx.x & 31;
    const float4* xr = (const float4*)(x + (size_t)row * E_DIM);
    float4 v0 = xr[lane * 2];
    float4 v1 = xr[lane * 2 + 1];
    float s  = v0.x + v0.y + v0.z + v0.w + v1.x + v1.y + v1.z + v1.w;
    float ss = v0.x*v0.x + v0.y*v0.y + v0.z*v0.z + v0.w*v0.w
             + v1.x*v1.x + v1.y*v1.y + v1.z*v1.z + v1.w*v1.w;
    s  = warp_sum(s);
    ss = warp_sum(ss);
    float mean = s * (1.f / E_DIM);
    float var  = ss * (1.f / E_DIM) - mean * mean;
    float rstd = rsqrtf(var + 1e-5f);

    float vv[8] = {v0.x, v0.y, v0.z, v0.w, v1.x, v1.y, v1.z, v1.w};
    const float* gp = g + lane * 8;
    const float* bp = b + lane * 8;
    __nv_bfloat162 H[4], L[4];
    #pragma unroll
    for (int i = 0; i < 4; i++) {
        float y0 = (vv[2*i]   - mean) * rstd * gp[2*i]   + bp[2*i];
        float y1 = (vv[2*i+1] - mean) * rstd * gp[2*i+1] + bp[2*i+1];
        bf16_split(y0, H[i].x, L[i].x);
        bf16_split(y1, H[i].y, L[i].y);
    }
    __nv_bfloat162* oh = (__nv_bfloat162*)(outH + (size_t)row * E_DIM) + lane * 4;
    __nv_bfloat162* ol = (__nv_bfloat162*)(outL + (size_t)row * E_DIM) + lane * 4;
    #pragma unroll
    for (int i = 0; i < 4; i++) { oh[i] = H[i]; ol[i] = L[i]; }
}

// ---------------- tensor-core GEMM (bf16 3-term, 3-stage cp.async pipeline) --
#define GBM 128
#define GBN 64
#define GBK 32
#define NSTAGE 3
#define AKP 40   // pitch: 80B rows, 16B-aligned, conflict-free 8-row LDSM phases

__device__ __forceinline__ void mma_bf16(float* c, const unsigned* a, const unsigned* b) {
    asm volatile(
        "mma.sync.aligned.m16n8k16.row.col.f32.bf16.bf16.f32 "
        "{%0,%1,%2,%3}, {%4,%5,%6,%7}, {%8,%9}, {%0,%1,%2,%3};\n"
        : "+f"(c[0]), "+f"(c[1]), "+f"(c[2]), "+f"(c[3])
        : "r"(a[0]), "r"(a[1]), "r"(a[2]), "r"(a[3]), "r"(b[0]), "r"(b[1]));
}

#define LDSM4(R, ADDR) \
    asm volatile("ldmatrix.sync.aligned.m8n8.x4.shared.b16 {%0,%1,%2,%3}, [%4];" \
        : "=r"((R)[0]), "=r"((R)[1]), "=r"((R)[2]), "=r"((R)[3]) : "r"(ADDR))

#define CP16(dst, src) \
    asm volatile("cp.async.cg.shared.global [%0], [%1], 16;" :: "r"(dst), "l"(src))
#define CP_COMMIT() asm volatile("cp.async.commit_group;" ::: "memory")
#define CP_WAIT(n)  asm volatile("cp.async.wait_group %0;" :: "n"(n) : "memory")

__global__ __launch_bounds__(256) void tgemm_kernel(
    const __nv_bfloat16* __restrict__ AH, const __nv_bfloat16* __restrict__ AL,
    const __nv_bfloat16* __restrict__ WtH, const __nv_bfloat16* __restrict__ WtL,
    const float* __restrict__ bias, const float* __restrict__ res,
    float* __restrict__ Cf,
    __nv_bfloat16* __restrict__ Ch, __nv_bfloat16* __restrict__ Cl,
    int K, int N, int gelu)
{
    __shared__ __nv_bfloat16 AsH[NSTAGE][GBM * AKP];
    __shared__ __nv_bfloat16 AsL[NSTAGE][GBM * AKP];
    __shared__ __nv_bfloat16 BsH[NSTAGE][GBN * AKP];
    __shared__ __nv_bfloat16 BsL[NSTAGE][GBN * AKP];

    const int tid  = threadIdx.x;
    const int lane = tid & 31;
    const int wid  = tid >> 5;
    const int wm   = wid & 3;
    const int wn   = wid >> 2;
    const int br   = blockIdx.y * GBM;
    const int bc   = blockIdx.x * GBN;
    const int qrow = lane >> 2;
    const int qcol = (lane & 3) * 2;

    const int arow = tid >> 1;            // 0..127
    const int akh  = (tid & 1) * 16;      // 0 or 16
    const __nv_bfloat16* AHbase = AH + (size_t)(br + arow) * K + akh;
    const __nv_bfloat16* ALbase = AL + (size_t)(br + arow) * K + akh;
    const int bn  = tid >> 2;
    const int bkg = (tid & 3) * 8;
    const __nv_bfloat16* BHbase = WtH + (size_t)(bc + bn) * K + bkg;
    const __nv_bfloat16* BLbase = WtL + (size_t)(bc + bn) * K + bkg;

    // per-lane LDSM offsets (elements)
    const unsigned a_off = (unsigned)((wm * 32 + (lane & 7) + ((lane >> 3) & 1) * 8) * AKP
                                      + ((lane >> 4) & 1) * 8);
    const unsigned b_off = (unsigned)((wn * 32 + ((lane >> 4) & 1) * 8 + (lane & 7)) * AKP
                                      + ((lane >> 3) & 1) * 8);

    const unsigned sAH0 = (unsigned)__cvta_generic_to_shared(&AsH[0][0]);
    const unsigned sAL0 = (unsigned)__cvta_generic_to_shared(&AsL[0][0]);
    const unsigned sBH0 = (unsigned)__cvta_generic_to_shared(&BsH[0][0]);
    const unsigned sBL0 = (unsigned)__cvta_generic_to_shared(&BsL[0][0]);

    // per-thread cp.async destination offsets (bytes)
    const unsigned dA = (unsigned)((arow * AKP + akh) * 2);
    const unsigned dB = (unsigned)((bn * AKP + bkg) * 2);

    float acc[2][4][4];
    #pragma unroll
    for (int i = 0; i < 2; i++)
        #pragma unroll
        for (int j = 0; j < 4; j++)
            #pragma unroll
            for (int r = 0; r < 4; r++) acc[i][j][r] = 0.f;

    auto cp_stage = [&](int k0, int s) {
        unsigned off  = (unsigned)(s * GBM * AKP * 2);
        unsigned offB = (unsigned)(s * GBN * AKP * 2);
        CP16(sAH0 + off + dA,      AHbase + k0);
        CP16(sAH0 + off + dA + 16, AHbase + k0 + 8);
        CP16(sAL0 + off + dA,      ALbase + k0);
        CP16(sAL0 + off + dA + 16, ALbase + k0 + 8);
        CP16(sBH0 + offB + dB,     BHbase + k0);
        CP16(sBL0 + offB + dB,     BLbase + k0);
    };

    auto compute = [&](int s) {
        const unsigned aHs = sAH0 + (unsigned)(s * GBM * AKP * 2);
        const unsigned aLs = sAL0 + (unsigned)(s * GBM * AKP * 2);
        const unsigned bHs = sBH0 + (unsigned)(s * GBN * AKP * 2);
        const unsigned bLs = sBL0 + (unsigned)(s * GBN * AKP * 2);
        #pragma unroll
        for (int kk = 0; kk < 2; kk++) {
            const unsigned kb = kk * 16;
            unsigned aH[2][4], aL[2][4], bHf[2][4], bLf[2][4];
            #pragma unroll
            for (int ma = 0; ma < 2; ma++) {
                unsigned eoff = a_off + (unsigned)(ma * 16 * AKP) + kb;
                LDSM4(aH[ma], aHs + eoff * 2);
                LDSM4(aL[ma], aLs + eoff * 2);
            }
            #pragma unroll
            for (int p = 0; p < 2; p++) {
                unsigned eoff = b_off + (unsigned)(p * 16 * AKP) + kb;
                LDSM4(bHf[p], bHs + eoff * 2);
                LDSM4(bLf[p], bLs + eoff * 2);
            }
            // term-major ordering across 8 independent accumulators
            #pragma unroll
            for (int ma = 0; ma < 2; ma++)
                #pragma unroll
                for (int na = 0; na < 4; na++)
                    mma_bf16(acc[ma][na], aH[ma], &bHf[na >> 1][(na & 1) * 2]);
            #pragma unroll
            for (int ma = 0; ma < 2; ma++)
                #pragma unroll
                for (int na = 0; na < 4; na++)
                    mma_bf16(acc[ma][na], aH[ma], &bLf[na >> 1][(na & 1) * 2]);
            #pragma unroll
            for (int ma = 0; ma < 2; ma++)
                #pragma unroll
                for (int na = 0; na < 4; na++)
                    mma_bf16(acc[ma][na], aL[ma], &bHf[na >> 1][(na & 1) * 2]);
        }
    };

    const int nst = K / GBK;              // >= 8 always
    // prologue: stages 0 and 1 in flight (one commit group each)
    cp_stage(0, 0);
    CP_COMMIT();
    cp_stage(GBK, 1);
    CP_COMMIT();

    int s = 0;                            // buffer index = k % 3 (tracked incrementally)
    for (int k = 0; k < nst; k++) {
        CP_WAIT(1);                       // stage k resident; k+1 may be in flight
        __syncthreads();                  // all warps done with buffer (k+2)%3's old data
        if (k + 2 < nst) {
            int ws = s + 2 - ((s + 2 >= NSTAGE) ? NSTAGE : 0);
            cp_stage((k + 2) * GBK, ws);
        }
        CP_COMMIT();                      // commit every iter (possibly empty group)
        compute(s);
        if (++s == NSTAGE) s = 0;
    }

    // epilogue
    #pragma unroll
    for (int ma = 0; ma < 2; ma++) {
        #pragma unroll
        for (int half = 0; half < 2; half++) {
            int gr = br + wm * 32 + ma * 16 + qrow + half * 8;
            #pragma unroll
            for (int na = 0; na < 4; na++) {
                int gc = bc + wn * 32 + na * 8 + qcol;
                float v0 = acc[ma][na][half * 2 + 0] + bias[gc];
                float v1 = acc[ma][na][half * 2 + 1] + bias[gc + 1];
                if (gelu) {
                    v0 = 0.5f * v0 * (1.0f + erff(v0 * 0.70710678118654752f));
                    v1 = 0.5f * v1 * (1.0f + erff(v1 * 0.70710678118654752f));
                }
                if (res) {
                    float2 r = *(const float2*)&res[(size_t)gr * N + gc];
                    v0 += r.x; v1 += r.y;
                }
                if (Cf) {
                    float2 ov = {v0, v1};
                    *(float2*)&Cf[(size_t)gr * N + gc] = ov;
                }
                if (Ch) {
                    __nv_bfloat162 Hh, Ll;
                    bf16_split(v0, Hh.x, Ll.x);
                    bf16_split(v1, Hh.y, Ll.y);
                    *(__nv_bfloat162*)&Ch[(size_t)gr * N + gc] = Hh;
                    *(__nv_bfloat162*)&Cl[(size_t)gr * N + gc] = Ll;
                }
            }
        }
    }
}

// ---------------- attention: 4 queries/warp, K + V^T + P in smem -------------
#define KS_ROWS 264
#define KS_PITCH 36
#define VT_PITCH 268
#define PS_PITCH 264
#define ATT_SMEM ((KS_ROWS * KS_PITCH + 32 * VT_PITCH + 32 * PS_PITCH + 32 * KS_PITCH) * 4)

__global__ __launch_bounds__(256) void attention_kernel(
    const float* __restrict__ qkv,
    __nv_bfloat16* __restrict__ oH, __nv_bfloat16* __restrict__ oL)
{
    extern __shared__ float sm[];
    float* Ks  = sm;                           // [264][36]
    float* VsT = Ks + KS_ROWS * KS_PITCH;      // [32][268]
    float* Ps  = VsT + 32 * VT_PITCH;          // [32][264]
    float* qs  = Ps + 32 * PS_PITCH;           // [32][36]

    const int h = blockIdx.x;
    const int b = blockIdx.y;
    const int tid = threadIdx.x;
    const int w = tid >> 5, lane = tid & 31;
    const size_t base = ((size_t)b * N_TOK) * QKV_DIM + h * HD;

    for (int idx = tid; idx < KS_ROWS * 32; idx += 256) {
        int k = idx >> 5, d = idx & 31;
        float kv = 0.f, vv = 0.f;
        if (k < N_TOK) {
            kv = qkv[base + (size_t)k * QKV_DIM + 256 + d];
            vv = qkv[base + (size_t)k * QKV_DIM + 512 + d];
        }
        Ks[k * KS_PITCH + d] = kv;
        VsT[d * VT_PITCH + k] = vv;
    }
    __syncthreads();

    const int qr = lane >> 3;
    const int d4 = (lane & 7) * 4;
    float* myqs[4];
    #pragma unroll
    for (int q = 0; q < 4; q++) myqs[q] = qs + (w * 4 + q) * KS_PITCH;

    for (int it = 0; it < 9; it++) {
        int qbase = it * 32;

        __syncwarp();
        {
            int query = qbase + w * 4 + qr;
            float4 qv = {0.f, 0.f, 0.f, 0.f};
            if (query < N_TOK)
                qv = *(const float4*)&qkv[base + (size_t)query * QKV_DIM + d4];
            *(float4*)&qs[(w * 4 + qr) * KS_PITCH + d4] = qv;
        }
        __syncwarp();

        float e[4][9];
        #pragma unroll
        for (int q = 0; q < 4; q++)
            #pragma unroll
            for (int j = 0; j < 9; j++) e[q][j] = 0.f;

        #pragma unroll
        for (int dd = 0; dd < 8; dd++) {
            float4 qv[4];
            #pragma unroll
            for (int q = 0; q < 4; q++)
                qv[q] = *(const float4*)&myqs[q][dd * 4];
            #pragma unroll
            for (int j = 0; j < 9; j++) {
                int key = j * 32 + lane;
                int kc = (key < KS_ROWS) ? key : 0;
                float4 kv = *(const float4*)&Ks[kc * KS_PITCH + dd * 4];
                #pragma unroll
                for (int q = 0; q < 4; q++) {
                    e[q][j] = fmaf(qv[q].x, kv.x, e[q][j]);
                    e[q][j] = fmaf(qv[q].y, kv.y, e[q][j]);
                    e[q][j] = fmaf(qv[q].z, kv.z, e[q][j]);
                    e[q][j] = fmaf(qv[q].w, kv.w, e[q][j]);
                }
            }
        }
        #pragma unroll
        for (int j = 0; j < 9; j++) {
            int key = j * 32 + lane;
            if (key >= N_TOK)
                #pragma unroll
                for (int q = 0; q < 4; q++) e[q][j] = -INFINITY;
        }

        float scale[4];
        #pragma unroll
        for (int q = 0; q < 4; q++) {
            float m = e[q][0];
            #pragma unroll
            for (int j = 1; j < 9; j++) m = fmaxf(m, e[q][j]);
            #pragma unroll
            for (int o = 16; o > 0; o >>= 1)
                m = fmaxf(m, __shfl_xor_sync(0xffffffffu, m, o));
            float sum = 0.f;
            #pragma unroll
            for (int j = 0; j < 9; j++) {
                int key = j * 32 + lane;
                float p = (key < N_TOK) ? __expf(e[q][j] - m) : 0.f;
                e[q][j] = p;
                sum += p;
            }
            sum = warp_sum(sum);
            scale[q] = 1.f / (sum * 16.0f);
            #pragma unroll
            for (int j = 0; j < 9; j++) {
                int key = j * 32 + lane;
                if (key < KS_ROWS)
                    Ps[(w * 4 + q) * PS_PITCH + key] = e[q][j];
            }
        }
        __syncwarp();

        float acc[4] = {0.f, 0.f, 0.f, 0.f};
        #pragma unroll 4
        for (int k4 = 0; k4 < PS_PITCH / 4; k4++) {
            float4 vv = *(const float4*)&VsT[lane * VT_PITCH + k4 * 4];
            #pragma unroll
            for (int q = 0; q < 4; q++) {
                float4 pv = *(const float4*)&Ps[(w * 4 + q) * PS_PITCH + k4 * 4];
                acc[q] = fmaf(pv.x, vv.x, acc[q]);
                acc[q] = fmaf(pv.y, vv.y, acc[q]);
                acc[q] = fmaf(pv.z, vv.z, acc[q]);
                acc[q] = fmaf(pv.w, vv.w, acc[q]);
            }
        }

        #pragma unroll
        for (int q = 0; q < 4; q++) {
            int query = qbase + w * 4 + q;
            if (query < N_TOK) {
                float val = acc[q] * scale[q];
                size_t oidx = ((size_t)b * N_TOK + query) * E_DIM + h * HD + lane;
                __nv_bfloat16 hh, ll;
                bf16_split(val, hh, ll);
                oH[oidx] = hh;
                oL[oidx] = ll;
            }
        }
        __syncwarp();
    }
}

// ---------------- mean-pool + head LN + linear -------------------------------
__global__ __launch_bounds__(256) void pool_head_kernel(
    const float* __restrict__ x, const float* __restrict__ g,
    const float* __restrict__ b, const float* __restrict__ W,
    const float* __restrict__ bias, float* __restrict__ out)
{
    int bb = blockIdx.x;
    int e = threadIdx.x;
    int w = e >> 5, lane = e & 31;
    float s = 0.f;
    const float* xb = x + (size_t)bb * N_TOK * E_DIM + e;
    for (int n = 0; n < N_TOK; n++) s += xb[(size_t)n * E_DIM];
    float pooled = s * (1.0f / N_TOK);

    __shared__ float sA[8], sB[8];
    float s1 = warp_sum(pooled);
    float s2 = warp_sum(pooled * pooled);
    if (lane == 0) { sA[w] = s1; sB[w] = s2; }
    __syncthreads();
    float tot = 0.f, tot2 = 0.f;
    #pragma unroll
    for (int i = 0; i < 8; i++) { tot += sA[i]; tot2 += sB[i]; }
    float mean = tot * (1.f / E_DIM);
    float var = tot2 * (1.f / E_DIM) - mean * mean;
    float rstd = rsqrtf(var + 1e-5f);
    float y = (pooled - mean) * rstd * g[e] + b[e];
    float t = y * W[e];
    __syncthreads();
    float t1 = warp_sum(t);
    if (lane == 0) sA[w] = t1;
    __syncthreads();
    if (e == 0) {
        float tot3 = 0.f;
        #pragma unroll
        for (int i = 0; i < 8; i++) tot3 += sA[i];
        out[bb] = tot3 + bias[0];
    }
}

// ---------------- driver ------------------------------------------------------
extern "C" void kernel_launch(void* const* d_in, const int* in_sizes, int n_in,
                              void* d_out, int out_size)
{
    const int*   user    = (const int*)  d_in[0];
    const int*   item    = (const int*)  d_in[1];
    const float* ut      = (const float*)d_in[2];
    const float* it      = (const float*)d_in[3];
    const float* cls     = (const float*)d_in[4];
    const float* pos     = (const float*)d_in[5];
    const float* ln1_g   = (const float*)d_in[6];
    const float* ln1_b   = (const float*)d_in[7];
    const float* Wq      = (const float*)d_in[8];
    const float* bq      = (const float*)d_in[9];
    const float* Wk      = (const float*)d_in[10];
    const float* bk      = (const float*)d_in[11];
    const float* Wv      = (const float*)d_in[12];
    const float* bv      = (const float*)d_in[13];
    const float* Wo      = (const float*)d_in[14];
    const float* bo      = (const float*)d_in[15];
    const float* ln2_g   = (const float*)d_in[16];
    const float* ln2_b   = (const float*)d_in[17];
    const float* W1      = (const float*)d_in[18];
    const float* b1      = (const float*)d_in[19];
    const float* W2      = (const float*)d_in[20];
    const float* b2      = (const float*)d_in[21];
    const float* head_g  = (const float*)d_in[22];
    const float* head_b  = (const float*)d_in[23];
    const float* head_W  = (const float*)d_in[24];
    const float* head_bi = (const float*)d_in[25];

    float *x, *qkv, *bqkv;
    __nv_bfloat16 *hH, *hL, *oH, *oL, *tH, *tL;
    __nv_bfloat16 *WqkvH, *WqkvL, *WoH, *WoL, *W1H, *W1L, *W2H, *W2L;
    cudaGetSymbolAddress((void**)&x,     d_x);
    cudaGetSymbolAddress((void**)&qkv,   d_qkv);
    cudaGetSymbolAddress((void**)&bqkv,  d_bqkv);
    cudaGetSymbolAddress((void**)&hH,    d_hH);
    cudaGetSymbolAddress((void**)&hL,    d_hL);
    cudaGetSymbolAddress((void**)&oH,    d_oH);
    cudaGetSymbolAddress((void**)&oL,    d_oL);
    cudaGetSymbolAddress((void**)&tH,    d_tH);
    cudaGetSymbolAddress((void**)&tL,    d_tL);
    cudaGetSymbolAddress((void**)&WqkvH, d_WqkvH);
    cudaGetSymbolAddress((void**)&WqkvL, d_WqkvL);
    cudaGetSymbolAddress((void**)&WoH,   d_WoH);
    cudaGetSymbolAddress((void**)&WoL,   d_WoL);
    cudaGetSymbolAddress((void**)&W1H,   d_W1H);
    cudaGetSymbolAddress((void**)&W1L,   d_W1L);
    cudaGetSymbolAddress((void**)&W2H,   d_W2H);
    cudaGetSymbolAddress((void**)&W2L,   d_W2L);

    cudaFuncSetAttribute(attention_kernel,
                         cudaFuncAttributeMaxDynamicSharedMemorySize, ATT_SMEM);

    // single fused pack launch
    pack_all_kernel<<<(int)((NPACK + 255LL) / 256), 256>>>(
        Wq, Wk, Wv, Wo, W1, W2, bq, bk, bv,
        WqkvH, WqkvL, WoH, WoL, W1H, W1L, W2H, W2L, bqkv);

    embed_kernel<<<dim3(N_TOK, B_DIM), 256>>>(user, item, ut, it, cls, pos, x);

    const dim3 gQKV(QKV_DIM / GBN, M_PAD / GBM);   // (12, 129)
    const dim3 gE(E_DIM / GBN, M_PAD / GBM);       // (4, 129)
    const dim3 gFF(FF_DIM / GBN, M_PAD / GBM);     // (16, 129)
    const int  lnGrid = M_ROWS / 8;                // 2056

    for (int l = 0; l < DEPTH; l++) {
        size_t eOff   = (size_t)l * E_DIM;
        size_t eeOff  = (size_t)l * E_DIM * E_DIM;
        size_t ffOff  = (size_t)l * E_DIM * FF_DIM;
        size_t qkvOff = (size_t)l * E_DIM * QKV_DIM;

        layernorm_kernel<<<lnGrid, 256>>>(x, ln1_g + eOff, ln1_b + eOff, hH, hL);

        tgemm_kernel<<<gQKV, 256>>>(hH, hL, WqkvH + qkvOff, WqkvL + qkvOff,
                                    bqkv + (size_t)l * QKV_DIM, nullptr,
                                    qkv, nullptr, nullptr, E_DIM, QKV_DIM, 0);

        attention_kernel<<<dim3(H_DIM, B_DIM), 256, ATT_SMEM>>>(qkv, oH, oL);

        // x = x + (o @ Wo + bo)
        tgemm_kernel<<<gE, 256>>>(oH, oL, WoH + eeOff, WoL + eeOff,
                                  bo + eOff, x, x, nullptr, nullptr,
                                  E_DIM, E_DIM, 0);

        layernorm_kernel<<<lnGrid, 256>>>(x, ln2_g + eOff, ln2_b + eOff, hH, hL);

        // t = gelu(h @ W1 + b1)  (bf16 hi/lo output)
        tgemm_kernel<<<gFF, 256>>>(hH, hL, W1H + ffOff, W1L + ffOff,
                                   b1 + (size_t)l * FF_DIM, nullptr,
                                   nullptr, tH, tL, E_DIM, FF_DIM, 1);
        // x = x + (t @ W2 + b2)
        tgemm_kernel<<<gE, 256>>>(tH, tL, W2H + ffOff, W2L + ffOff,
                                  b2 + eOff, x, x, nullptr, nullptr,
                                  FF_DIM, E_DIM, 0);
    }

    pool_head_kernel<<<B_DIM, 256>>>(x, head_g, head_b, head_W, head_bi,
                                     (float*)d_out);
}

// round 10
// speedup vs baseline: 2.7564x; 1.0183x over previous
#include <cuda_runtime.h>
#include <cuda_bf16.h>
#include <math.h>
#include <stdint.h>

// Problem constants
#define DEPTH 12
#define E_DIM 256
#define F_DIM 128
#define H_DIM 8
#define HD 32
#define U_DIM 1000
#define I_DIM 1000
#define B_DIM 64
#define N_TOK 257                  // 2F+1
#define M_ROWS (B_DIM * N_TOK)     // 16448
#define M_PAD 16512                // 129*128 (pad rows: junk, never real outputs)
#define FF_DIM 1024
#define QKV_DIM 768

// ---------------- scratch (device globals; zero-init, no allocation) --------
__device__ float d_x[M_PAD * E_DIM];
__device__ float d_qkv[M_PAD * QKV_DIM];
__device__ float d_bqkv[DEPTH * QKV_DIM];
__device__ __nv_bfloat16 d_hH[M_PAD * E_DIM];
__device__ __nv_bfloat16 d_hL[M_PAD * E_DIM];
__device__ __nv_bfloat16 d_oH[M_PAD * E_DIM];
__device__ __nv_bfloat16 d_oL[M_PAD * E_DIM];
__device__ __nv_bfloat16 d_tH[M_PAD * FF_DIM];
__device__ __nv_bfloat16 d_tL[M_PAD * FF_DIM];
// packed bf16 hi/lo transposed weights: layout [l][N][K]
__device__ __nv_bfloat16 d_WqkvH[DEPTH * QKV_DIM * E_DIM];
__device__ __nv_bfloat16 d_WqkvL[DEPTH * QKV_DIM * E_DIM];
__device__ __nv_bfloat16 d_WoH[DEPTH * E_DIM * E_DIM];
__device__ __nv_bfloat16 d_WoL[DEPTH * E_DIM * E_DIM];
__device__ __nv_bfloat16 d_W1H[DEPTH * FF_DIM * E_DIM];
__device__ __nv_bfloat16 d_W1L[DEPTH * FF_DIM * E_DIM];
__device__ __nv_bfloat16 d_W2H[DEPTH * E_DIM * FF_DIM];
__device__ __nv_bfloat16 d_W2L[DEPTH * E_DIM * FF_DIM];

// ---------------- bf16 split helper -----------------------------------------
__device__ __forceinline__ void bf16_split(float x, __nv_bfloat16& h, __nv_bfloat16& l) {
    h = __float2bfloat16(x);
    l = __float2bfloat16(x - __bfloat162float(h));
}

// ---------------- fused weight/bias pack (single launch) ---------------------
#define NQKV (DEPTH * QKV_DIM * E_DIM)
#define NWO  (DEPTH * E_DIM * E_DIM)
#define NW1  (DEPTH * E_DIM * FF_DIM)
#define NW2  (DEPTH * FF_DIM * E_DIM)
#define NB   (DEPTH * QKV_DIM)
#define NPACK (NQKV + NWO + NW1 + NW2 + NB)

__global__ __launch_bounds__(256) void pack_all_kernel(
    const float* __restrict__ Wq, const float* __restrict__ Wk,
    const float* __restrict__ Wv, const float* __restrict__ Wo,
    const float* __restrict__ W1, const float* __restrict__ W2,
    const float* __restrict__ bq, const float* __restrict__ bk,
    const float* __restrict__ bv,
    __nv_bfloat16* __restrict__ WqkvH, __nv_bfloat16* __restrict__ WqkvL,
    __nv_bfloat16* __restrict__ WoH, __nv_bfloat16* __restrict__ WoL,
    __nv_bfloat16* __restrict__ W1H, __nv_bfloat16* __restrict__ W1L,
    __nv_bfloat16* __restrict__ W2H, __nv_bfloat16* __restrict__ W2L,
    float* __restrict__ bqkv)
{
    long long idx = (long long)blockIdx.x * 256 + threadIdx.x;
    if (idx >= NPACK) return;
    if (idx < NQKV) {
        int k = idx % E_DIM;
        int n = (idx / E_DIM) % QKV_DIM;
        int l = idx / ((long long)E_DIM * QKV_DIM);
        const float* W = (n < 256) ? Wq : (n < 512) ? Wk : Wv;
        float v = W[((long long)l * E_DIM + k) * E_DIM + (n & 255)];
        bf16_split(v, WqkvH[idx], WqkvL[idx]);
        return;
    }
    idx -= NQKV;
    if (idx < NWO) {
        int k = idx % E_DIM;
        int n = (idx / E_DIM) % E_DIM;
        int l = idx / ((long long)E_DIM * E_DIM);
        float v = Wo[((long long)l * E_DIM + k) * E_DIM + n];
        bf16_split(v, WoH[idx], WoL[idx]);
        return;
    }
    idx -= NWO;
    if (idx < NW1) {
        int k = idx % E_DIM;
        int n = (idx / E_DIM) % FF_DIM;
        int l = idx / ((long long)E_DIM * FF_DIM);
        float v = W1[((long long)l * E_DIM + k) * FF_DIM + n];
        bf16_split(v, W1H[idx], W1L[idx]);
        return;
    }
    idx -= NW1;
    if (idx < NW2) {
        int k = idx % FF_DIM;
        int n = (idx / FF_DIM) % E_DIM;
        int l = idx / ((long long)FF_DIM * E_DIM);
        float v = W2[((long long)l * FF_DIM + k) * E_DIM + n];
        bf16_split(v, W2H[idx], W2L[idx]);
        return;
    }
    idx -= NW2;
    {
        int n = idx % QKV_DIM;
        int l = idx / QKV_DIM;
        float v;
        if (n < 256)      v = bq[l * E_DIM + n];
        else if (n < 512) v = bk[l * E_DIM + (n - 256)];
        else              v = bv[l * E_DIM + (n - 512)];
        bqkv[idx] = v;
    }
}

// ---------------- embedding --------------------------------------------------
__global__ __launch_bounds__(256) void embed_kernel(
    const int* __restrict__ user, const int* __restrict__ item,
    const float* __restrict__ ut, const float* __restrict__ it,
    const float* __restrict__ cls, const float* __restrict__ pos,
    float* __restrict__ x)
{
    int n = blockIdx.x;
    int b = blockIdx.y;
    int e = threadIdx.x;
    float v;
    if (n == 0) {
        v = cls[e];
    } else if (n <= F_DIM) {
        int uid = user[b];
        v = ut[((size_t)e * U_DIM + uid) * F_DIM + (n - 1)];
    } else {
        int iid = item[b];
        v = it[((size_t)e * I_DIM + iid) * F_DIM + (n - 1 - F_DIM)];
    }
    x[((size_t)b * N_TOK + n) * E_DIM + e] = v + pos[(size_t)n * E_DIM + e];
}

// ---------------- layernorm: warp per row, emits bf16 hi/lo ------------------
__device__ __forceinline__ float warp_sum(float v) {
    #pragma unroll
    for (int o = 16; o > 0; o >>= 1) v += __shfl_xor_sync(0xffffffffu, v, o);
    return v;
}

__global__ __launch_bounds__(256) void layernorm_kernel(
    const float* __restrict__ x, const float* __restrict__ g,
    const float* __restrict__ b,
    __nv_bfloat16* __restrict__ outH, __nv_bfloat16* __restrict__ outL)
{
    int row  = blockIdx.x * 8 + (threadIdx.x >> 5);
    int lane = threadIdx.x & 31;
    const float4* xr = (const float4*)(x + (size_t)row * E_DIM);
    float4 v0 = xr[lane * 2];
    float4 v1 = xr[lane * 2 + 1];
    float s  = v0.x + v0.y + v0.z + v0.w + v1.x + v1.y + v1.z + v1.w;
    float ss = v0.x*v0.x + v0.y*v0.y + v0.z*v0.z + v0.w*v0.w
             + v1.x*v1.x + v1.y*v1.y + v1.z*v1.z + v1.w*v1.w;
    s  = warp_sum(s);
    ss = warp_sum(ss);
    float mean = s * (1.f / E_DIM);
    float var  = ss * (1.f / E_DIM) - mean * mean;
    float rstd = rsqrtf(var + 1e-5f);

    float vv[8] = {v0.x, v0.y, v0.z, v0.w, v1.x, v1.y, v1.z, v1.w};
    const float* gp = g + lane * 8;
    const float* bp = b + lane * 8;
    __nv_bfloat162 H[4], L[4];
    #pragma unroll
    for (int i = 0; i < 4; i++) {
        float y0 = (vv[2*i]   - mean) * rstd * gp[2*i]   + bp[2*i];
        float y1 = (vv[2*i+1] - mean) * rstd * gp[2*i+1] + bp[2*i+1];
        bf16_split(y0, H[i].x, L[i].x);
        bf16_split(y1, H[i].y, L[i].y);
    }
    __nv_bfloat162* oh = (__nv_bfloat162*)(outH + (size_t)row * E_DIM) + lane * 4;
    __nv_bfloat162* ol = (__nv_bfloat162*)(outL + (size_t)row * E_DIM) + lane * 4;
    #pragma unroll
    for (int i = 0; i < 4; i++) { oh[i] = H[i]; ol[i] = L[i]; }
}

// ---------------- tensor-core GEMM (bf16 3-term, 2-stage, 3 CTAs/SM) ---------
#define GBM 128
#define GBN 64
#define GBK 32
#define NSTAGE 2
#define AKP 40   // pitch: 80B rows, 16B-aligned, conflict-free 8-row LDSM phases

__device__ __forceinline__ void mma_bf16(float* c, const unsigned* a, const unsigned* b) {
    asm volatile(
        "mma.sync.aligned.m16n8k16.row.col.f32.bf16.bf16.f32 "
        "{%0,%1,%2,%3}, {%4,%5,%6,%7}, {%8,%9}, {%0,%1,%2,%3};\n"
        : "+f"(c[0]), "+f"(c[1]), "+f"(c[2]), "+f"(c[3])
        : "r"(a[0]), "r"(a[1]), "r"(a[2]), "r"(a[3]), "r"(b[0]), "r"(b[1]));
}

#define LDSM4(R, ADDR) \
    asm volatile("ldmatrix.sync.aligned.m8n8.x4.shared.b16 {%0,%1,%2,%3}, [%4];" \
        : "=r"((R)[0]), "=r"((R)[1]), "=r"((R)[2]), "=r"((R)[3]) : "r"(ADDR))

#define CP16(dst, src) \
    asm volatile("cp.async.cg.shared.global [%0], [%1], 16;" :: "r"(dst), "l"(src))
#define CP_COMMIT() asm volatile("cp.async.commit_group;" ::: "memory")
#define CP_WAIT(n)  asm volatile("cp.async.wait_group %0;" :: "n"(n) : "memory")

__global__ void __launch_bounds__(256, 3) tgemm_kernel(
    const __nv_bfloat16* __restrict__ AH, const __nv_bfloat16* __restrict__ AL,
    const __nv_bfloat16* __restrict__ WtH, const __nv_bfloat16* __restrict__ WtL,
    const float* __restrict__ bias, const float* __restrict__ res,
    float* __restrict__ Cf,
    __nv_bfloat16* __restrict__ Ch, __nv_bfloat16* __restrict__ Cl,
    int K, int N, int gelu)
{
    __shared__ __nv_bfloat16 AsH[NSTAGE][GBM * AKP];
    __shared__ __nv_bfloat16 AsL[NSTAGE][GBM * AKP];
    __shared__ __nv_bfloat16 BsH[NSTAGE][GBN * AKP];
    __shared__ __nv_bfloat16 BsL[NSTAGE][GBN * AKP];

    const int tid  = threadIdx.x;
    const int lane = tid & 31;
    const int wid  = tid >> 5;
    const int wm   = wid & 3;
    const int wn   = wid >> 2;
    const int br   = blockIdx.y * GBM;
    const int bc   = blockIdx.x * GBN;
    const int qrow = lane >> 2;
    const int qcol = (lane & 3) * 2;

    const int arow = tid >> 1;            // 0..127
    const int akh  = (tid & 1) * 16;      // 0 or 16
    const __nv_bfloat16* AHbase = AH + (size_t)(br + arow) * K + akh;
    const __nv_bfloat16* ALbase = AL + (size_t)(br + arow) * K + akh;
    const int bn  = tid >> 2;
    const int bkg = (tid & 3) * 8;
    const __nv_bfloat16* BHbase = WtH + (size_t)(bc + bn) * K + bkg;
    const __nv_bfloat16* BLbase = WtL + (size_t)(bc + bn) * K + bkg;

    // per-lane LDSM offsets (elements)
    const unsigned a_off = (unsigned)((wm * 32 + (lane & 7) + ((lane >> 3) & 1) * 8) * AKP
                                      + ((lane >> 4) & 1) * 8);
    const unsigned b_off = (unsigned)((wn * 32 + ((lane >> 4) & 1) * 8 + (lane & 7)) * AKP
                                      + ((lane >> 3) & 1) * 8);

    const unsigned sAH0 = (unsigned)__cvta_generic_to_shared(&AsH[0][0]);
    const unsigned sAL0 = (unsigned)__cvta_generic_to_shared(&AsL[0][0]);
    const unsigned sBH0 = (unsigned)__cvta_generic_to_shared(&BsH[0][0]);
    const unsigned sBL0 = (unsigned)__cvta_generic_to_shared(&BsL[0][0]);

    // per-thread cp.async destination offsets (bytes)
    const unsigned dA = (unsigned)((arow * AKP + akh) * 2);
    const unsigned dB = (unsigned)((bn * AKP + bkg) * 2);

    float acc[2][4][4];
    #pragma unroll
    for (int i = 0; i < 2; i++)
        #pragma unroll
        for (int j = 0; j < 4; j++)
            #pragma unroll
            for (int r = 0; r < 4; r++) acc[i][j][r] = 0.f;

    auto cp_stage = [&](int k0, int s) {
        unsigned off  = (unsigned)(s * GBM * AKP * 2);
        unsigned offB = (unsigned)(s * GBN * AKP * 2);
        CP16(sAH0 + off + dA,      AHbase + k0);
        CP16(sAH0 + off + dA + 16, AHbase + k0 + 8);
        CP16(sAL0 + off + dA,      ALbase + k0);
        CP16(sAL0 + off + dA + 16, ALbase + k0 + 8);
        CP16(sBH0 + offB + dB,     BHbase + k0);
        CP16(sBL0 + offB + dB,     BLbase + k0);
    };

    auto compute = [&](int s) {
        const unsigned aHs = sAH0 + (unsigned)(s * GBM * AKP * 2);
        const unsigned aLs = sAL0 + (unsigned)(s * GBM * AKP * 2);
        const unsigned bHs = sBH0 + (unsigned)(s * GBN * AKP * 2);
        const unsigned bLs = sBL0 + (unsigned)(s * GBN * AKP * 2);
        #pragma unroll
        for (int kk = 0; kk < 2; kk++) {
            const unsigned kb = kk * 16;
            unsigned aH[2][4], aL[2][4], bHf[2][4], bLf[2][4];
            #pragma unroll
            for (int ma = 0; ma < 2; ma++) {
                unsigned eoff = a_off + (unsigned)(ma * 16 * AKP) + kb;
                LDSM4(aH[ma], aHs + eoff * 2);
                LDSM4(aL[ma], aLs + eoff * 2);
            }
            #pragma unroll
            for (int p = 0; p < 2; p++) {
                unsigned eoff = b_off + (unsigned)(p * 16 * AKP) + kb;
                LDSM4(bHf[p], bHs + eoff * 2);
                LDSM4(bLf[p], bLs + eoff * 2);
            }
            // term-major ordering across 8 independent accumulators
            #pragma unroll
            for (int ma = 0; ma < 2; ma++)
                #pragma unroll
                for (int na = 0; na < 4; na++)
                    mma_bf16(acc[ma][na], aH[ma], &bHf[na >> 1][(na & 1) * 2]);
            #pragma unroll
            for (int ma = 0; ma < 2; ma++)
                #pragma unroll
                for (int na = 0; na < 4; na++)
                    mma_bf16(acc[ma][na], aH[ma], &bLf[na >> 1][(na & 1) * 2]);
            #pragma unroll
            for (int ma = 0; ma < 2; ma++)
                #pragma unroll
                for (int na = 0; na < 4; na++)
                    mma_bf16(acc[ma][na], aL[ma], &bHf[na >> 1][(na & 1) * 2]);
        }
    };

    const int nst = K / GBK;              // >= 8 always
    cp_stage(0, 0);
    CP_COMMIT();

    int s = 0;
    for (int k = 0; k < nst; k++) {
        CP_WAIT(0);                       // stage k resident (loaded during compute(k-1))
        __syncthreads();                  // publish stage k; buffer s^1 free for reuse
        if (k + 1 < nst) {
            cp_stage((k + 1) * GBK, s ^ 1);
            CP_COMMIT();
        }
        compute(s);
        s ^= 1;
    }

    // epilogue
    #pragma unroll
    for (int ma = 0; ma < 2; ma++) {
        #pragma unroll
        for (int half = 0; half < 2; half++) {
            int gr = br + wm * 32 + ma * 16 + qrow + half * 8;
            #pragma unroll
            for (int na = 0; na < 4; na++) {
                int gc = bc + wn * 32 + na * 8 + qcol;
                float v0 = acc[ma][na][half * 2 + 0] + bias[gc];
                float v1 = acc[ma][na][half * 2 + 1] + bias[gc + 1];
                if (gelu) {
                    v0 = 0.5f * v0 * (1.0f + erff(v0 * 0.70710678118654752f));
                    v1 = 0.5f * v1 * (1.0f + erff(v1 * 0.70710678118654752f));
                }
                if (res) {
                    float2 r = *(const float2*)&res[(size_t)gr * N + gc];
                    v0 += r.x; v1 += r.y;
                }
                if (Cf) {
                    float2 ov = {v0, v1};
                    *(float2*)&Cf[(size_t)gr * N + gc] = ov;
                }
                if (Ch) {
                    __nv_bfloat162 Hh, Ll;
                    bf16_split(v0, Hh.x, Ll.x);
                    bf16_split(v1, Hh.y, Ll.y);
                    *(__nv_bfloat162*)&Ch[(size_t)gr * N + gc] = Hh;
                    *(__nv_bfloat162*)&Cl[(size_t)gr * N + gc] = Ll;
                }
            }
        }
    }
}

// ---------------- attention: 4 queries/warp, K + V^T + P in smem -------------
#define KS_ROWS 264
#define KS_PITCH 36
#define VT_PITCH 268
#define PS_PITCH 264
#define ATT_SMEM ((KS_ROWS * KS_PITCH + 32 * VT_PITCH + 32 * PS_PITCH + 32 * KS_PITCH) * 4)

__global__ __launch_bounds__(256) void attention_kernel(
    const float* __restrict__ qkv,
    __nv_bfloat16* __restrict__ oH, __nv_bfloat16* __restrict__ oL)
{
    extern __shared__ float sm[];
    float* Ks  = sm;                           // [264][36]
    float* VsT = Ks + KS_ROWS * KS_PITCH;      // [32][268]
    float* Ps  = VsT + 32 * VT_PITCH;          // [32][264]
    float* qs  = Ps + 32 * PS_PITCH;           // [32][36]

    const int h = blockIdx.x;
    const int b = blockIdx.y;
    const int tid = threadIdx.x;
    const int w = tid >> 5, lane = tid & 31;
    const size_t base = ((size_t)b * N_TOK) * QKV_DIM + h * HD;

    for (int idx = tid; idx < KS_ROWS * 32; idx += 256) {
        int k = idx >> 5, d = idx & 31;
        float kv = 0.f, vv = 0.f;
        if (k < N_TOK) {
            kv = qkv[base + (size_t)k * QKV_DIM + 256 + d];
            vv = qkv[base + (size_t)k * QKV_DIM + 512 + d];
        }
        Ks[k * KS_PITCH + d] = kv;
        VsT[d * VT_PITCH + k] = vv;
    }
    __syncthreads();

    const int qr = lane >> 3;
    const int d4 = (lane & 7) * 4;
    float* myqs[4];
    #pragma unroll
    for (int q = 0; q < 4; q++) myqs[q] = qs + (w * 4 + q) * KS_PITCH;

    for (int it = 0; it < 9; it++) {
        int qbase = it * 32;

        __syncwarp();
        {
            int query = qbase + w * 4 + qr;
            float4 qv = {0.f, 0.f, 0.f, 0.f};
            if (query < N_TOK)
                qv = *(const float4*)&qkv[base + (size_t)query * QKV_DIM + d4];
            *(float4*)&qs[(w * 4 + qr) * KS_PITCH + d4] = qv;
        }
        __syncwarp();

        float e[4][9];
        #pragma unroll
        for (int q = 0; q < 4; q++)
            #pragma unroll
            for (int j = 0; j < 9; j++) e[q][j] = 0.f;

        #pragma unroll
        for (int dd = 0; dd < 8; dd++) {
            float4 qv[4];
            #pragma unroll
            for (int q = 0; q < 4; q++)
                qv[q] = *(const float4*)&myqs[q][dd * 4];
            #pragma unroll
            for (int j = 0; j < 9; j++) {
                int key = j * 32 + lane;
                int kc = (key < KS_ROWS) ? key : 0;
                float4 kv = *(const float4*)&Ks[kc * KS_PITCH + dd * 4];
                #pragma unroll
                for (int q = 0; q < 4; q++) {
                    e[q][j] = fmaf(qv[q].x, kv.x, e[q][j]);
                    e[q][j] = fmaf(qv[q].y, kv.y, e[q][j]);
                    e[q][j] = fmaf(qv[q].z, kv.z, e[q][j]);
                    e[q][j] = fmaf(qv[q].w, kv.w, e[q][j]);
                }
            }
        }
        #pragma unroll
        for (int j = 0; j < 9; j++) {
            int key = j * 32 + lane;
            if (key >= N_TOK)
                #pragma unroll
                for (int q = 0; q < 4; q++) e[q][j] = -INFINITY;
        }

        float scale[4];
        #pragma unroll
        for (int q = 0; q < 4; q++) {
            float m = e[q][0];
            #pragma unroll
            for (int j = 1; j < 9; j++) m = fmaxf(m, e[q][j]);
            #pragma unroll
            for (int o = 16; o > 0; o >>= 1)
                m = fmaxf(m, __shfl_xor_sync(0xffffffffu, m, o));
            float sum = 0.f;
            #pragma unroll
            for (int j = 0; j < 9; j++) {
                int key = j * 32 + lane;
                float p = (key < N_TOK) ? __expf(e[q][j] - m) : 0.f;
                e[q][j] = p;
                sum += p;
            }
            sum = warp_sum(sum);
            scale[q] = 1.f / (sum * 16.0f);
            #pragma unroll
            for (int j = 0; j < 9; j++) {
                int key = j * 32 + lane;
                if (key < KS_ROWS)
                    Ps[(w * 4 + q) * PS_PITCH + key] = e[q][j];
            }
        }
        __syncwarp();

        float acc[4] = {0.f, 0.f, 0.f, 0.f};
        #pragma unroll 4
        for (int k4 = 0; k4 < PS_PITCH / 4; k4++) {
            float4 vv = *(const float4*)&VsT[lane * VT_PITCH + k4 * 4];
            #pragma unroll
            for (int q = 0; q < 4; q++) {
                float4 pv = *(const float4*)&Ps[(w * 4 + q) * PS_PITCH + k4 * 4];
                acc[q] = fmaf(pv.x, vv.x, acc[q]);
                acc[q] = fmaf(pv.y, vv.y, acc[q]);
                acc[q] = fmaf(pv.z, vv.z, acc[q]);
                acc[q] = fmaf(pv.w, vv.w, acc[q]);
            }
        }

        #pragma unroll
        for (int q = 0; q < 4; q++) {
            int query = qbase + w * 4 + q;
            if (query < N_TOK) {
                float val = acc[q] * scale[q];
                size_t oidx = ((size_t)b * N_TOK + query) * E_DIM + h * HD + lane;
                __nv_bfloat16 hh, ll;
                bf16_split(val, hh, ll);
                oH[oidx] = hh;
                oL[oidx] = ll;
            }
        }
        __syncwarp();
    }
}

// ---------------- mean-pool + head LN + linear -------------------------------
__global__ __launch_bounds__(256) void pool_head_kernel(
    const float* __restrict__ x, const float* __restrict__ g,
    const float* __restrict__ b, const float* __restrict__ W,
    const float* __restrict__ bias, float* __restrict__ out)
{
    int bb = blockIdx.x;
    int e = threadIdx.x;
    int w = e >> 5, lane = e & 31;
    float s = 0.f;
    const float* xb = x + (size_t)bb * N_TOK * E_DIM + e;
    for (int n = 0; n < N_TOK; n++) s += xb[(size_t)n * E_DIM];
    float pooled = s * (1.0f / N_TOK);

    __shared__ float sA[8], sB[8];
    float s1 = warp_sum(pooled);
    float s2 = warp_sum(pooled * pooled);
    if (lane == 0) { sA[w] = s1; sB[w] = s2; }
    __syncthreads();
    float tot = 0.f, tot2 = 0.f;
    #pragma unroll
    for (int i = 0; i < 8; i++) { tot += sA[i]; tot2 += sB[i]; }
    float mean = tot * (1.f / E_DIM);
    float var = tot2 * (1.f / E_DIM) - mean * mean;
    float rstd = rsqrtf(var + 1e-5f);
    float y = (pooled - mean) * rstd * g[e] + b[e];
    float t = y * W[e];
    __syncthreads();
    float t1 = warp_sum(t);
    if (lane == 0) sA[w] = t1;
    __syncthreads();
    if (e == 0) {
        float tot3 = 0.f;
        #pragma unroll
        for (int i = 0; i < 8; i++) tot3 += sA[i];
        out[bb] = tot3 + bias[0];
    }
}

// ---------------- driver ------------------------------------------------------
extern "C" void kernel_launch(void* const* d_in, const int* in_sizes, int n_in,
                              void* d_out, int out_size)
{
    const int*   user    = (const int*)  d_in[0];
    const int*   item    = (const int*)  d_in[1];
    const float* ut      = (const float*)d_in[2];
    const float* it      = (const float*)d_in[3];
    const float* cls     = (const float*)d_in[4];
    const float* pos     = (const float*)d_in[5];
    const float* ln1_g   = (const float*)d_in[6];
    const float* ln1_b   = (const float*)d_in[7];
    const float* Wq      = (const float*)d_in[8];
    const float* bq      = (const float*)d_in[9];
    const float* Wk      = (const float*)d_in[10];
    const float* bk      = (const float*)d_in[11];
    const float* Wv      = (const float*)d_in[12];
    const float* bv      = (const float*)d_in[13];
    const float* Wo      = (const float*)d_in[14];
    const float* bo      = (const float*)d_in[15];
    const float* ln2_g   = (const float*)d_in[16];
    const float* ln2_b   = (const float*)d_in[17];
    const float* W1      = (const float*)d_in[18];
    const float* b1      = (const float*)d_in[19];
    const float* W2      = (const float*)d_in[20];
    const float* b2      = (const float*)d_in[21];
    const float* head_g  = (const float*)d_in[22];
    const float* head_b  = (const float*)d_in[23];
    const float* head_W  = (const float*)d_in[24];
    const float* head_bi = (const float*)d_in[25];

    float *x, *qkv, *bqkv;
    __nv_bfloat16 *hH, *hL, *oH, *oL, *tH, *tL;
    __nv_bfloat16 *WqkvH, *WqkvL, *WoH, *WoL, *W1H, *W1L, *W2H, *W2L;
    cudaGetSymbolAddress((void**)&x,     d_x);
    cudaGetSymbolAddress((void**)&qkv,   d_qkv);
    cudaGetSymbolAddress((void**)&bqkv,  d_bqkv);
    cudaGetSymbolAddress((void**)&hH,    d_hH);
    cudaGetSymbolAddress((void**)&hL,    d_hL);
    cudaGetSymbolAddress((void**)&oH,    d_oH);
    cudaGetSymbolAddress((void**)&oL,    d_oL);
    cudaGetSymbolAddress((void**)&tH,    d_tH);
    cudaGetSymbolAddress((void**)&tL,    d_tL);
    cudaGetSymbolAddress((void**)&WqkvH, d_WqkvH);
    cudaGetSymbolAddress((void**)&WqkvL, d_WqkvL);
    cudaGetSymbolAddress((void**)&WoH,   d_WoH);
    cudaGetSymbolAddress((void**)&WoL,   d_WoL);
    cudaGetSymbolAddress((void**)&W1H,   d_W1H);
    cudaGetSymbolAddress((void**)&W1L,   d_W1L);
    cudaGetSymbolAddress((void**)&W2H,   d_W2H);
    cudaGetSymbolAddress((void**)&W2L,   d_W2L);

    cudaFuncSetAttribute(attention_kernel,
                         cudaFuncAttributeMaxDynamicSharedMemorySize, ATT_SMEM);

    // single fused pack launch
    pack_all_kernel<<<(int)((NPACK + 255LL) / 256), 256>>>(
        Wq, Wk, Wv, Wo, W1, W2, bq, bk, bv,
        WqkvH, WqkvL, WoH, WoL, W1H, W1L, W2H, W2L, bqkv);

    embed_kernel<<<dim3(N_TOK, B_DIM), 256>>>(user, item, ut, it, cls, pos, x);

    const dim3 gQKV(QKV_DIM / GBN, M_PAD / GBM);   // (12, 129)
    const dim3 gE(E_DIM / GBN, M_PAD / GBM);       // (4, 129)
    const dim3 gFF(FF_DIM / GBN, M_PAD / GBM);     // (16, 129)
    const int  lnGrid = M_ROWS / 8;                // 2056

    for (int l = 0; l < DEPTH; l++) {
        size_t eOff   = (size_t)l * E_DIM;
        size_t eeOff  = (size_t)l * E_DIM * E_DIM;
        size_t ffOff  = (size_t)l * E_DIM * FF_DIM;
        size_t qkvOff = (size_t)l * E_DIM * QKV_DIM;

        layernorm_kernel<<<lnGrid, 256>>>(x, ln1_g + eOff, ln1_b + eOff, hH, hL);

        tgemm_kernel<<<gQKV, 256>>>(hH, hL, WqkvH + qkvOff, WqkvL + qkvOff,
                                    bqkv + (size_t)l * QKV_DIM, nullptr,
                                    qkv, nullptr, nullptr, E_DIM, QKV_DIM, 0);

        attention_kernel<<<dim3(H_DIM, B_DIM), 256, ATT_SMEM>>>(qkv, oH, oL);

        // x = x + (o @ Wo + bo)
        tgemm_kernel<<<gE, 256>>>(oH, oL, WoH + eeOff, WoL + eeOff,
                                  bo + eOff, x, x, nullptr, nullptr,
                                  E_DIM, E_DIM, 0);

        layernorm_kernel<<<lnGrid, 256>>>(x, ln2_g + eOff, ln2_b + eOff, hH, hL);

        // t = gelu(h @ W1 + b1)  (bf16 hi/lo output)
        tgemm_kernel<<<gFF, 256>>>(hH, hL, W1H + ffOff, W1L + ffOff,
                                   b1 + (size_t)l * FF_DIM, nullptr,
                                   nullptr, tH, tL, E_DIM, FF_DIM, 1);
        // x = x + (t @ W2 + b2)
        tgemm_kernel<<<gE, 256>>>(tH, tL, W2H + ffOff, W2L + ffOff,
                                  b2 + eOff, x, x, nullptr, nullptr,
                                  FF_DIM, E_DIM, 0);
    }

    pool_head_kernel<<<B_DIM, 256>>>(x, head_g, head_b, head_W, head_bi,
                                     (float*)d_out);
}

// round 11
// speedup vs baseline: 2.8529x; 1.0350x over previous
#include <cuda_runtime.h>
#include <cuda_bf16.h>
#include <math.h>
#include <stdint.h>

// Problem constants
#define DEPTH 12
#define E_DIM 256
#define F_DIM 128
#define H_DIM 8
#define HD 32
#define U_DIM 1000
#define I_DIM 1000
#define B_DIM 64
#define N_TOK 257                  // 2F+1
#define M_ROWS (B_DIM * N_TOK)     // 16448
#define M_PAD 16512                // 129*128 (pad rows: junk, never real outputs)
#define FF_DIM 1024
#define QKV_DIM 768

// ---------------- scratch (device globals; zero-init, no allocation) --------
__device__ float d_x[M_PAD * E_DIM];
__device__ float d_qkv[M_PAD * QKV_DIM];
__device__ float d_bqkv[DEPTH * QKV_DIM];
__device__ __nv_bfloat16 d_hH[M_PAD * E_DIM];
__device__ __nv_bfloat16 d_hL[M_PAD * E_DIM];
__device__ __nv_bfloat16 d_oH[M_PAD * E_DIM];
__device__ __nv_bfloat16 d_oL[M_PAD * E_DIM];
__device__ __nv_bfloat16 d_tH[M_PAD * FF_DIM];
__device__ __nv_bfloat16 d_tL[M_PAD * FF_DIM];
// packed bf16 hi/lo transposed weights: layout [l][N][K]
__device__ __nv_bfloat16 d_WqkvH[DEPTH * QKV_DIM * E_DIM];
__device__ __nv_bfloat16 d_WqkvL[DEPTH * QKV_DIM * E_DIM];
__device__ __nv_bfloat16 d_WoH[DEPTH * E_DIM * E_DIM];
__device__ __nv_bfloat16 d_WoL[DEPTH * E_DIM * E_DIM];
__device__ __nv_bfloat16 d_W1H[DEPTH * FF_DIM * E_DIM];
__device__ __nv_bfloat16 d_W1L[DEPTH * FF_DIM * E_DIM];
__device__ __nv_bfloat16 d_W2H[DEPTH * E_DIM * FF_DIM];
__device__ __nv_bfloat16 d_W2L[DEPTH * E_DIM * FF_DIM];

// ---------------- bf16 split helper -----------------------------------------
__device__ __forceinline__ void bf16_split(float x, __nv_bfloat16& h, __nv_bfloat16& l) {
    h = __float2bfloat16(x);
    l = __float2bfloat16(x - __bfloat162float(h));
}

// ---------------- fused weight/bias pack (single launch) ---------------------
#define NQKV (DEPTH * QKV_DIM * E_DIM)
#define NWO  (DEPTH * E_DIM * E_DIM)
#define NW1  (DEPTH * E_DIM * FF_DIM)
#define NW2  (DEPTH * FF_DIM * E_DIM)
#define NB   (DEPTH * QKV_DIM)
#define NPACK (NQKV + NWO + NW1 + NW2 + NB)

__global__ __launch_bounds__(256) void pack_all_kernel(
    const float* __restrict__ Wq, const float* __restrict__ Wk,
    const float* __restrict__ Wv, const float* __restrict__ Wo,
    const float* __restrict__ W1, const float* __restrict__ W2,
    const float* __restrict__ bq, const float* __restrict__ bk,
    const float* __restrict__ bv,
    __nv_bfloat16* __restrict__ WqkvH, __nv_bfloat16* __restrict__ WqkvL,
    __nv_bfloat16* __restrict__ WoH, __nv_bfloat16* __restrict__ WoL,
    __nv_bfloat16* __restrict__ W1H, __nv_bfloat16* __restrict__ W1L,
    __nv_bfloat16* __restrict__ W2H, __nv_bfloat16* __restrict__ W2L,
    float* __restrict__ bqkv)
{
    long long idx = (long long)blockIdx.x * 256 + threadIdx.x;
    if (idx >= NPACK) return;
    if (idx < NQKV) {
        int k = idx % E_DIM;
        int n = (idx / E_DIM) % QKV_DIM;
        int l = idx / ((long long)E_DIM * QKV_DIM);
        const float* W = (n < 256) ? Wq : (n < 512) ? Wk : Wv;
        float v = W[((long long)l * E_DIM + k) * E_DIM + (n & 255)];
        bf16_split(v, WqkvH[idx], WqkvL[idx]);
        return;
    }
    idx -= NQKV;
    if (idx < NWO) {
        int k = idx % E_DIM;
        int n = (idx / E_DIM) % E_DIM;
        int l = idx / ((long long)E_DIM * E_DIM);
        float v = Wo[((long long)l * E_DIM + k) * E_DIM + n];
        bf16_split(v, WoH[idx], WoL[idx]);
        return;
    }
    idx -= NWO;
    if (idx < NW1) {
        int k = idx % E_DIM;
        int n = (idx / E_DIM) % FF_DIM;
        int l = idx / ((long long)E_DIM * FF_DIM);
        float v = W1[((long long)l * E_DIM + k) * FF_DIM + n];
        bf16_split(v, W1H[idx], W1L[idx]);
        return;
    }
    idx -= NW1;
    if (idx < NW2) {
        int k = idx % FF_DIM;
        int n = (idx / FF_DIM) % E_DIM;
        int l = idx / ((long long)FF_DIM * E_DIM);
        float v = W2[((long long)l * FF_DIM + k) * E_DIM + n];
        bf16_split(v, W2H[idx], W2L[idx]);
        return;
    }
    idx -= NW2;
    {
        int n = idx % QKV_DIM;
        int l = idx / QKV_DIM;
        float v;
        if (n < 256)      v = bq[l * E_DIM + n];
        else if (n < 512) v = bk[l * E_DIM + (n - 256)];
        else              v = bv[l * E_DIM + (n - 512)];
        bqkv[idx] = v;
    }
}

// ---------------- embedding --------------------------------------------------
__global__ __launch_bounds__(256) void embed_kernel(
    const int* __restrict__ user, const int* __restrict__ item,
    const float* __restrict__ ut, const float* __restrict__ it,
    const float* __restrict__ cls, const float* __restrict__ pos,
    float* __restrict__ x)
{
    int n = blockIdx.x;
    int b = blockIdx.y;
    int e = threadIdx.x;
    float v;
    if (n == 0) {
        v = cls[e];
    } else if (n <= F_DIM) {
        int uid = user[b];
        v = ut[((size_t)e * U_DIM + uid) * F_DIM + (n - 1)];
    } else {
        int iid = item[b];
        v = it[((size_t)e * I_DIM + iid) * F_DIM + (n - 1 - F_DIM)];
    }
    x[((size_t)b * N_TOK + n) * E_DIM + e] = v + pos[(size_t)n * E_DIM + e];
}

// ---------------- layernorm: warp per row, emits bf16 hi/lo ------------------
__device__ __forceinline__ float warp_sum(float v) {
    #pragma unroll
    for (int o = 16; o > 0; o >>= 1) v += __shfl_xor_sync(0xffffffffu, v, o);
    return v;
}

__global__ __launch_bounds__(256) void layernorm_kernel(
    const float* __restrict__ x, const float* __restrict__ g,
    const float* __restrict__ b,
    __nv_bfloat16* __restrict__ outH, __nv_bfloat16* __restrict__ outL)
{
    int row  = blockIdx.x * 8 + (threadIdx.x >> 5);
    int lane = threadIdx.x & 31;
    const float4* xr = (const float4*)(x + (size_t)row * E_DIM);
    float4 v0 = xr[lane * 2];
    float4 v1 = xr[lane * 2 + 1];
    float s  = v0.x + v0.y + v0.z + v0.w + v1.x + v1.y + v1.z + v1.w;
    float ss = v0.x*v0.x + v0.y*v0.y + v0.z*v0.z + v0.w*v0.w
             + v1.x*v1.x + v1.y*v1.y + v1.z*v1.z + v1.w*v1.w;
    s  = warp_sum(s);
    ss = warp_sum(ss);
    float mean = s * (1.f / E_DIM);
    float var  = ss * (1.f / E_DIM) - mean * mean;
    float rstd = rsqrtf(var + 1e-5f);

    float vv[8] = {v0.x, v0.y, v0.z, v0.w, v1.x, v1.y, v1.z, v1.w};
    const float* gp = g + lane * 8;
    const float* bp = b + lane * 8;
    __nv_bfloat162 H[4], L[4];
    #pragma unroll
    for (int i = 0; i < 4; i++) {
        float y0 = (vv[2*i]   - mean) * rstd * gp[2*i]   + bp[2*i];
        float y1 = (vv[2*i+1] - mean) * rstd * gp[2*i+1] + bp[2*i+1];
        bf16_split(y0, H[i].x, L[i].x);
        bf16_split(y1, H[i].y, L[i].y);
    }
    __nv_bfloat162* oh = (__nv_bfloat162*)(outH + (size_t)row * E_DIM) + lane * 4;
    __nv_bfloat162* ol = (__nv_bfloat162*)(outL + (size_t)row * E_DIM) + lane * 4;
    #pragma unroll
    for (int i = 0; i < 4; i++) { oh[i] = H[i]; ol[i] = L[i]; }
}

// ---------------- tensor-core GEMM (bf16 3-term, 128x128 tile, 2-stage) ------
#define GBM 128
#define GBN 128
#define GBK 32
#define AKP 40       // pitch: 80B rows, conflict-free 8-row LDSM phases
#define MATB (GBM * AKP * 2)          // bytes per matrix per stage (10240)
#define TG_SMEM (8 * MATB)            // 2 stages x 4 matrices = 81920 B

__device__ __forceinline__ void mma_bf16(float* c, const unsigned* a, const unsigned* b) {
    asm volatile(
        "mma.sync.aligned.m16n8k16.row.col.f32.bf16.bf16.f32 "
        "{%0,%1,%2,%3}, {%4,%5,%6,%7}, {%8,%9}, {%0,%1,%2,%3};\n"
        : "+f"(c[0]), "+f"(c[1]), "+f"(c[2]), "+f"(c[3])
        : "r"(a[0]), "r"(a[1]), "r"(a[2]), "r"(a[3]), "r"(b[0]), "r"(b[1]));
}

#define LDSM4(R, ADDR) \
    asm volatile("ldmatrix.sync.aligned.m8n8.x4.shared.b16 {%0,%1,%2,%3}, [%4];" \
        : "=r"((R)[0]), "=r"((R)[1]), "=r"((R)[2]), "=r"((R)[3]) : "r"(ADDR))

#define CP16(dst, src) \
    asm volatile("cp.async.cg.shared.global [%0], [%1], 16;" :: "r"(dst), "l"(src))
#define CP_COMMIT() asm volatile("cp.async.commit_group;" ::: "memory")
#define CP_WAIT(n)  asm volatile("cp.async.wait_group %0;" :: "n"(n) : "memory")

__global__ void __launch_bounds__(256, 2) tgemm_kernel(
    const __nv_bfloat16* __restrict__ AH, const __nv_bfloat16* __restrict__ AL,
    const __nv_bfloat16* __restrict__ WtH, const __nv_bfloat16* __restrict__ WtL,
    const float* __restrict__ bias, const float* __restrict__ res,
    float* __restrict__ Cf,
    __nv_bfloat16* __restrict__ Ch, __nv_bfloat16* __restrict__ Cl,
    int K, int N, int gelu)
{
    extern __shared__ char smem[];

    const int tid  = threadIdx.x;
    const int lane = tid & 31;
    const int wid  = tid >> 5;
    const int wm   = wid & 3;            // 0..3  (m, 32 rows each)
    const int wn   = wid >> 2;           // 0..1  (n, 64 cols each)
    const int br   = blockIdx.y * GBM;
    const int bc   = blockIdx.x * GBN;
    const int qrow = lane >> 2;
    const int qcol = (lane & 3) * 2;

    const int arow = tid >> 1;           // 0..127
    const int akh  = (tid & 1) * 16;     // 0 or 16
    const __nv_bfloat16* AHbase = AH + (size_t)(br + arow) * K + akh;
    const __nv_bfloat16* ALbase = AL + (size_t)(br + arow) * K + akh;
    const __nv_bfloat16* BHbase = WtH + (size_t)(bc + arow) * K + akh;
    const __nv_bfloat16* BLbase = WtL + (size_t)(bc + arow) * K + akh;

    // per-lane LDSM offsets (elements)
    const unsigned a_off = (unsigned)((wm * 32 + (lane & 7) + ((lane >> 3) & 1) * 8) * AKP
                                      + ((lane >> 4) & 1) * 8);
    const unsigned b_off = (unsigned)((wn * 64 + ((lane >> 4) & 1) * 8 + (lane & 7)) * AKP
                                      + ((lane >> 3) & 1) * 8);

    const unsigned sAH0 = (unsigned)__cvta_generic_to_shared(smem);
    const unsigned sAL0 = sAH0 + 2 * MATB;
    const unsigned sBH0 = sAH0 + 4 * MATB;
    const unsigned sBL0 = sAH0 + 6 * MATB;

    // per-thread cp.async destination offsets (bytes) — same for A and B tiles
    const unsigned dT = (unsigned)((arow * AKP + akh) * 2);

    float acc[2][8][4];
    #pragma unroll
    for (int i = 0; i < 2; i++)
        #pragma unroll
        for (int j = 0; j < 8; j++)
            #pragma unroll
            for (int r = 0; r < 4; r++) acc[i][j][r] = 0.f;

    auto cp_stage = [&](int k0, int s) {
        unsigned off = (unsigned)(s * MATB);
        CP16(sAH0 + off + dT,      AHbase + k0);
        CP16(sAH0 + off + dT + 16, AHbase + k0 + 8);
        CP16(sAL0 + off + dT,      ALbase + k0);
        CP16(sAL0 + off + dT + 16, ALbase + k0 + 8);
        CP16(sBH0 + off + dT,      BHbase + k0);
        CP16(sBH0 + off + dT + 16, BHbase + k0 + 8);
        CP16(sBL0 + off + dT,      BLbase + k0);
        CP16(sBL0 + off + dT + 16, BLbase + k0 + 8);
    };

    auto compute = [&](int s) {
        const unsigned off = (unsigned)(s * MATB);
        const unsigned aHs = sAH0 + off;
        const unsigned aLs = sAL0 + off;
        const unsigned bHs = sBH0 + off;
        const unsigned bLs = sBL0 + off;
        #pragma unroll
        for (int kk = 0; kk < 2; kk++) {
            const unsigned kb = kk * 16;
            unsigned aH[2][4], aL[2][4];
            #pragma unroll
            for (int ma = 0; ma < 2; ma++) {
                unsigned eoff = a_off + (unsigned)(ma * 16 * AKP) + kb;
                LDSM4(aH[ma], aHs + eoff * 2);
                LDSM4(aL[ma], aLs + eoff * 2);
            }
            #pragma unroll
            for (int p = 0; p < 4; p++) {
                unsigned bH[4], bL[4];
                unsigned eoff = b_off + (unsigned)(p * 16 * AKP) + kb;
                LDSM4(bH, bHs + eoff * 2);
                LDSM4(bL, bLs + eoff * 2);
                #pragma unroll
                for (int half = 0; half < 2; half++) {
                    const int na = p * 2 + half;
                    const unsigned* bh = &bH[half * 2];
                    const unsigned* bl = &bL[half * 2];
                    #pragma unroll
                    for (int ma = 0; ma < 2; ma++) {
                        mma_bf16(acc[ma][na], aH[ma], bh);
                        mma_bf16(acc[ma][na], aH[ma], bl);
                        mma_bf16(acc[ma][na], aL[ma], bh);
                    }
                }
            }
        }
    };

    const int nst = K / GBK;             // >= 8 always
    cp_stage(0, 0);
    CP_COMMIT();

    int s = 0;
    for (int k = 0; k < nst; k++) {
        CP_WAIT(0);                      // stage k resident (loaded during compute(k-1))
        __syncthreads();                 // publish stage k; buffer s^1 free for reuse
        if (k + 1 < nst) {
            cp_stage((k + 1) * GBK, s ^ 1);
            CP_COMMIT();
        }
        compute(s);
        s ^= 1;
    }

    // epilogue
    #pragma unroll
    for (int ma = 0; ma < 2; ma++) {
        #pragma unroll
        for (int half = 0; half < 2; half++) {
            int gr = br + wm * 32 + ma * 16 + qrow + half * 8;
            #pragma unroll
            for (int na = 0; na < 8; na++) {
                int gc = bc + wn * 64 + na * 8 + qcol;
                float v0 = acc[ma][na][half * 2 + 0] + bias[gc];
                float v1 = acc[ma][na][half * 2 + 1] + bias[gc + 1];
                if (gelu) {
                    v0 = 0.5f * v0 * (1.0f + erff(v0 * 0.70710678118654752f));
                    v1 = 0.5f * v1 * (1.0f + erff(v1 * 0.70710678118654752f));
                }
                if (res) {
                    float2 r = *(const float2*)&res[(size_t)gr * N + gc];
                    v0 += r.x; v1 += r.y;
                }
                if (Cf) {
                    float2 ov = {v0, v1};
                    *(float2*)&Cf[(size_t)gr * N + gc] = ov;
                }
                if (Ch) {
                    __nv_bfloat162 Hh, Ll;
                    bf16_split(v0, Hh.x, Ll.x);
                    bf16_split(v1, Hh.y, Ll.y);
                    *(__nv_bfloat162*)&Ch[(size_t)gr * N + gc] = Hh;
                    *(__nv_bfloat162*)&Cl[(size_t)gr * N + gc] = Ll;
                }
            }
        }
    }
}

// ---------------- attention: 4 queries/warp, K + V^T + P in smem -------------
#define KS_ROWS 264
#define KS_PITCH 36
#define VT_PITCH 268
#define PS_PITCH 264
#define ATT_SMEM ((KS_ROWS * KS_PITCH + 32 * VT_PITCH + 32 * PS_PITCH + 32 * KS_PITCH) * 4)

__global__ __launch_bounds__(256) void attention_kernel(
    const float* __restrict__ qkv,
    __nv_bfloat16* __restrict__ oH, __nv_bfloat16* __restrict__ oL)
{
    extern __shared__ float sm[];
    float* Ks  = sm;                           // [264][36]
    float* VsT = Ks + KS_ROWS * KS_PITCH;      // [32][268]
    float* Ps  = VsT + 32 * VT_PITCH;          // [32][264]
    float* qs  = Ps + 32 * PS_PITCH;           // [32][36]

    const int h = blockIdx.x;
    const int b = blockIdx.y;
    const int tid = threadIdx.x;
    const int w = tid >> 5, lane = tid & 31;
    const size_t base = ((size_t)b * N_TOK) * QKV_DIM + h * HD;

    for (int idx = tid; idx < KS_ROWS * 32; idx += 256) {
        int k = idx >> 5, d = idx & 31;
        float kv = 0.f, vv = 0.f;
        if (k < N_TOK) {
            kv = qkv[base + (size_t)k * QKV_DIM + 256 + d];
            vv = qkv[base + (size_t)k * QKV_DIM + 512 + d];
        }
        Ks[k * KS_PITCH + d] = kv;
        VsT[d * VT_PITCH + k] = vv;
    }
    __syncthreads();

    const int qr = lane >> 3;
    const int d4 = (lane & 7) * 4;
    float* myqs[4];
    #pragma unroll
    for (int q = 0; q < 4; q++) myqs[q] = qs + (w * 4 + q) * KS_PITCH;

    for (int it = 0; it < 9; it++) {
        int qbase = it * 32;

        __syncwarp();
        {
            int query = qbase + w * 4 + qr;
            float4 qv = {0.f, 0.f, 0.f, 0.f};
            if (query < N_TOK)
                qv = *(const float4*)&qkv[base + (size_t)query * QKV_DIM + d4];
            *(float4*)&qs[(w * 4 + qr) * KS_PITCH + d4] = qv;
        }
        __syncwarp();

        float e[4][9];
        #pragma unroll
        for (int q = 0; q < 4; q++)
            #pragma unroll
            for (int j = 0; j < 9; j++) e[q][j] = 0.f;

        #pragma unroll
        for (int dd = 0; dd < 8; dd++) {
            float4 qv[4];
            #pragma unroll
            for (int q = 0; q < 4; q++)
                qv[q] = *(const float4*)&myqs[q][dd * 4];
            #pragma unroll
            for (int j = 0; j < 9; j++) {
                int key = j * 32 + lane;
                int kc = (key < KS_ROWS) ? key : 0;
                float4 kv = *(const float4*)&Ks[kc * KS_PITCH + dd * 4];
                #pragma unroll
                for (int q = 0; q < 4; q++) {
                    e[q][j] = fmaf(qv[q].x, kv.x, e[q][j]);
                    e[q][j] = fmaf(qv[q].y, kv.y, e[q][j]);
                    e[q][j] = fmaf(qv[q].z, kv.z, e[q][j]);
                    e[q][j] = fmaf(qv[q].w, kv.w, e[q][j]);
                }
            }
        }
        #pragma unroll
        for (int j = 0; j < 9; j++) {
            int key = j * 32 + lane;
            if (key >= N_TOK)
                #pragma unroll
                for (int q = 0; q < 4; q++) e[q][j] = -INFINITY;
        }

        float scale[4];
        #pragma unroll
        for (int q = 0; q < 4; q++) {
            float m = e[q][0];
            #pragma unroll
            for (int j = 1; j < 9; j++) m = fmaxf(m, e[q][j]);
            #pragma unroll
            for (int o = 16; o > 0; o >>= 1)
                m = fmaxf(m, __shfl_xor_sync(0xffffffffu, m, o));
            float sum = 0.f;
            #pragma unroll
            for (int j = 0; j < 9; j++) {
                int key = j * 32 + lane;
                float p = (key < N_TOK) ? __expf(e[q][j] - m) : 0.f;
                e[q][j] = p;
                sum += p;
            }
            sum = warp_sum(sum);
            scale[q] = 1.f / (sum * 16.0f);
            #pragma unroll
            for (int j = 0; j < 9; j++) {
                int key = j * 32 + lane;
                if (key < KS_ROWS)
                    Ps[(w * 4 + q) * PS_PITCH + key] = e[q][j];
            }
        }
        __syncwarp();

        float acc[4] = {0.f, 0.f, 0.f, 0.f};
        #pragma unroll 4
        for (int k4 = 0; k4 < PS_PITCH / 4; k4++) {
            float4 vv = *(const float4*)&VsT[lane * VT_PITCH + k4 * 4];
            #pragma unroll
            for (int q = 0; q < 4; q++) {
                float4 pv = *(const float4*)&Ps[(w * 4 + q) * PS_PITCH + k4 * 4];
                acc[q] = fmaf(pv.x, vv.x, acc[q]);
                acc[q] = fmaf(pv.y, vv.y, acc[q]);
                acc[q] = fmaf(pv.z, vv.z, acc[q]);
                acc[q] = fmaf(pv.w, vv.w, acc[q]);
            }
        }

        #pragma unroll
        for (int q = 0; q < 4; q++) {
            int query = qbase + w * 4 + q;
            if (query < N_TOK) {
                float val = acc[q] * scale[q];
                size_t oidx = ((size_t)b * N_TOK + query) * E_DIM + h * HD + lane;
                __nv_bfloat16 hh, ll;
                bf16_split(val, hh, ll);
                oH[oidx] = hh;
                oL[oidx] = ll;
            }
        }
        __syncwarp();
    }
}

// ---------------- mean-pool + head LN + linear -------------------------------
__global__ __launch_bounds__(256) void pool_head_kernel(
    const float* __restrict__ x, const float* __restrict__ g,
    const float* __restrict__ b, const float* __restrict__ W,
    const float* __restrict__ bias, float* __restrict__ out)
{
    int bb = blockIdx.x;
    int e = threadIdx.x;
    int w = e >> 5, lane = e & 31;
    float s = 0.f;
    const float* xb = x + (size_t)bb * N_TOK * E_DIM + e;
    for (int n = 0; n < N_TOK; n++) s += xb[(size_t)n * E_DIM];
    float pooled = s * (1.0f / N_TOK);

    __shared__ float sA[8], sB[8];
    float s1 = warp_sum(pooled);
    float s2 = warp_sum(pooled * pooled);
    if (lane == 0) { sA[w] = s1; sB[w] = s2; }
    __syncthreads();
    float tot = 0.f, tot2 = 0.f;
    #pragma unroll
    for (int i = 0; i < 8; i++) { tot += sA[i]; tot2 += sB[i]; }
    float mean = tot * (1.f / E_DIM);
    float var = tot2 * (1.f / E_DIM) - mean * mean;
    float rstd = rsqrtf(var + 1e-5f);
    float y = (pooled - mean) * rstd * g[e] + b[e];
    float t = y * W[e];
    __syncthreads();
    float t1 = warp_sum(t);
    if (lane == 0) sA[w] = t1;
    __syncthreads();
    if (e == 0) {
        float tot3 = 0.f;
        #pragma unroll
        for (int i = 0; i < 8; i++) tot3 += sA[i];
        out[bb] = tot3 + bias[0];
    }
}

// ---------------- driver ------------------------------------------------------
extern "C" void kernel_launch(void* const* d_in, const int* in_sizes, int n_in,
                              void* d_out, int out_size)
{
    const int*   user    = (const int*)  d_in[0];
    const int*   item    = (const int*)  d_in[1];
    const float* ut      = (const float*)d_in[2];
    const float* it      = (const float*)d_in[3];
    const float* cls     = (const float*)d_in[4];
    const float* pos     = (const float*)d_in[5];
    const float* ln1_g   = (const float*)d_in[6];
    const float* ln1_b   = (const float*)d_in[7];
    const float* Wq      = (const float*)d_in[8];
    const float* bq      = (const float*)d_in[9];
    const float* Wk      = (const float*)d_in[10];
    const float* bk      = (const float*)d_in[11];
    const float* Wv      = (const float*)d_in[12];
    const float* bv      = (const float*)d_in[13];
    const float* Wo      = (const float*)d_in[14];
    const float* bo      = (const float*)d_in[15];
    const float* ln2_g   = (const float*)d_in[16];
    const float* ln2_b   = (const float*)d_in[17];
    const float* W1      = (const float*)d_in[18];
    const float* b1      = (const float*)d_in[19];
    const float* W2      = (const float*)d_in[20];
    const float* b2      = (const float*)d_in[21];
    const float* head_g  = (const float*)d_in[22];
    const float* head_b  = (const float*)d_in[23];
    const float* head_W  = (const float*)d_in[24];
    const float* head_bi = (const float*)d_in[25];

    float *x, *qkv, *bqkv;
    __nv_bfloat16 *hH, *hL, *oH, *oL, *tH, *tL;
    __nv_bfloat16 *WqkvH, *WqkvL, *WoH, *WoL, *W1H, *W1L, *W2H, *W2L;
    cudaGetSymbolAddress((void**)&x,     d_x);
    cudaGetSymbolAddress((void**)&qkv,   d_qkv);
    cudaGetSymbolAddress((void**)&bqkv,  d_bqkv);
    cudaGetSymbolAddress((void**)&hH,    d_hH);
    cudaGetSymbolAddress((void**)&hL,    d_hL);
    cudaGetSymbolAddress((void**)&oH,    d_oH);
    cudaGetSymbolAddress((void**)&oL,    d_oL);
    cudaGetSymbolAddress((void**)&tH,    d_tH);
    cudaGetSymbolAddress((void**)&tL,    d_tL);
    cudaGetSymbolAddress((void**)&WqkvH, d_WqkvH);
    cudaGetSymbolAddress((void**)&WqkvL, d_WqkvL);
    cudaGetSymbolAddress((void**)&WoH,   d_WoH);
    cudaGetSymbolAddress((void**)&WoL,   d_WoL);
    cudaGetSymbolAddress((void**)&W1H,   d_W1H);
    cudaGetSymbolAddress((void**)&W1L,   d_W1L);
    cudaGetSymbolAddress((void**)&W2H,   d_W2H);
    cudaGetSymbolAddress((void**)&W2L,   d_W2L);

    cudaFuncSetAttribute(attention_kernel,
                         cudaFuncAttributeMaxDynamicSharedMemorySize, ATT_SMEM);
    cudaFuncSetAttribute(tgemm_kernel,
                         cudaFuncAttributeMaxDynamicSharedMemorySize, TG_SMEM);

    // single fused pack launch
    pack_all_kernel<<<(int)((NPACK + 255LL) / 256), 256>>>(
        Wq, Wk, Wv, Wo, W1, W2, bq, bk, bv,
        WqkvH, WqkvL, WoH, WoL, W1H, W1L, W2H, W2L, bqkv);

    embed_kernel<<<dim3(N_TOK, B_DIM), 256>>>(user, item, ut, it, cls, pos, x);

    const dim3 gQKV(QKV_DIM / GBN, M_PAD / GBM);   // (6, 129)
    const dim3 gE(E_DIM / GBN, M_PAD / GBM);       // (2, 129)
    const dim3 gFF(FF_DIM / GBN, M_PAD / GBM);     // (8, 129)
    const int  lnGrid = M_ROWS / 8;                // 2056

    for (int l = 0; l < DEPTH; l++) {
        size_t eOff   = (size_t)l * E_DIM;
        size_t eeOff  = (size_t)l * E_DIM * E_DIM;
        size_t ffOff  = (size_t)l * E_DIM * FF_DIM;
        size_t qkvOff = (size_t)l * E_DIM * QKV_DIM;

        layernorm_kernel<<<lnGrid, 256>>>(x, ln1_g + eOff, ln1_b + eOff, hH, hL);

        tgemm_kernel<<<gQKV, 256, TG_SMEM>>>(hH, hL, WqkvH + qkvOff, WqkvL + qkvOff,
                                             bqkv + (size_t)l * QKV_DIM, nullptr,
                                             qkv, nullptr, nullptr, E_DIM, QKV_DIM, 0);

        attention_kernel<<<dim3(H_DIM, B_DIM), 256, ATT_SMEM>>>(qkv, oH, oL);

        // x = x + (o @ Wo + bo)
        tgemm_kernel<<<gE, 256, TG_SMEM>>>(oH, oL, WoH + eeOff, WoL + eeOff,
                                           bo + eOff, x, x, nullptr, nullptr,
                                           E_DIM, E_DIM, 0);

        layernorm_kernel<<<lnGrid, 256>>>(x, ln2_g + eOff, ln2_b + eOff, hH, hL);

        // t = gelu(h @ W1 + b1)  (bf16 hi/lo output)
        tgemm_kernel<<<gFF, 256, TG_SMEM>>>(hH, hL, W1H + ffOff, W1L + ffOff,
                                            b1 + (size_t)l * FF_DIM, nullptr,
                                            nullptr, tH, tL, E_DIM, FF_DIM, 1);
        // x = x + (t @ W2 + b2)
        tgemm_kernel<<<gE, 256, TG_SMEM>>>(tH, tL, W2H + ffOff, W2L + ffOff,
                                           b2 + eOff, x, x, nullptr, nullptr,
                                           FF_DIM, E_DIM, 0);
    }

    pool_head_kernel<<<B_DIM, 256>>>(x, head_g, head_b, head_W, head_bi,
                                     (float*)d_out);
}

// round 12
// speedup vs baseline: 2.8626x; 1.0034x over previous
#include <cuda_runtime.h>
#include <cuda_bf16.h>
#include <math.h>
#include <stdint.h>

// Problem constants
#define DEPTH 12
#define E_DIM 256
#define F_DIM 128
#define H_DIM 8
#define HD 32
#define U_DIM 1000
#define I_DIM 1000
#define B_DIM 64
#define N_TOK 257                  // 2F+1
#define M_ROWS (B_DIM * N_TOK)     // 16448
#define M_PAD 16512                // 129*128 (pad rows: junk, never real outputs)
#define FF_DIM 1024
#define QKV_DIM 768

// ---------------- scratch (device globals; zero-init, no allocation) --------
__device__ float d_x[M_PAD * E_DIM];
__device__ float d_qkv[M_PAD * QKV_DIM];
__device__ float d_bqkv[DEPTH * QKV_DIM];
__device__ __nv_bfloat16 d_hH[M_PAD * E_DIM];
__device__ __nv_bfloat16 d_hL[M_PAD * E_DIM];
__device__ __nv_bfloat16 d_oH[M_PAD * E_DIM];
__device__ __nv_bfloat16 d_oL[M_PAD * E_DIM];
__device__ __nv_bfloat16 d_tH[M_PAD * FF_DIM];
__device__ __nv_bfloat16 d_tL[M_PAD * FF_DIM];
// packed bf16 hi/lo transposed weights: layout [l][N][K]
__device__ __nv_bfloat16 d_WqkvH[DEPTH * QKV_DIM * E_DIM];
__device__ __nv_bfloat16 d_WqkvL[DEPTH * QKV_DIM * E_DIM];
__device__ __nv_bfloat16 d_WoH[DEPTH * E_DIM * E_DIM];
__device__ __nv_bfloat16 d_WoL[DEPTH * E_DIM * E_DIM];
__device__ __nv_bfloat16 d_W1H[DEPTH * FF_DIM * E_DIM];
__device__ __nv_bfloat16 d_W1L[DEPTH * FF_DIM * E_DIM];
__device__ __nv_bfloat16 d_W2H[DEPTH * E_DIM * FF_DIM];
__device__ __nv_bfloat16 d_W2L[DEPTH * E_DIM * FF_DIM];

// ---------------- bf16 split helper -----------------------------------------
__device__ __forceinline__ void bf16_split(float x, __nv_bfloat16& h, __nv_bfloat16& l) {
    h = __float2bfloat16(x);
    l = __float2bfloat16(x - __bfloat162float(h));
}

// ---------------- fused weight/bias pack (single launch) ---------------------
#define NQKV (DEPTH * QKV_DIM * E_DIM)
#define NWO  (DEPTH * E_DIM * E_DIM)
#define NW1  (DEPTH * E_DIM * FF_DIM)
#define NW2  (DEPTH * FF_DIM * E_DIM)
#define NB   (DEPTH * QKV_DIM)
#define NPACK (NQKV + NWO + NW1 + NW2 + NB)

__global__ __launch_bounds__(256) void pack_all_kernel(
    const float* __restrict__ Wq, const float* __restrict__ Wk,
    const float* __restrict__ Wv, const float* __restrict__ Wo,
    const float* __restrict__ W1, const float* __restrict__ W2,
    const float* __restrict__ bq, const float* __restrict__ bk,
    const float* __restrict__ bv,
    __nv_bfloat16* __restrict__ WqkvH, __nv_bfloat16* __restrict__ WqkvL,
    __nv_bfloat16* __restrict__ WoH, __nv_bfloat16* __restrict__ WoL,
    __nv_bfloat16* __restrict__ W1H, __nv_bfloat16* __restrict__ W1L,
    __nv_bfloat16* __restrict__ W2H, __nv_bfloat16* __restrict__ W2L,
    float* __restrict__ bqkv)
{
    long long idx = (long long)blockIdx.x * 256 + threadIdx.x;
    if (idx >= NPACK) return;
    if (idx < NQKV) {
        int k = idx % E_DIM;
        int n = (idx / E_DIM) % QKV_DIM;
        int l = idx / ((long long)E_DIM * QKV_DIM);
        const float* W = (n < 256) ? Wq : (n < 512) ? Wk : Wv;
        float v = W[((long long)l * E_DIM + k) * E_DIM + (n & 255)];
        bf16_split(v, WqkvH[idx], WqkvL[idx]);
        return;
    }
    idx -= NQKV;
    if (idx < NWO) {
        int k = idx % E_DIM;
        int n = (idx / E_DIM) % E_DIM;
        int l = idx / ((long long)E_DIM * E_DIM);
        float v = Wo[((long long)l * E_DIM + k) * E_DIM + n];
        bf16_split(v, WoH[idx], WoL[idx]);
        return;
    }
    idx -= NWO;
    if (idx < NW1) {
        int k = idx % E_DIM;
        int n = (idx / E_DIM) % FF_DIM;
        int l = idx / ((long long)E_DIM * FF_DIM);
        float v = W1[((long long)l * E_DIM + k) * FF_DIM + n];
        bf16_split(v, W1H[idx], W1L[idx]);
        return;
    }
    idx -= NW1;
    if (idx < NW2) {
        int k = idx % FF_DIM;
        int n = (idx / FF_DIM) % E_DIM;
        int l = idx / ((long long)FF_DIM * E_DIM);
        float v = W2[((long long)l * FF_DIM + k) * E_DIM + n];
        bf16_split(v, W2H[idx], W2L[idx]);
        return;
    }
    idx -= NW2;
    {
        int n = idx % QKV_DIM;
        int l = idx / QKV_DIM;
        float v;
        if (n < 256)      v = bq[l * E_DIM + n];
        else if (n < 512) v = bk[l * E_DIM + (n - 256)];
        else              v = bv[l * E_DIM + (n - 512)];
        bqkv[idx] = v;
    }
}

// ---------------- embedding --------------------------------------------------
__global__ __launch_bounds__(256) void embed_kernel(
    const int* __restrict__ user, const int* __restrict__ item,
    const float* __restrict__ ut, const float* __restrict__ it,
    const float* __restrict__ cls, const float* __restrict__ pos,
    float* __restrict__ x)
{
    int n = blockIdx.x;
    int b = blockIdx.y;
    int e = threadIdx.x;
    float v;
    if (n == 0) {
        v = cls[e];
    } else if (n <= F_DIM) {
        int uid = user[b];
        v = ut[((size_t)e * U_DIM + uid) * F_DIM + (n - 1)];
    } else {
        int iid = item[b];
        v = it[((size_t)e * I_DIM + iid) * F_DIM + (n - 1 - F_DIM)];
    }
    x[((size_t)b * N_TOK + n) * E_DIM + e] = v + pos[(size_t)n * E_DIM + e];
}

// ---------------- layernorm: warp per row, emits bf16 hi/lo ------------------
__device__ __forceinline__ float warp_sum(float v) {
    #pragma unroll
    for (int o = 16; o > 0; o >>= 1) v += __shfl_xor_sync(0xffffffffu, v, o);
    return v;
}

__global__ __launch_bounds__(256) void layernorm_kernel(
    const float* __restrict__ x, const float* __restrict__ g,
    const float* __restrict__ b,
    __nv_bfloat16* __restrict__ outH, __nv_bfloat16* __restrict__ outL)
{
    int row  = blockIdx.x * 8 + (threadIdx.x >> 5);
    int lane = threadIdx.x & 31;
    const float4* xr = (const float4*)(x + (size_t)row * E_DIM);
    float4 v0 = xr[lane * 2];
    float4 v1 = xr[lane * 2 + 1];
    float s  = v0.x + v0.y + v0.z + v0.w + v1.x + v1.y + v1.z + v1.w;
    float ss = v0.x*v0.x + v0.y*v0.y + v0.z*v0.z + v0.w*v0.w
             + v1.x*v1.x + v1.y*v1.y + v1.z*v1.z + v1.w*v1.w;
    s  = warp_sum(s);
    ss = warp_sum(ss);
    float mean = s * (1.f / E_DIM);
    float var  = ss * (1.f / E_DIM) - mean * mean;
    float rstd = rsqrtf(var + 1e-5f);

    float vv[8] = {v0.x, v0.y, v0.z, v0.w, v1.x, v1.y, v1.z, v1.w};
    const float* gp = g + lane * 8;
    const float* bp = b + lane * 8;
    __nv_bfloat162 H[4], L[4];
    #pragma unroll
    for (int i = 0; i < 4; i++) {
        float y0 = (vv[2*i]   - mean) * rstd * gp[2*i]   + bp[2*i];
        float y1 = (vv[2*i+1] - mean) * rstd * gp[2*i+1] + bp[2*i+1];
        bf16_split(y0, H[i].x, L[i].x);
        bf16_split(y1, H[i].y, L[i].y);
    }
    __nv_bfloat162* oh = (__nv_bfloat162*)(outH + (size_t)row * E_DIM) + lane * 4;
    __nv_bfloat162* ol = (__nv_bfloat162*)(outL + (size_t)row * E_DIM) + lane * 4;
    #pragma unroll
    for (int i = 0; i < 4; i++) { oh[i] = H[i]; ol[i] = L[i]; }
}

// ---------------- tensor-core GEMM (bf16 3-term, 128x128, term-major x16) ----
#define GBM 128
#define GBN 128
#define GBK 32
#define AKP 40       // pitch: 80B rows, conflict-free 8-row LDSM phases
#define MATB (GBM * AKP * 2)          // bytes per matrix per stage (10240)
#define TG_SMEM (8 * MATB)            // 2 stages x 4 matrices = 81920 B

__device__ __forceinline__ void mma_bf16(float* c, const unsigned* a, const unsigned* b) {
    asm volatile(
        "mma.sync.aligned.m16n8k16.row.col.f32.bf16.bf16.f32 "
        "{%0,%1,%2,%3}, {%4,%5,%6,%7}, {%8,%9}, {%0,%1,%2,%3};\n"
        : "+f"(c[0]), "+f"(c[1]), "+f"(c[2]), "+f"(c[3])
        : "r"(a[0]), "r"(a[1]), "r"(a[2]), "r"(a[3]), "r"(b[0]), "r"(b[1]));
}

#define LDSM4(R, ADDR) \
    asm volatile("ldmatrix.sync.aligned.m8n8.x4.shared.b16 {%0,%1,%2,%3}, [%4];" \
        : "=r"((R)[0]), "=r"((R)[1]), "=r"((R)[2]), "=r"((R)[3]) : "r"(ADDR))

#define CP16(dst, src) \
    asm volatile("cp.async.cg.shared.global [%0], [%1], 16;" :: "r"(dst), "l"(src))
#define CP_COMMIT() asm volatile("cp.async.commit_group;" ::: "memory")
#define CP_WAIT(n)  asm volatile("cp.async.wait_group %0;" :: "n"(n) : "memory")

__global__ void __launch_bounds__(256, 2) tgemm_kernel(
    const __nv_bfloat16* __restrict__ AH, const __nv_bfloat16* __restrict__ AL,
    const __nv_bfloat16* __restrict__ WtH, const __nv_bfloat16* __restrict__ WtL,
    const float* __restrict__ bias, const float* __restrict__ res,
    float* __restrict__ Cf,
    __nv_bfloat16* __restrict__ Ch, __nv_bfloat16* __restrict__ Cl,
    int K, int N, int gelu)
{
    extern __shared__ char smem[];

    const int tid  = threadIdx.x;
    const int lane = tid & 31;
    const int wid  = tid >> 5;
    const int wm   = wid & 3;            // 0..3  (m, 32 rows each)
    const int wn   = wid >> 2;           // 0..1  (n, 64 cols each)
    const int br   = blockIdx.y * GBM;
    const int bc   = blockIdx.x * GBN;
    const int qrow = lane >> 2;
    const int qcol = (lane & 3) * 2;

    const int arow = tid >> 1;           // 0..127
    const int akh  = (tid & 1) * 16;     // 0 or 16
    const __nv_bfloat16* AHbase = AH + (size_t)(br + arow) * K + akh;
    const __nv_bfloat16* ALbase = AL + (size_t)(br + arow) * K + akh;
    const __nv_bfloat16* BHbase = WtH + (size_t)(bc + arow) * K + akh;
    const __nv_bfloat16* BLbase = WtL + (size_t)(bc + arow) * K + akh;

    // per-lane LDSM offsets (elements)
    const unsigned a_off = (unsigned)((wm * 32 + (lane & 7) + ((lane >> 3) & 1) * 8) * AKP
                                      + ((lane >> 4) & 1) * 8);
    const unsigned b_off = (unsigned)((wn * 64 + ((lane >> 4) & 1) * 8 + (lane & 7)) * AKP
                                      + ((lane >> 3) & 1) * 8);

    const unsigned sAH0 = (unsigned)__cvta_generic_to_shared(smem);
    const unsigned sAL0 = sAH0 + 2 * MATB;
    const unsigned sBH0 = sAH0 + 4 * MATB;
    const unsigned sBL0 = sAH0 + 6 * MATB;

    // per-thread cp.async destination offsets (bytes) — same for A and B tiles
    const unsigned dT = (unsigned)((arow * AKP + akh) * 2);

    float acc[2][8][4];
    #pragma unroll
    for (int i = 0; i < 2; i++)
        #pragma unroll
        for (int j = 0; j < 8; j++)
            #pragma unroll
            for (int r = 0; r < 4; r++) acc[i][j][r] = 0.f;

    auto cp_stage = [&](int k0, int s) {
        unsigned off = (unsigned)(s * MATB);
        CP16(sAH0 + off + dT,      AHbase + k0);
        CP16(sAH0 + off + dT + 16, AHbase + k0 + 8);
        CP16(sAL0 + off + dT,      ALbase + k0);
        CP16(sAL0 + off + dT + 16, ALbase + k0 + 8);
        CP16(sBH0 + off + dT,      BHbase + k0);
        CP16(sBH0 + off + dT + 16, BHbase + k0 + 8);
        CP16(sBL0 + off + dT,      BLbase + k0);
        CP16(sBL0 + off + dT + 16, BLbase + k0 + 8);
    };

    auto compute = [&](int s) {
        const unsigned off = (unsigned)(s * MATB);
        const unsigned aHs = sAH0 + off;
        const unsigned aLs = sAL0 + off;
        const unsigned bHs = sBH0 + off;
        const unsigned bLs = sBL0 + off;
        #pragma unroll
        for (int kk = 0; kk < 2; kk++) {
            const unsigned kb = kk * 16;
            unsigned aH[2][4], aL[2][4], bH[4][4], bL[4][4];
            #pragma unroll
            for (int ma = 0; ma < 2; ma++) {
                unsigned eoff = a_off + (unsigned)(ma * 16 * AKP) + kb;
                LDSM4(aH[ma], aHs + eoff * 2);
                LDSM4(aL[ma], aLs + eoff * 2);
            }
            #pragma unroll
            for (int p = 0; p < 4; p++) {
                unsigned eoff = b_off + (unsigned)(p * 16 * AKP) + kb;
                LDSM4(bH[p], bHs + eoff * 2);
                LDSM4(bL[p], bLs + eoff * 2);
            }
            // three term-major passes; each pass touches all 16 accumulators
            // once -> same-acc HMMA reuse distance = 16 (RAW latency hidden)
            #pragma unroll
            for (int ma = 0; ma < 2; ma++)
                #pragma unroll
                for (int na = 0; na < 8; na++)
                    mma_bf16(acc[ma][na], aH[ma], &bH[na >> 1][(na & 1) * 2]);
            #pragma unroll
            for (int ma = 0; ma < 2; ma++)
                #pragma unroll
                for (int na = 0; na < 8; na++)
                    mma_bf16(acc[ma][na], aL[ma], &bH[na >> 1][(na & 1) * 2]);
            #pragma unroll
            for (int ma = 0; ma < 2; ma++)
                #pragma unroll
                for (int na = 0; na < 8; na++)
                    mma_bf16(acc[ma][na], aH[ma], &bL[na >> 1][(na & 1) * 2]);
        }
    };

    const int nst = K / GBK;             // >= 8 always
    cp_stage(0, 0);
    CP_COMMIT();

    int s = 0;
    for (int k = 0; k < nst; k++) {
        CP_WAIT(0);                      // stage k resident (loaded during compute(k-1))
        __syncthreads();                 // publish stage k; buffer s^1 free for reuse
        if (k + 1 < nst) {
            cp_stage((k + 1) * GBK, s ^ 1);
            CP_COMMIT();
        }
        compute(s);
        s ^= 1;
    }

    // epilogue
    #pragma unroll
    for (int ma = 0; ma < 2; ma++) {
        #pragma unroll
        for (int half = 0; half < 2; half++) {
            int gr = br + wm * 32 + ma * 16 + qrow + half * 8;
            #pragma unroll
            for (int na = 0; na < 8; na++) {
                int gc = bc + wn * 64 + na * 8 + qcol;
                float v0 = acc[ma][na][half * 2 + 0] + bias[gc];
                float v1 = acc[ma][na][half * 2 + 1] + bias[gc + 1];
                if (gelu) {
                    v0 = 0.5f * v0 * (1.0f + erff(v0 * 0.70710678118654752f));
                    v1 = 0.5f * v1 * (1.0f + erff(v1 * 0.70710678118654752f));
                }
                if (res) {
                    float2 r = *(const float2*)&res[(size_t)gr * N + gc];
                    v0 += r.x; v1 += r.y;
                }
                if (Cf) {
                    float2 ov = {v0, v1};
                    *(float2*)&Cf[(size_t)gr * N + gc] = ov;
                }
                if (Ch) {
                    __nv_bfloat162 Hh, Ll;
                    bf16_split(v0, Hh.x, Ll.x);
                    bf16_split(v1, Hh.y, Ll.y);
                    *(__nv_bfloat162*)&Ch[(size_t)gr * N + gc] = Hh;
                    *(__nv_bfloat162*)&Cl[(size_t)gr * N + gc] = Ll;
                }
            }
        }
    }
}

// ---------------- attention: 4 queries/warp, K + V^T + P in smem -------------
#define KS_ROWS 264
#define KS_PITCH 36
#define VT_PITCH 268
#define PS_PITCH 264
#define ATT_SMEM ((KS_ROWS * KS_PITCH + 32 * VT_PITCH + 32 * PS_PITCH + 32 * KS_PITCH) * 4)

__global__ __launch_bounds__(256) void attention_kernel(
    const float* __restrict__ qkv,
    __nv_bfloat16* __restrict__ oH, __nv_bfloat16* __restrict__ oL)
{
    extern __shared__ float sm[];
    float* Ks  = sm;                           // [264][36]
    float* VsT = Ks + KS_ROWS * KS_PITCH;      // [32][268]
    float* Ps  = VsT + 32 * VT_PITCH;          // [32][264]
    float* qs  = Ps + 32 * PS_PITCH;           // [32][36]

    const int h = blockIdx.x;
    const int b = blockIdx.y;
    const int tid = threadIdx.x;
    const int w = tid >> 5, lane = tid & 31;
    const size_t base = ((size_t)b * N_TOK) * QKV_DIM + h * HD;

    for (int idx = tid; idx < KS_ROWS * 32; idx += 256) {
        int k = idx >> 5, d = idx & 31;
        float kv = 0.f, vv = 0.f;
        if (k < N_TOK) {
            kv = qkv[base + (size_t)k * QKV_DIM + 256 + d];
            vv = qkv[base + (size_t)k * QKV_DIM + 512 + d];
        }
        Ks[k * KS_PITCH + d] = kv;
        VsT[d * VT_PITCH + k] = vv;
    }
    __syncthreads();

    const int qr = lane >> 3;
    const int d4 = (lane & 7) * 4;
    float* myqs[4];
    #pragma unroll
    for (int q = 0; q < 4; q++) myqs[q] = qs + (w * 4 + q) * KS_PITCH;

    for (int it = 0; it < 9; it++) {
        int qbase = it * 32;

        __syncwarp();
        {
            int query = qbase + w * 4 + qr;
            float4 qv = {0.f, 0.f, 0.f, 0.f};
            if (query < N_TOK)
                qv = *(const float4*)&qkv[base + (size_t)query * QKV_DIM + d4];
            *(float4*)&qs[(w * 4 + qr) * KS_PITCH + d4] = qv;
        }
        __syncwarp();

        float e[4][9];
        #pragma unroll
        for (int q = 0; q < 4; q++)
            #pragma unroll
            for (int j = 0; j < 9; j++) e[q][j] = 0.f;

        #pragma unroll
        for (int dd = 0; dd < 8; dd++) {
            float4 qv[4];
            #pragma unroll
            for (int q = 0; q < 4; q++)
                qv[q] = *(const float4*)&myqs[q][dd * 4];
            #pragma unroll
            for (int j = 0; j < 9; j++) {
                int key = j * 32 + lane;
                int kc = (key < KS_ROWS) ? key : 0;
                float4 kv = *(const float4*)&Ks[kc * KS_PITCH + dd * 4];
                #pragma unroll
                for (int q = 0; q < 4; q++) {
                    e[q][j] = fmaf(qv[q].x, kv.x, e[q][j]);
                    e[q][j] = fmaf(qv[q].y, kv.y, e[q][j]);
                    e[q][j] = fmaf(qv[q].z, kv.z, e[q][j]);
                    e[q][j] = fmaf(qv[q].w, kv.w, e[q][j]);
                }
            }
        }
        #pragma unroll
        for (int j = 0; j < 9; j++) {
            int key = j * 32 + lane;
            if (key >= N_TOK)
                #pragma unroll
                for (int q = 0; q < 4; q++) e[q][j] = -INFINITY;
        }

        float scale[4];
        #pragma unroll
        for (int q = 0; q < 4; q++) {
            float m = e[q][0];
            #pragma unroll
            for (int j = 1; j < 9; j++) m = fmaxf(m, e[q][j]);
            #pragma unroll
            for (int o = 16; o > 0; o >>= 1)
                m = fmaxf(m, __shfl_xor_sync(0xffffffffu, m, o));
            float sum = 0.f;
            #pragma unroll
            for (int j = 0; j < 9; j++) {
                int key = j * 32 + lane;
                float p = (key < N_TOK) ? __expf(e[q][j] - m) : 0.f;
                e[q][j] = p;
                sum += p;
            }
            sum = warp_sum(sum);
            scale[q] = 1.f / (sum * 16.0f);
            #pragma unroll
            for (int j = 0; j < 9; j++) {
                int key = j * 32 + lane;
                if (key < KS_ROWS)
                    Ps[(w * 4 + q) * PS_PITCH + key] = e[q][j];
            }
        }
        __syncwarp();

        float acc[4] = {0.f, 0.f, 0.f, 0.f};
        #pragma unroll 4
        for (int k4 = 0; k4 < PS_PITCH / 4; k4++) {
            float4 vv = *(const float4*)&VsT[lane * VT_PITCH + k4 * 4];
            #pragma unroll
            for (int q = 0; q < 4; q++) {
                float4 pv = *(const float4*)&Ps[(w * 4 + q) * PS_PITCH + k4 * 4];
                acc[q] = fmaf(pv.x, vv.x, acc[q]);
                acc[q] = fmaf(pv.y, vv.y, acc[q]);
                acc[q] = fmaf(pv.z, vv.z, acc[q]);
                acc[q] = fmaf(pv.w, vv.w, acc[q]);
            }
        }

        #pragma unroll
        for (int q = 0; q < 4; q++) {
            int query = qbase + w * 4 + q;
            if (query < N_TOK) {
                float val = acc[q] * scale[q];
                size_t oidx = ((size_t)b * N_TOK + query) * E_DIM + h * HD + lane;
                __nv_bfloat16 hh, ll;
                bf16_split(val, hh, ll);
                oH[oidx] = hh;
                oL[oidx] = ll;
            }
        }
        __syncwarp();
    }
}

// ---------------- mean-pool + head LN + linear -------------------------------
__global__ __launch_bounds__(256) void pool_head_kernel(
    const float* __restrict__ x, const float* __restrict__ g,
    const float* __restrict__ b, const float* __restrict__ W,
    const float* __restrict__ bias, float* __restrict__ out)
{
    int bb = blockIdx.x;
    int e = threadIdx.x;
    int w = e >> 5, lane = e & 31;
    float s = 0.f;
    const float* xb = x + (size_t)bb * N_TOK * E_DIM + e;
    for (int n = 0; n < N_TOK; n++) s += xb[(size_t)n * E_DIM];
    float pooled = s * (1.0f / N_TOK);

    __shared__ float sA[8], sB[8];
    float s1 = warp_sum(pooled);
    float s2 = warp_sum(pooled * pooled);
    if (lane == 0) { sA[w] = s1; sB[w] = s2; }
    __syncthreads();
    float tot = 0.f, tot2 = 0.f;
    #pragma unroll
    for (int i = 0; i < 8; i++) { tot += sA[i]; tot2 += sB[i]; }
    float mean = tot * (1.f / E_DIM);
    float var = tot2 * (1.f / E_DIM) - mean * mean;
    float rstd = rsqrtf(var + 1e-5f);
    float y = (pooled - mean) * rstd * g[e] + b[e];
    float t = y * W[e];
    __syncthreads();
    float t1 = warp_sum(t);
    if (lane == 0) sA[w] = t1;
    __syncthreads();
    if (e == 0) {
        float tot3 = 0.f;
        #pragma unroll
        for (int i = 0; i < 8; i++) tot3 += sA[i];
        out[bb] = tot3 + bias[0];
    }
}

// ---------------- driver ------------------------------------------------------
extern "C" void kernel_launch(void* const* d_in, const int* in_sizes, int n_in,
                              void* d_out, int out_size)
{
    const int*   user    = (const int*)  d_in[0];
    const int*   item    = (const int*)  d_in[1];
    const float* ut      = (const float*)d_in[2];
    const float* it      = (const float*)d_in[3];
    const float* cls     = (const float*)d_in[4];
    const float* pos     = (const float*)d_in[5];
    const float* ln1_g   = (const float*)d_in[6];
    const float* ln1_b   = (const float*)d_in[7];
    const float* Wq      = (const float*)d_in[8];
    const float* bq      = (const float*)d_in[9];
    const float* Wk      = (const float*)d_in[10];
    const float* bk      = (const float*)d_in[11];
    const float* Wv      = (const float*)d_in[12];
    const float* bv      = (const float*)d_in[13];
    const float* Wo      = (const float*)d_in[14];
    const float* bo      = (const float*)d_in[15];
    const float* ln2_g   = (const float*)d_in[16];
    const float* ln2_b   = (const float*)d_in[17];
    const float* W1      = (const float*)d_in[18];
    const float* b1      = (const float*)d_in[19];
    const float* W2      = (const float*)d_in[20];
    const float* b2      = (const float*)d_in[21];
    const float* head_g  = (const float*)d_in[22];
    const float* head_b  = (const float*)d_in[23];
    const float* head_W  = (const float*)d_in[24];
    const float* head_bi = (const float*)d_in[25];

    float *x, *qkv, *bqkv;
    __nv_bfloat16 *hH, *hL, *oH, *oL, *tH, *tL;
    __nv_bfloat16 *WqkvH, *WqkvL, *WoH, *WoL, *W1H, *W1L, *W2H, *W2L;
    cudaGetSymbolAddress((void**)&x,     d_x);
    cudaGetSymbolAddress((void**)&qkv,   d_qkv);
    cudaGetSymbolAddress((void**)&bqkv,  d_bqkv);
    cudaGetSymbolAddress((void**)&hH,    d_hH);
    cudaGetSymbolAddress((void**)&hL,    d_hL);
    cudaGetSymbolAddress((void**)&oH,    d_oH);
    cudaGetSymbolAddress((void**)&oL,    d_oL);
    cudaGetSymbolAddress((void**)&tH,    d_tH);
    cudaGetSymbolAddress((void**)&tL,    d_tL);
    cudaGetSymbolAddress((void**)&WqkvH, d_WqkvH);
    cudaGetSymbolAddress((void**)&WqkvL, d_WqkvL);
    cudaGetSymbolAddress((void**)&WoH,   d_WoH);
    cudaGetSymbolAddress((void**)&WoL,   d_WoL);
    cudaGetSymbolAddress((void**)&W1H,   d_W1H);
    cudaGetSymbolAddress((void**)&W1L,   d_W1L);
    cudaGetSymbolAddress((void**)&W2H,   d_W2H);
    cudaGetSymbolAddress((void**)&W2L,   d_W2L);

    cudaFuncSetAttribute(attention_kernel,
                         cudaFuncAttributeMaxDynamicSharedMemorySize, ATT_SMEM);
    cudaFuncSetAttribute(tgemm_kernel,
                         cudaFuncAttributeMaxDynamicSharedMemorySize, TG_SMEM);

    // single fused pack launch
    pack_all_kernel<<<(int)((NPACK + 255LL) / 256), 256>>>(
        Wq, Wk, Wv, Wo, W1, W2, bq, bk, bv,
        WqkvH, WqkvL, WoH, WoL, W1H, W1L, W2H, W2L, bqkv);

    embed_kernel<<<dim3(N_TOK, B_DIM), 256>>>(user, item, ut, it, cls, pos, x);

    const dim3 gQKV(QKV_DIM / GBN, M_PAD / GBM);   // (6, 129)
    const dim3 gE(E_DIM / GBN, M_PAD / GBM);       // (2, 129)
    const dim3 gFF(FF_DIM / GBN, M_PAD / GBM);     // (8, 129)
    const int  lnGrid = M_ROWS / 8;                // 2056

    for (int l = 0; l < DEPTH; l++) {
        size_t eOff   = (size_t)l * E_DIM;
        size_t eeOff  = (size_t)l * E_DIM * E_DIM;
        size_t ffOff  = (size_t)l * E_DIM * FF_DIM;
        size_t qkvOff = (size_t)l * E_DIM * QKV_DIM;

        layernorm_kernel<<<lnGrid, 256>>>(x, ln1_g + eOff, ln1_b + eOff, hH, hL);

        tgemm_kernel<<<gQKV, 256, TG_SMEM>>>(hH, hL, WqkvH + qkvOff, WqkvL + qkvOff,
                                             bqkv + (size_t)l * QKV_DIM, nullptr,
                                             qkv, nullptr, nullptr, E_DIM, QKV_DIM, 0);

        attention_kernel<<<dim3(H_DIM, B_DIM), 256, ATT_SMEM>>>(qkv, oH, oL);

        // x = x + (o @ Wo + bo)
        tgemm_kernel<<<gE, 256, TG_SMEM>>>(oH, oL, WoH + eeOff, WoL + eeOff,
                                           bo + eOff, x, x, nullptr, nullptr,
                                           E_DIM, E_DIM, 0);

        layernorm_kernel<<<lnGrid, 256>>>(x, ln2_g + eOff, ln2_b + eOff, hH, hL);

        // t = gelu(h @ W1 + b1)  (bf16 hi/lo output)
        tgemm_kernel<<<gFF, 256, TG_SMEM>>>(hH, hL, W1H + ffOff, W1L + ffOff,
                                            b1 + (size_t)l * FF_DIM, nullptr,
                                            nullptr, tH, tL, E_DIM, FF_DIM, 1);
        // x = x + (t @ W2 + b2)
        tgemm_kernel<<<gE, 256, TG_SMEM>>>(tH, tL, W2H + ffOff, W2L + ffOff,
                                           b2 + eOff, x, x, nullptr, nullptr,
                                           FF_DIM, E_DIM, 0);
    }

    pool_head_kernel<<<B_DIM, 256>>>(x, head_g, head_b, head_W, head_bi,
                                     (float*)d_out);
}

// round 13
// speedup vs baseline: 3.7392x; 1.3062x over previous
#include <cuda_runtime.h>
#include <cuda_bf16.h>
#include <math.h>
#include <stdint.h>

// Problem constants
#define DEPTH 12
#define E_DIM 256
#define F_DIM 128
#define H_DIM 8
#define HD 32
#define U_DIM 1000
#define I_DIM 1000
#define B_DIM 64
#define N_TOK 257                  // 2F+1
#define M_ROWS (B_DIM * N_TOK)     // 16448
#define M_PAD 16512                // 129*128 (pad rows: junk, never real outputs)
#define FF_DIM 1024
#define QKV_DIM 768

// ---------------- scratch (device globals; zero-init, no allocation) --------
__device__ float d_x[M_PAD * E_DIM];
__device__ float d_qkv[M_PAD * QKV_DIM];
__device__ float d_bqkv[DEPTH * QKV_DIM];
__device__ __nv_bfloat16 d_hH[M_PAD * E_DIM];
__device__ __nv_bfloat16 d_hL[M_PAD * E_DIM];
__device__ __nv_bfloat16 d_oH[M_PAD * E_DIM];
__device__ __nv_bfloat16 d_oL[M_PAD * E_DIM];
__device__ __nv_bfloat16 d_tH[M_PAD * FF_DIM];
__device__ __nv_bfloat16 d_tL[M_PAD * FF_DIM];
// packed bf16 hi/lo transposed weights: layout [l][N][K]
__device__ __nv_bfloat16 d_WqkvH[DEPTH * QKV_DIM * E_DIM];
__device__ __nv_bfloat16 d_WqkvL[DEPTH * QKV_DIM * E_DIM];
__device__ __nv_bfloat16 d_WoH[DEPTH * E_DIM * E_DIM];
__device__ __nv_bfloat16 d_WoL[DEPTH * E_DIM * E_DIM];
__device__ __nv_bfloat16 d_W1H[DEPTH * FF_DIM * E_DIM];
__device__ __nv_bfloat16 d_W1L[DEPTH * FF_DIM * E_DIM];
__device__ __nv_bfloat16 d_W2H[DEPTH * E_DIM * FF_DIM];
__device__ __nv_bfloat16 d_W2L[DEPTH * E_DIM * FF_DIM];

// ---------------- bf16 split helpers -----------------------------------------
__device__ __forceinline__ void bf16_split(float x, __nv_bfloat16& h, __nv_bfloat16& l) {
    h = __float2bfloat16(x);
    l = __float2bfloat16(x - __bfloat162float(h));
}

__device__ __forceinline__ void split2(float a, float b, unsigned& h, unsigned& l) {
    __nv_bfloat162 H, L;
    H.x = __float2bfloat16(a);
    H.y = __float2bfloat16(b);
    L.x = __float2bfloat16(a - __bfloat162float(H.x));
    L.y = __float2bfloat16(b - __bfloat162float(H.y));
    h = *(unsigned*)&H;
    l = *(unsigned*)&L;
}

// ---------------- fused weight/bias pack (single launch) ---------------------
#define NQKV (DEPTH * QKV_DIM * E_DIM)
#define NWO  (DEPTH * E_DIM * E_DIM)
#define NW1  (DEPTH * E_DIM * FF_DIM)
#define NW2  (DEPTH * FF_DIM * E_DIM)
#define NB   (DEPTH * QKV_DIM)
#define NPACK (NQKV + NWO + NW1 + NW2 + NB)

__global__ __launch_bounds__(256) void pack_all_kernel(
    const float* __restrict__ Wq, const float* __restrict__ Wk,
    const float* __restrict__ Wv, const float* __restrict__ Wo,
    const float* __restrict__ W1, const float* __restrict__ W2,
    const float* __restrict__ bq, const float* __restrict__ bk,
    const float* __restrict__ bv,
    __nv_bfloat16* __restrict__ WqkvH, __nv_bfloat16* __restrict__ WqkvL,
    __nv_bfloat16* __restrict__ WoH, __nv_bfloat16* __restrict__ WoL,
    __nv_bfloat16* __restrict__ W1H, __nv_bfloat16* __restrict__ W1L,
    __nv_bfloat16* __restrict__ W2H, __nv_bfloat16* __restrict__ W2L,
    float* __restrict__ bqkv)
{
    long long idx = (long long)blockIdx.x * 256 + threadIdx.x;
    if (idx >= NPACK) return;
    if (idx < NQKV) {
        int k = idx % E_DIM;
        int n = (idx / E_DIM) % QKV_DIM;
        int l = idx / ((long long)E_DIM * QKV_DIM);
        const float* W = (n < 256) ? Wq : (n < 512) ? Wk : Wv;
        float v = W[((long long)l * E_DIM + k) * E_DIM + (n & 255)];
        bf16_split(v, WqkvH[idx], WqkvL[idx]);
        return;
    }
    idx -= NQKV;
    if (idx < NWO) {
        int k = idx % E_DIM;
        int n = (idx / E_DIM) % E_DIM;
        int l = idx / ((long long)E_DIM * E_DIM);
        float v = Wo[((long long)l * E_DIM + k) * E_DIM + n];
        bf16_split(v, WoH[idx], WoL[idx]);
        return;
    }
    idx -= NWO;
    if (idx < NW1) {
        int k = idx % E_DIM;
        int n = (idx / E_DIM) % FF_DIM;
        int l = idx / ((long long)E_DIM * FF_DIM);
        float v = W1[((long long)l * E_DIM + k) * FF_DIM + n];
        bf16_split(v, W1H[idx], W1L[idx]);
        return;
    }
    idx -= NW1;
    if (idx < NW2) {
        int k = idx % FF_DIM;
        int n = (idx / FF_DIM) % E_DIM;
        int l = idx / ((long long)FF_DIM * E_DIM);
        float v = W2[((long long)l * FF_DIM + k) * E_DIM + n];
        bf16_split(v, W2H[idx], W2L[idx]);
        return;
    }
    idx -= NW2;
    {
        int n = idx % QKV_DIM;
        int l = idx / QKV_DIM;
        float v;
        if (n < 256)      v = bq[l * E_DIM + n];
        else if (n < 512) v = bk[l * E_DIM + (n - 256)];
        else              v = bv[l * E_DIM + (n - 512)];
        bqkv[idx] = v;
    }
}

// ---------------- embedding --------------------------------------------------
__global__ __launch_bounds__(256) void embed_kernel(
    const int* __restrict__ user, const int* __restrict__ item,
    const float* __restrict__ ut, const float* __restrict__ it,
    const float* __restrict__ cls, const float* __restrict__ pos,
    float* __restrict__ x)
{
    int n = blockIdx.x;
    int b = blockIdx.y;
    int e = threadIdx.x;
    float v;
    if (n == 0) {
        v = cls[e];
    } else if (n <= F_DIM) {
        int uid = user[b];
        v = ut[((size_t)e * U_DIM + uid) * F_DIM + (n - 1)];
    } else {
        int iid = item[b];
        v = it[((size_t)e * I_DIM + iid) * F_DIM + (n - 1 - F_DIM)];
    }
    x[((size_t)b * N_TOK + n) * E_DIM + e] = v + pos[(size_t)n * E_DIM + e];
}

// ---------------- layernorm: warp per row, emits bf16 hi/lo ------------------
__device__ __forceinline__ float warp_sum(float v) {
    #pragma unroll
    for (int o = 16; o > 0; o >>= 1) v += __shfl_xor_sync(0xffffffffu, v, o);
    return v;
}

__global__ __launch_bounds__(256) void layernorm_kernel(
    const float* __restrict__ x, const float* __restrict__ g,
    const float* __restrict__ b,
    __nv_bfloat16* __restrict__ outH, __nv_bfloat16* __restrict__ outL)
{
    int row  = blockIdx.x * 8 + (threadIdx.x >> 5);
    int lane = threadIdx.x & 31;
    const float4* xr = (const float4*)(x + (size_t)row * E_DIM);
    float4 v0 = xr[lane * 2];
    float4 v1 = xr[lane * 2 + 1];
    float s  = v0.x + v0.y + v0.z + v0.w + v1.x + v1.y + v1.z + v1.w;
    float ss = v0.x*v0.x + v0.y*v0.y + v0.z*v0.z + v0.w*v0.w
             + v1.x*v1.x + v1.y*v1.y + v1.z*v1.z + v1.w*v1.w;
    s  = warp_sum(s);
    ss = warp_sum(ss);
    float mean = s * (1.f / E_DIM);
    float var  = ss * (1.f / E_DIM) - mean * mean;
    float rstd = rsqrtf(var + 1e-5f);

    float vv[8] = {v0.x, v0.y, v0.z, v0.w, v1.x, v1.y, v1.z, v1.w};
    const float* gp = g + lane * 8;
    const float* bp = b + lane * 8;
    __nv_bfloat162 H[4], L[4];
    #pragma unroll
    for (int i = 0; i < 4; i++) {
        float y0 = (vv[2*i]   - mean) * rstd * gp[2*i]   + bp[2*i];
        float y1 = (vv[2*i+1] - mean) * rstd * gp[2*i+1] + bp[2*i+1];
        bf16_split(y0, H[i].x, L[i].x);
        bf16_split(y1, H[i].y, L[i].y);
    }
    __nv_bfloat162* oh = (__nv_bfloat162*)(outH + (size_t)row * E_DIM) + lane * 4;
    __nv_bfloat162* ol = (__nv_bfloat162*)(outL + (size_t)row * E_DIM) + lane * 4;
    #pragma unroll
    for (int i = 0; i < 4; i++) { oh[i] = H[i]; ol[i] = L[i]; }
}

// ---------------- tensor-core GEMM (bf16 3-term, 128x128, term-major) --------
#define GBM 128
#define GBN 128
#define GBK 32
#define AKP 40       // pitch: 80B rows, conflict-free 8-row LDSM phases
#define MATB (GBM * AKP * 2)          // bytes per matrix per stage (10240)
#define TG_SMEM (8 * MATB)            // 2 stages x 4 matrices = 81920 B

__device__ __forceinline__ void mma_bf16(float* c, const unsigned* a, const unsigned* b) {
    asm volatile(
        "mma.sync.aligned.m16n8k16.row.col.f32.bf16.bf16.f32 "
        "{%0,%1,%2,%3}, {%4,%5,%6,%7}, {%8,%9}, {%0,%1,%2,%3};\n"
        : "+f"(c[0]), "+f"(c[1]), "+f"(c[2]), "+f"(c[3])
        : "r"(a[0]), "r"(a[1]), "r"(a[2]), "r"(a[3]), "r"(b[0]), "r"(b[1]));
}

#define LDSM4(R, ADDR) \
    asm volatile("ldmatrix.sync.aligned.m8n8.x4.shared.b16 {%0,%1,%2,%3}, [%4];" \
        : "=r"((R)[0]), "=r"((R)[1]), "=r"((R)[2]), "=r"((R)[3]) : "r"(ADDR))

#define CP16(dst, src) \
    asm volatile("cp.async.cg.shared.global [%0], [%1], 16;" :: "r"(dst), "l"(src))
#define CP_COMMIT() asm volatile("cp.async.commit_group;" ::: "memory")
#define CP_WAIT(n)  asm volatile("cp.async.wait_group %0;" :: "n"(n) : "memory")

__global__ void __launch_bounds__(256, 2) tgemm_kernel(
    const __nv_bfloat16* __restrict__ AH, const __nv_bfloat16* __restrict__ AL,
    const __nv_bfloat16* __restrict__ WtH, const __nv_bfloat16* __restrict__ WtL,
    const float* __restrict__ bias, const float* __restrict__ res,
    float* __restrict__ Cf,
    __nv_bfloat16* __restrict__ Ch, __nv_bfloat16* __restrict__ Cl,
    int K, int N, int gelu)
{
    extern __shared__ char smem[];

    const int tid  = threadIdx.x;
    const int lane = tid & 31;
    const int wid  = tid >> 5;
    const int wm   = wid & 3;
    const int wn   = wid >> 2;
    const int br   = blockIdx.y * GBM;
    const int bc   = blockIdx.x * GBN;
    const int qrow = lane >> 2;
    const int qcol = (lane & 3) * 2;

    const int arow = tid >> 1;
    const int akh  = (tid & 1) * 16;
    const __nv_bfloat16* AHbase = AH + (size_t)(br + arow) * K + akh;
    const __nv_bfloat16* ALbase = AL + (size_t)(br + arow) * K + akh;
    const __nv_bfloat16* BHbase = WtH + (size_t)(bc + arow) * K + akh;
    const __nv_bfloat16* BLbase = WtL + (size_t)(bc + arow) * K + akh;

    const unsigned a_off = (unsigned)((wm * 32 + (lane & 7) + ((lane >> 3) & 1) * 8) * AKP
                                      + ((lane >> 4) & 1) * 8);
    const unsigned b_off = (unsigned)((wn * 64 + ((lane >> 4) & 1) * 8 + (lane & 7)) * AKP
                                      + ((lane >> 3) & 1) * 8);

    const unsigned sAH0 = (unsigned)__cvta_generic_to_shared(smem);
    const unsigned sAL0 = sAH0 + 2 * MATB;
    const unsigned sBH0 = sAH0 + 4 * MATB;
    const unsigned sBL0 = sAH0 + 6 * MATB;

    const unsigned dT = (unsigned)((arow * AKP + akh) * 2);

    float acc[2][8][4];
    #pragma unroll
    for (int i = 0; i < 2; i++)
        #pragma unroll
        for (int j = 0; j < 8; j++)
            #pragma unroll
            for (int r = 0; r < 4; r++) acc[i][j][r] = 0.f;

    auto cp_stage = [&](int k0, int s) {
        unsigned off = (unsigned)(s * MATB);
        CP16(sAH0 + off + dT,      AHbase + k0);
        CP16(sAH0 + off + dT + 16, AHbase + k0 + 8);
        CP16(sAL0 + off + dT,      ALbase + k0);
        CP16(sAL0 + off + dT + 16, ALbase + k0 + 8);
        CP16(sBH0 + off + dT,      BHbase + k0);
        CP16(sBH0 + off + dT + 16, BHbase + k0 + 8);
        CP16(sBL0 + off + dT,      BLbase + k0);
        CP16(sBL0 + off + dT + 16, BLbase + k0 + 8);
    };

    auto compute = [&](int s) {
        const unsigned off = (unsigned)(s * MATB);
        const unsigned aHs = sAH0 + off;
        const unsigned aLs = sAL0 + off;
        const unsigned bHs = sBH0 + off;
        const unsigned bLs = sBL0 + off;
        #pragma unroll
        for (int kk = 0; kk < 2; kk++) {
            const unsigned kb = kk * 16;
            unsigned aH[2][4], aL[2][4], bH[4][4], bL[4][4];
            #pragma unroll
            for (int ma = 0; ma < 2; ma++) {
                unsigned eoff = a_off + (unsigned)(ma * 16 * AKP) + kb;
                LDSM4(aH[ma], aHs + eoff * 2);
                LDSM4(aL[ma], aLs + eoff * 2);
            }
            #pragma unroll
            for (int p = 0; p < 4; p++) {
                unsigned eoff = b_off + (unsigned)(p * 16 * AKP) + kb;
                LDSM4(bH[p], bHs + eoff * 2);
                LDSM4(bL[p], bLs + eoff * 2);
            }
            #pragma unroll
            for (int ma = 0; ma < 2; ma++)
                #pragma unroll
                for (int na = 0; na < 8; na++)
                    mma_bf16(acc[ma][na], aH[ma], &bH[na >> 1][(na & 1) * 2]);
            #pragma unroll
            for (int ma = 0; ma < 2; ma++)
                #pragma unroll
                for (int na = 0; na < 8; na++)
                    mma_bf16(acc[ma][na], aL[ma], &bH[na >> 1][(na & 1) * 2]);
            #pragma unroll
            for (int ma = 0; ma < 2; ma++)
                #pragma unroll
                for (int na = 0; na < 8; na++)
                    mma_bf16(acc[ma][na], aH[ma], &bL[na >> 1][(na & 1) * 2]);
        }
    };

    const int nst = K / GBK;
    cp_stage(0, 0);
    CP_COMMIT();

    int s = 0;
    for (int k = 0; k < nst; k++) {
        CP_WAIT(0);
        __syncthreads();
        if (k + 1 < nst) {
            cp_stage((k + 1) * GBK, s ^ 1);
            CP_COMMIT();
        }
        compute(s);
        s ^= 1;
    }

    // epilogue
    #pragma unroll
    for (int ma = 0; ma < 2; ma++) {
        #pragma unroll
        for (int half = 0; half < 2; half++) {
            int gr = br + wm * 32 + ma * 16 + qrow + half * 8;
            #pragma unroll
            for (int na = 0; na < 8; na++) {
                int gc = bc + wn * 64 + na * 8 + qcol;
                float v0 = acc[ma][na][half * 2 + 0] + bias[gc];
                float v1 = acc[ma][na][half * 2 + 1] + bias[gc + 1];
                if (gelu) {
                    v0 = 0.5f * v0 * (1.0f + erff(v0 * 0.70710678118654752f));
                    v1 = 0.5f * v1 * (1.0f + erff(v1 * 0.70710678118654752f));
                }
                if (res) {
                    float2 r = *(const float2*)&res[(size_t)gr * N + gc];
                    v0 += r.x; v1 += r.y;
                }
                if (Cf) {
                    float2 ov = {v0, v1};
                    *(float2*)&Cf[(size_t)gr * N + gc] = ov;
                }
                if (Ch) {
                    __nv_bfloat162 Hh, Ll;
                    bf16_split(v0, Hh.x, Ll.x);
                    bf16_split(v1, Hh.y, Ll.y);
                    *(__nv_bfloat162*)&Ch[(size_t)gr * N + gc] = Hh;
                    *(__nv_bfloat162*)&Cl[(size_t)gr * N + gc] = Ll;
                }
            }
        }
    }
}

// ---------------- flash attention on tensor cores ----------------------------
// Block per (h, b). K (272x32, hi/lo) and V^T (32x280, hi/lo) in smem.
// Each warp owns 16-query tiles; online softmax in fp32; S and PV via
// 3-term bf16 mma. Keys padded to 272; tile kt==16 masks keys 257..271.
#define NKP 272
#define KSP 40
#define VTP 280
#define ATT_SMEM ((2 * NKP * KSP + 2 * 32 * VTP) * 2)

__global__ void __launch_bounds__(256, 2) attention_kernel(
    const float* __restrict__ qkv,
    __nv_bfloat16* __restrict__ oH, __nv_bfloat16* __restrict__ oL)
{
    extern __shared__ __nv_bfloat16 asmem[];
    __nv_bfloat16* KsH = asmem;
    __nv_bfloat16* KsL = KsH + NKP * KSP;
    __nv_bfloat16* VtH = KsL + NKP * KSP;
    __nv_bfloat16* VtL = VtH + 32 * VTP;

    const int h = blockIdx.x;
    const int b = blockIdx.y;
    const int tid = threadIdx.x;
    const int w = tid >> 5, lane = tid & 31;
    const int qrow = lane >> 2, qcol = (lane & 3) * 2;
    const size_t base = ((size_t)b * N_TOK) * QKV_DIM + h * HD;

    // K: rows = keys, cols = dims (coalesced loads)
    for (int idx = tid; idx < NKP * 16; idx += 256) {
        int key = idx >> 4, d2 = idx & 15;
        float2 kv = make_float2(0.f, 0.f);
        if (key < N_TOK)
            kv = *(const float2*)&qkv[base + (size_t)key * QKV_DIM + 256 + d2 * 2];
        unsigned hh, ll;
        split2(kv.x, kv.y, hh, ll);
        *(unsigned*)&KsH[key * KSP + d2 * 2] = hh;
        *(unsigned*)&KsL[key * KSP + d2 * 2] = ll;
    }
    // V^T: rows = dims, cols = keys
    for (int idx = tid; idx < NKP * 32; idx += 256) {
        int key = idx >> 5, d = idx & 31;
        float v = (key < N_TOK) ? qkv[base + (size_t)key * QKV_DIM + 512 + d] : 0.f;
        __nv_bfloat16 hh = __float2bfloat16(v);
        VtH[d * VTP + key] = hh;
        VtL[d * VTP + key] = __float2bfloat16(v - __bfloat162float(hh));
    }
    __syncthreads();

    const unsigned sKH = (unsigned)__cvta_generic_to_shared(KsH);
    const unsigned sKL = (unsigned)__cvta_generic_to_shared(KsL);
    const unsigned sVH = (unsigned)__cvta_generic_to_shared(VtH);
    const unsigned sVL = (unsigned)__cvta_generic_to_shared(VtL);
    const int ld_row = ((lane >> 4) & 1) * 8 + (lane & 7);
    const int ld_col = ((lane >> 3) & 1) * 8;

    for (int qt = w; qt < 17; qt += 8) {
        const int q0 = qt * 16;

        // Q fragments straight from gmem (fp32 -> bf16 hi/lo)
        unsigned aQh[2][4], aQl[2][4];
        #pragma unroll
        for (int kk = 0; kk < 2; kk++)
            #pragma unroll
            for (int f = 0; f < 4; f++) {
                int row = q0 + qrow + (f & 1) * 8;
                int col = kk * 16 + qcol + (f >> 1) * 8;
                float2 qv = *(const float2*)&qkv[base + (size_t)row * QKV_DIM + col];
                split2(qv.x, qv.y, aQh[kk][f], aQl[kk][f]);
            }

        float m0 = -INFINITY, m1 = -INFINITY, s0 = 0.f, s1 = 0.f;
        float oa[4][4];
        #pragma unroll
        for (int na = 0; na < 4; na++)
            #pragma unroll
            for (int r = 0; r < 4; r++) oa[na][r] = 0.f;

        for (int kt = 0; kt < 17; kt++) {
            // K fragments: 16 keys x 32 dims (2 k-chunks), hi/lo
            unsigned kh[2][4], kl[2][4];
            #pragma unroll
            for (int kk = 0; kk < 2; kk++) {
                unsigned eoff = (unsigned)((kt * 16 + ld_row) * KSP + kk * 16 + ld_col);
                LDSM4(kh[kk], sKH + eoff * 2);
                LDSM4(kl[kk], sKL + eoff * 2);
            }
            float sL[4] = {0.f, 0.f, 0.f, 0.f};
            float sR[4] = {0.f, 0.f, 0.f, 0.f};
            #pragma unroll
            for (int kk = 0; kk < 2; kk++) {
                mma_bf16(sL, aQh[kk], &kh[kk][0]);
                mma_bf16(sR, aQh[kk], &kh[kk][2]);
                mma_bf16(sL, aQl[kk], &kh[kk][0]);
                mma_bf16(sR, aQl[kk], &kh[kk][2]);
                mma_bf16(sL, aQh[kk], &kl[kk][0]);
                mma_bf16(sR, aQh[kk], &kl[kk][2]);
            }
            if (kt == 16) {   // keys 256..271: only 256 valid
                if (qcol != 0) { sL[0] = -INFINITY; sL[2] = -INFINITY; }
                sL[1] = -INFINITY; sL[3] = -INFINITY;
                sR[0] = -INFINITY; sR[1] = -INFINITY;
                sR[2] = -INFINITY; sR[3] = -INFINITY;
            }

            float vm0 = fmaxf(fmaxf(sL[0], sL[1]), fmaxf(sR[0], sR[1]));
            float vm1 = fmaxf(fmaxf(sL[2], sL[3]), fmaxf(sR[2], sR[3]));
            vm0 = fmaxf(vm0, __shfl_xor_sync(0xffffffffu, vm0, 1));
            vm0 = fmaxf(vm0, __shfl_xor_sync(0xffffffffu, vm0, 2));
            vm1 = fmaxf(vm1, __shfl_xor_sync(0xffffffffu, vm1, 1));
            vm1 = fmaxf(vm1, __shfl_xor_sync(0xffffffffu, vm1, 2));
            float mn0 = fmaxf(m0, vm0), mn1 = fmaxf(m1, vm1);
            float c0 = __expf(m0 - mn0), c1 = __expf(m1 - mn1);
            m0 = mn0; m1 = mn1;

            float p0 = __expf(sL[0] - m0), p1 = __expf(sL[1] - m0);
            float p2 = __expf(sL[2] - m1), p3 = __expf(sL[3] - m1);
            float r0 = __expf(sR[0] - m0), r1 = __expf(sR[1] - m0);
            float r2 = __expf(sR[2] - m1), r3 = __expf(sR[3] - m1);
            s0 = s0 * c0 + p0 + p1 + r0 + r1;
            s1 = s1 * c1 + p2 + p3 + r2 + r3;
            #pragma unroll
            for (int na = 0; na < 4; na++) {
                oa[na][0] *= c0; oa[na][1] *= c0;
                oa[na][2] *= c1; oa[na][3] *= c1;
            }

            // P -> A fragments (hi/lo)
            unsigned aPh[4], aPl[4];
            split2(p0, p1, aPh[0], aPl[0]);
            split2(p2, p3, aPh[1], aPl[1]);
            split2(r0, r1, aPh[2], aPl[2]);
            split2(r2, r3, aPh[3], aPl[3]);

            // V fragments: 32 dims (2 chunks of 16) x 16 keys, hi/lo
            unsigned vh[2][4], vl[2][4];
            #pragma unroll
            for (int pd = 0; pd < 2; pd++) {
                unsigned eoff = (unsigned)((pd * 16 + ld_row) * VTP + kt * 16 + ld_col);
                LDSM4(vh[pd], sVH + eoff * 2);
                LDSM4(vl[pd], sVL + eoff * 2);
            }
            #pragma unroll
            for (int na = 0; na < 4; na++) {
                const unsigned* bh = &vh[na >> 1][(na & 1) * 2];
                const unsigned* bl = &vl[na >> 1][(na & 1) * 2];
                mma_bf16(oa[na], aPh, bh);
                mma_bf16(oa[na], aPl, bh);
                mma_bf16(oa[na], aPh, bl);
            }
        }

        s0 += __shfl_xor_sync(0xffffffffu, s0, 1);
        s0 += __shfl_xor_sync(0xffffffffu, s0, 2);
        s1 += __shfl_xor_sync(0xffffffffu, s1, 1);
        s1 += __shfl_xor_sync(0xffffffffu, s1, 2);
        float sc0 = 1.f / (s0 * 16.0f);   // /sqrt(E) applied after softmax
        float sc1 = 1.f / (s1 * 16.0f);

        int row0 = q0 + qrow;
        int row1 = row0 + 8;
        #pragma unroll
        for (int na = 0; na < 4; na++) {
            size_t col = (size_t)h * HD + na * 8 + qcol;
            if (row0 < N_TOK) {
                unsigned hh, ll;
                split2(oa[na][0] * sc0, oa[na][1] * sc0, hh, ll);
                size_t o = ((size_t)b * N_TOK + row0) * E_DIM + col;
                *(unsigned*)&oH[o] = hh;
                *(unsigned*)&oL[o] = ll;
            }
            if (row1 < N_TOK) {
                unsigned hh, ll;
                split2(oa[na][2] * sc1, oa[na][3] * sc1, hh, ll);
                size_t o = ((size_t)b * N_TOK + row1) * E_DIM + col;
                *(unsigned*)&oH[o] = hh;
                *(unsigned*)&oL[o] = ll;
            }
        }
    }
}

// ---------------- mean-pool + head LN + linear -------------------------------
__global__ __launch_bounds__(256) void pool_head_kernel(
    const float* __restrict__ x, const float* __restrict__ g,
    const float* __restrict__ b, const float* __restrict__ W,
    const float* __restrict__ bias, float* __restrict__ out)
{
    int bb = blockIdx.x;
    int e = threadIdx.x;
    int w = e >> 5, lane = e & 31;
    float s = 0.f;
    const float* xb = x + (size_t)bb * N_TOK * E_DIM + e;
    for (int n = 0; n < N_TOK; n++) s += xb[(size_t)n * E_DIM];
    float pooled = s * (1.0f / N_TOK);

    __shared__ float sA[8], sB[8];
    float s1 = warp_sum(pooled);
    float s2 = warp_sum(pooled * pooled);
    if (lane == 0) { sA[w] = s1; sB[w] = s2; }
    __syncthreads();
    float tot = 0.f, tot2 = 0.f;
    #pragma unroll
    for (int i = 0; i < 8; i++) { tot += sA[i]; tot2 += sB[i]; }
    float mean = tot * (1.f / E_DIM);
    float var = tot2 * (1.f / E_DIM) - mean * mean;
    float rstd = rsqrtf(var + 1e-5f);
    float y = (pooled - mean) * rstd * g[e] + b[e];
    float t = y * W[e];
    __syncthreads();
    float t1 = warp_sum(t);
    if (lane == 0) sA[w] = t1;
    __syncthreads();
    if (e == 0) {
        float tot3 = 0.f;
        #pragma unroll
        for (int i = 0; i < 8; i++) tot3 += sA[i];
        out[bb] = tot3 + bias[0];
    }
}

// ---------------- driver ------------------------------------------------------
extern "C" void kernel_launch(void* const* d_in, const int* in_sizes, int n_in,
                              void* d_out, int out_size)
{
    const int*   user    = (const int*)  d_in[0];
    const int*   item    = (const int*)  d_in[1];
    const float* ut      = (const float*)d_in[2];
    const float* it      = (const float*)d_in[3];
    const float* cls     = (const float*)d_in[4];
    const float* pos     = (const float*)d_in[5];
    const float* ln1_g   = (const float*)d_in[6];
    const float* ln1_b   = (const float*)d_in[7];
    const float* Wq      = (const float*)d_in[8];
    const float* bq      = (const float*)d_in[9];
    const float* Wk      = (const float*)d_in[10];
    const float* bk      = (const float*)d_in[11];
    const float* Wv      = (const float*)d_in[12];
    const float* bv      = (const float*)d_in[13];
    const float* Wo      = (const float*)d_in[14];
    const float* bo      = (const float*)d_in[15];
    const float* ln2_g   = (const float*)d_in[16];
    const float* ln2_b   = (const float*)d_in[17];
    const float* W1      = (const float*)d_in[18];
    const float* b1      = (const float*)d_in[19];
    const float* W2      = (const float*)d_in[20];
    const float* b2      = (const float*)d_in[21];
    const float* head_g  = (const float*)d_in[22];
    const float* head_b  = (const float*)d_in[23];
    const float* head_W  = (const float*)d_in[24];
    const float* head_bi = (const float*)d_in[25];

    float *x, *qkv, *bqkv;
    __nv_bfloat16 *hH, *hL, *oH, *oL, *tH, *tL;
    __nv_bfloat16 *WqkvH, *WqkvL, *WoH, *WoL, *W1H, *W1L, *W2H, *W2L;
    cudaGetSymbolAddress((void**)&x,     d_x);
    cudaGetSymbolAddress((void**)&qkv,   d_qkv);
    cudaGetSymbolAddress((void**)&bqkv,  d_bqkv);
    cudaGetSymbolAddress((void**)&hH,    d_hH);
    cudaGetSymbolAddress((void**)&hL,    d_hL);
    cudaGetSymbolAddress((void**)&oH,    d_oH);
    cudaGetSymbolAddress((void**)&oL,    d_oL);
    cudaGetSymbolAddress((void**)&tH,    d_tH);
    cudaGetSymbolAddress((void**)&tL,    d_tL);
    cudaGetSymbolAddress((void**)&WqkvH, d_WqkvH);
    cudaGetSymbolAddress((void**)&WqkvL, d_WqkvL);
    cudaGetSymbolAddress((void**)&WoH,   d_WoH);
    cudaGetSymbolAddress((void**)&WoL,   d_WoL);
    cudaGetSymbolAddress((void**)&W1H,   d_W1H);
    cudaGetSymbolAddress((void**)&W1L,   d_W1L);
    cudaGetSymbolAddress((void**)&W2H,   d_W2H);
    cudaGetSymbolAddress((void**)&W2L,   d_W2L);

    cudaFuncSetAttribute(attention_kernel,
                         cudaFuncAttributeMaxDynamicSharedMemorySize, ATT_SMEM);
    cudaFuncSetAttribute(tgemm_kernel,
                         cudaFuncAttributeMaxDynamicSharedMemorySize, TG_SMEM);

    // single fused pack launch
    pack_all_kernel<<<(int)((NPACK + 255LL) / 256), 256>>>(
        Wq, Wk, Wv, Wo, W1, W2, bq, bk, bv,
        WqkvH, WqkvL, WoH, WoL, W1H, W1L, W2H, W2L, bqkv);

    embed_kernel<<<dim3(N_TOK, B_DIM), 256>>>(user, item, ut, it, cls, pos, x);

    const dim3 gQKV(QKV_DIM / GBN, M_PAD / GBM);   // (6, 129)
    const dim3 gE(E_DIM / GBN, M_PAD / GBM);       // (2, 129)
    const dim3 gFF(FF_DIM / GBN, M_PAD / GBM);     // (8, 129)
    const int  lnGrid = M_ROWS / 8;                // 2056

    for (int l = 0; l < DEPTH; l++) {
        size_t eOff   = (size_t)l * E_DIM;
        size_t eeOff  = (size_t)l * E_DIM * E_DIM;
        size_t ffOff  = (size_t)l * E_DIM * FF_DIM;
        size_t qkvOff = (size_t)l * E_DIM * QKV_DIM;

        layernorm_kernel<<<lnGrid, 256>>>(x, ln1_g + eOff, ln1_b + eOff, hH, hL);

        tgemm_kernel<<<gQKV, 256, TG_SMEM>>>(hH, hL, WqkvH + qkvOff, WqkvL + qkvOff,
                                             bqkv + (size_t)l * QKV_DIM, nullptr,
                                             qkv, nullptr, nullptr, E_DIM, QKV_DIM, 0);

        attention_kernel<<<dim3(H_DIM, B_DIM), 256, ATT_SMEM>>>(qkv, oH, oL);

        // x = x + (o @ Wo + bo)
        tgemm_kernel<<<gE, 256, TG_SMEM>>>(oH, oL, WoH + eeOff, WoL + eeOff,
                                           bo + eOff, x, x, nullptr, nullptr,
                                           E_DIM, E_DIM, 0);

        layernorm_kernel<<<lnGrid, 256>>>(x, ln2_g + eOff, ln2_b + eOff, hH, hL);

        // t = gelu(h @ W1 + b1)  (bf16 hi/lo output)
        tgemm_kernel<<<gFF, 256, TG_SMEM>>>(hH, hL, W1H + ffOff, W1L + ffOff,
                                            b1 + (size_t)l * FF_DIM, nullptr,
                                            nullptr, tH, tL, E_DIM, FF_DIM, 1);
        // x = x + (t @ W2 + b2)
        tgemm_kernel<<<gE, 256, TG_SMEM>>>(tH, tL, W2H + ffOff, W2L + ffOff,
                                           b2 + eOff, x, x, nullptr, nullptr,
                                           FF_DIM, E_DIM, 0);
    }

    pool_head_kernel<<<B_DIM, 256>>>(x, head_g, head_b, head_W, head_bi,
                                     (float*)d_out);
}